// round 5
// baseline (speedup 1.0000x reference)
#include <cuda_runtime.h>
#include <cuda_bf16.h>
#include <math.h>
#include <stdint.h>

// Problem constants
#define BATCH   2
#define SEQ     2048
#define DM      2048
#define NH      16
#define KVH     4
#define HD      128
#define QKV_N   3072
#define BS      (BATCH*SEQ)   // 4096
#define QSCALE  0.08838834764831845f

// ---------------------------------------------------------------------------
// Scratch
// ---------------------------------------------------------------------------
__device__ float g_qkv [BS * QKV_N];

__device__ __nv_bfloat16 g_xn_h [BS * DM];
__device__ __nv_bfloat16 g_xn_l [BS * DM];
__device__ __nv_bfloat16 g_at_h [BS * DM];
__device__ __nv_bfloat16 g_at_l [BS * DM];
__device__ __nv_bfloat16 g_wq_h [DM * QKV_N];
__device__ __nv_bfloat16 g_wq_l [DM * QKV_N];
__device__ __nv_bfloat16 g_wo_h [DM * DM];
__device__ __nv_bfloat16 g_wo_l [DM * DM];

__device__ __nv_bfloat16 g_qh [BATCH * NH  * SEQ * HD];
__device__ __nv_bfloat16 g_ql [BATCH * NH  * SEQ * HD];
__device__ __nv_bfloat16 g_kh [BATCH * KVH * SEQ * HD];
__device__ __nv_bfloat16 g_kl [BATCH * KVH * SEQ * HD];
__device__ __nv_bfloat16 g_vh [BATCH * KVH * SEQ * HD];
__device__ __nv_bfloat16 g_vl [BATCH * KVH * SEQ * HD];

// ---------------------------------------------------------------------------
// PTX helpers (compute_103-safe)
// ---------------------------------------------------------------------------
__device__ __forceinline__ uint32_t smem_u32(const void* p) {
    uint32_t a;
    asm("{ .reg .u64 t; cvta.to.shared.u64 t, %1; cvt.u32.u64 %0, t; }"
        : "=r"(a) : "l"(p));
    return a;
}
__device__ __forceinline__ void cp16(uint32_t dst, const void* src) {
    asm volatile("cp.async.cg.shared.global [%0], [%1], 16;"
                 :: "r"(dst), "l"(src));
}
__device__ __forceinline__ void cp_commit() {
    asm volatile("cp.async.commit_group;" ::: "memory");
}
template<int N>
__device__ __forceinline__ void cp_wait() {
    asm volatile("cp.async.wait_group %0;" :: "n"(N) : "memory");
}
__device__ __forceinline__ void ldsm_x4(uint32_t* r, uint32_t addr) {
    asm volatile("ldmatrix.sync.aligned.m8n8.x4.shared.b16 {%0,%1,%2,%3}, [%4];"
                 : "=r"(r[0]), "=r"(r[1]), "=r"(r[2]), "=r"(r[3]) : "r"(addr));
}
__device__ __forceinline__ void ldsm_x4t(uint32_t* r, uint32_t addr) {
    asm volatile("ldmatrix.sync.aligned.m8n8.x4.trans.shared.b16 {%0,%1,%2,%3}, [%4];"
                 : "=r"(r[0]), "=r"(r[1]), "=r"(r[2]), "=r"(r[3]) : "r"(addr));
}
__device__ __forceinline__ void mma_bf16(float* d, const uint32_t* a, const uint32_t* b) {
    asm volatile(
        "mma.sync.aligned.m16n8k16.row.col.f32.bf16.bf16.f32 "
        "{%0,%1,%2,%3}, {%4,%5,%6,%7}, {%8,%9}, {%0,%1,%2,%3};"
        : "+f"(d[0]), "+f"(d[1]), "+f"(d[2]), "+f"(d[3])
        : "r"(a[0]), "r"(a[1]), "r"(a[2]), "r"(a[3]), "r"(b[0]), "r"(b[1]));
}
__device__ __forceinline__ void mma_bf16_2(float* d, const uint32_t* a,
                                           uint32_t b0, uint32_t b1) {
    asm volatile(
        "mma.sync.aligned.m16n8k16.row.col.f32.bf16.bf16.f32 "
        "{%0,%1,%2,%3}, {%4,%5,%6,%7}, {%8,%9}, {%0,%1,%2,%3};"
        : "+f"(d[0]), "+f"(d[1]), "+f"(d[2]), "+f"(d[3])
        : "r"(a[0]), "r"(a[1]), "r"(a[2]), "r"(a[3]), "r"(b0), "r"(b1));
}

// ---------------------------------------------------------------------------
// RMSNorm (fp32 out)
// ---------------------------------------------------------------------------
__global__ void rmsnorm_kernel(const float* __restrict__ x,
                               const float* __restrict__ w,
                               float* __restrict__ y)
{
    __shared__ float red[256];
    int row = blockIdx.x;
    const float4* xr = (const float4*)(x + (size_t)row * DM);
    float s = 0.f;
    #pragma unroll
    for (int i = threadIdx.x; i < DM/4; i += 256) {
        float4 v = xr[i];
        s += v.x*v.x + v.y*v.y + v.z*v.z + v.w*v.w;
    }
    red[threadIdx.x] = s;
    __syncthreads();
    for (int st = 128; st > 0; st >>= 1) {
        if (threadIdx.x < st) red[threadIdx.x] += red[threadIdx.x + st];
        __syncthreads();
    }
    float rs = rsqrtf(red[0] * (1.0f/(float)DM) + 1e-5f);
    float4* yr = (float4*)(y + (size_t)row * DM);
    const float4* wr = (const float4*)w;
    #pragma unroll
    for (int i = threadIdx.x; i < DM/4; i += 256) {
        float4 v = xr[i];
        float4 ww = wr[i];
        v.x = v.x * rs * ww.x;
        v.y = v.y * rs * ww.y;
        v.z = v.z * rs * ww.z;
        v.w = v.w * rs * ww.w;
        yr[i] = v;
    }
}

// RMSNorm -> bf16 hi/lo split output
__global__ void rmsnorm_split_kernel(const float* __restrict__ x,
                                     const float* __restrict__ w,
                                     __nv_bfloat16* __restrict__ yh,
                                     __nv_bfloat16* __restrict__ yl)
{
    __shared__ float red[256];
    int row = blockIdx.x;
    const float4* xr = (const float4*)(x + (size_t)row * DM);
    float s = 0.f;
    #pragma unroll
    for (int i = threadIdx.x; i < DM/4; i += 256) {
        float4 v = xr[i];
        s += v.x*v.x + v.y*v.y + v.z*v.z + v.w*v.w;
    }
    red[threadIdx.x] = s;
    __syncthreads();
    for (int st = 128; st > 0; st >>= 1) {
        if (threadIdx.x < st) red[threadIdx.x] += red[threadIdx.x + st];
        __syncthreads();
    }
    float rs = rsqrtf(red[0] * (1.0f/(float)DM) + 1e-5f);
    const float4* wr = (const float4*)w;
    #pragma unroll
    for (int i = threadIdx.x; i < DM/4; i += 256) {
        float4 v = xr[i];
        float4 ww = wr[i];
        float f[4] = {v.x*rs*ww.x, v.y*rs*ww.y, v.z*rs*ww.z, v.w*rs*ww.w};
        __nv_bfloat16 h[4], l[4];
        #pragma unroll
        for (int j = 0; j < 4; j++) {
            h[j] = __float2bfloat16(f[j]);
            l[j] = __float2bfloat16(f[j] - __bfloat162float(h[j]));
        }
        size_t o = (size_t)row * DM + i*4;
        *(ulonglong1*)&yh[o] = *(ulonglong1*)h;
        *(ulonglong1*)&yl[o] = *(ulonglong1*)l;
    }
}

// fp32 -> bf16 hi/lo split
__global__ void split_kernel(const float* __restrict__ x,
                             __nv_bfloat16* __restrict__ xh,
                             __nv_bfloat16* __restrict__ xl, int n4)
{
    int i = blockIdx.x * blockDim.x + threadIdx.x;
    if (i >= n4) return;
    float4 v = ((const float4*)x)[i];
    float f[4] = {v.x, v.y, v.z, v.w};
    __nv_bfloat16 h[4], l[4];
    #pragma unroll
    for (int j = 0; j < 4; j++) {
        h[j] = __float2bfloat16(f[j]);
        l[j] = __float2bfloat16(f[j] - __bfloat162float(h[j]));
    }
    *(ulonglong1*)&xh[(size_t)i*4] = *(ulonglong1*)h;
    *(ulonglong1*)&xl[(size_t)i*4] = *(ulonglong1*)l;
}

// ---------------------------------------------------------------------------
// HMMA GEMM (bfx3): CTA 128x256, warp tile 64x64, k-chunk 32, 3-stage cp.async.
// EPI 0: clip [-8,8].  EPI 1: +Resid.
// ---------------------------------------------------------------------------
#define A_STRIDE  80        // 64B data + 16B pad
#define B_STRIDE  528       // 512B data + 16B pad
#define AH_OFF    0
#define AL_OFF    10240     // 128*80
#define BH_OFF    20480
#define BL_OFF    37376     // 20480 + 32*528
#define STAGE_SZ  54272     // 20480 + 2*16896
#define HG_SMEM   (3*STAGE_SZ)   // 162816

template<int EPI>
__global__ void __launch_bounds__(256, 1)
hgemm_kernel(const __nv_bfloat16* __restrict__ Ah, const __nv_bfloat16* __restrict__ Al,
             const __nv_bfloat16* __restrict__ Bh, const __nv_bfloat16* __restrict__ Bl,
             const float* __restrict__ Resid, float* __restrict__ C,
             int M, int N, int K)
{
    extern __shared__ char sm[];
    uint32_t sb = smem_u32(sm);

    int tid  = threadIdx.x;
    int lane = tid & 31;
    int warp = tid >> 5;
    int warpM = warp & 1;       // 64-row half
    int warpN = warp >> 1;      // 0..3 -> 64-col group
    int rowBase = blockIdx.y * 128;
    int colBase = blockIdx.x * 256;

    float acc[4][8][4];
    #pragma unroll
    for (int i = 0; i < 4; i++)
        #pragma unroll
        for (int j = 0; j < 8; j++)
            #pragma unroll
            for (int q = 0; q < 4; q++) acc[i][j][q] = 0.f;

    int nC = K / 32;

    auto issue = [&](int c) {
        uint32_t base = sb + (uint32_t)(c % 3) * STAGE_SZ;
        int k0 = c * 32;
        // A: 128 rows x 64B (hi+lo)
        #pragma unroll
        for (int it = 0; it < 2; it++) {
            int idx = it * 256 + tid;          // 0..511
            int r  = idx >> 2;
            int kc = idx & 3;
            size_t go = (size_t)(rowBase + r) * K + k0 + kc*8;
            uint32_t so = r * A_STRIDE + kc * 16;
            cp16(base + AH_OFF + so, Ah + go);
            cp16(base + AL_OFF + so, Al + go);
        }
        // B: 32 rows x 512B (hi+lo)
        #pragma unroll
        for (int it = 0; it < 4; it++) {
            int idx = it * 256 + tid;          // 0..1023
            int r   = idx >> 5;
            int c32 = idx & 31;
            size_t go = (size_t)(k0 + r) * N + colBase + c32*8;
            uint32_t so = r * B_STRIDE + c32 * 16;
            cp16(base + BH_OFF + so, Bh + go);
            cp16(base + BL_OFF + so, Bl + go);
        }
        cp_commit();
    };

    issue(0);
    if (nC > 1) issue(1);

    for (int c = 0; c < nC; c++) {
        if (c + 2 < nC) { issue(c + 2); cp_wait<2>(); }
        else if (c + 1 < nC) { cp_wait<1>(); }
        else { cp_wait<0>(); }
        __syncthreads();

        uint32_t base = sb + (uint32_t)(c % 3) * STAGE_SZ;

        #pragma unroll
        for (int kk = 0; kk < 2; kk++) {
            uint32_t aH[4][4], aL[4][4];
            #pragma unroll
            for (int mt = 0; mt < 4; mt++) {
                uint32_t aoff = (uint32_t)(warpM*64 + mt*16 + (lane & 15)) * A_STRIDE
                              + kk*32 + ((lane >> 4) * 16);
                ldsm_x4(aH[mt], base + AH_OFF + aoff);
                ldsm_x4(aL[mt], base + AL_OFF + aoff);
            }
            #pragma unroll
            for (int nt = 0; nt < 4; nt++) {
                uint32_t bHv[4], bLv[4];
                uint32_t boff = (uint32_t)(kk*16 + (lane & 15)) * B_STRIDE
                              + (uint32_t)(warpN*64 + nt*16)*2 + ((lane >> 4) * 16);
                ldsm_x4t(bHv, base + BH_OFF + boff);
                ldsm_x4t(bLv, base + BL_OFF + boff);
                #pragma unroll
                for (int mt = 0; mt < 4; mt++) {
                    #pragma unroll
                    for (int half = 0; half < 2; half++) {
                        int n8 = nt*2 + half;
                        int hf = half*2;
                        mma_bf16(acc[mt][n8], aH[mt], &bHv[hf]);
                        mma_bf16(acc[mt][n8], aH[mt], &bLv[hf]);
                        mma_bf16(acc[mt][n8], aL[mt], &bHv[hf]);
                    }
                }
            }
        }
        __syncthreads();
    }

    // Epilogue
    int rg = lane >> 2;
    int cg = (lane & 3) * 2;
    #pragma unroll
    for (int mt = 0; mt < 4; mt++) {
        #pragma unroll
        for (int n8 = 0; n8 < 8; n8++) {
            int r0 = rowBase + warpM*64 + mt*16 + rg;
            int cc = colBase + warpN*64 + n8*8 + cg;
            #pragma unroll
            for (int half = 0; half < 2; half++) {
                int r = r0 + half * 8;
                float2 v;
                v.x = acc[mt][n8][half*2+0];
                v.y = acc[mt][n8][half*2+1];
                if (EPI == 0) {
                    v.x = fminf(8.f, fmaxf(-8.f, v.x));
                    v.y = fminf(8.f, fmaxf(-8.f, v.y));
                } else {
                    float2 rv = *(const float2*)&Resid[(size_t)r * N + cc];
                    v.x += rv.x; v.y += rv.y;
                }
                *(float2*)&C[(size_t)r * N + cc] = v;
            }
        }
    }
}

// ---------------------------------------------------------------------------
// RoPE + split to bf16 hi/lo Q/K/V
// ---------------------------------------------------------------------------
__global__ void rope_kernel(const float* __restrict__ qkv,
                            const int* __restrict__ posids,
                            const float* __restrict__ rsin,
                            const float* __restrict__ rcos,
                            __nv_bfloat16* __restrict__ Qh, __nv_bfloat16* __restrict__ Ql,
                            __nv_bfloat16* __restrict__ Kh, __nv_bfloat16* __restrict__ Kl,
                            __nv_bfloat16* __restrict__ Vh, __nv_bfloat16* __restrict__ Vl)
{
    int bs = blockIdx.x;
    int b = bs >> 11;
    int s = bs & 2047;
    int pos = posids[bs];
    const float* base = qkv + (size_t)bs * QKV_N;

    for (int idx = threadIdx.x; idx < QKV_N; idx += 256) {
        int head = idx >> 7;
        int d = idx & 127;
        float x = base[idx];
        float val;
        size_t o;
        __nv_bfloat16* Dh;
        __nv_bfloat16* Dl;
        if (head < NH + KVH) {
            float c  = rcos[pos * HD + d];
            float sn = rsin[pos * HD + d];
            float other = (d < 64) ? -base[head*HD + d + 64]
                                   :  base[head*HD + d - 64];
            val = x * c + other * sn;
            if (head < NH) {
                val *= QSCALE;
                o = (((size_t)(b*NH + head)) * SEQ + s) * HD + d;
                Dh = Qh; Dl = Ql;
            } else {
                o = (((size_t)(b*KVH + head - NH)) * SEQ + s) * HD + d;
                Dh = Kh; Dl = Kl;
            }
        } else {
            val = x;
            o = (((size_t)(b*KVH + head - NH - KVH)) * SEQ + s) * HD + d;
            Dh = Vh; Dl = Vl;
        }
        __nv_bfloat16 h = __float2bfloat16(val);
        __nv_bfloat16 l = __float2bfloat16(val - __bfloat162float(h));
        Dh[o] = h;
        Dl[o] = l;
    }
}

// ---------------------------------------------------------------------------
// Flash attention, HMMA bfx3. BM=64, BN=64, HD=128, 8 warps, 256 thr.
// ---------------------------------------------------------------------------
#define AT_QKV_STRIDE 272
#define AT_P_STRIDE   144
#define AT_S_STRIDE   66
#define AQH 0
#define AQL 17408
#define AKV 34816
#define AKV_BUF 69632
#define AS_OFF  174080
#define APH 190976
#define APL 200192
#define AST 209408
#define ATT_SMEM 210432

__global__ void __launch_bounds__(256, 1)
attn_mma_kernel(const __nv_bfloat16* __restrict__ Qh, const __nv_bfloat16* __restrict__ Ql,
                const __nv_bfloat16* __restrict__ Kh, const __nv_bfloat16* __restrict__ Kl,
                const __nv_bfloat16* __restrict__ Vh, const __nv_bfloat16* __restrict__ Vl,
                const int* __restrict__ amask,
                __nv_bfloat16* __restrict__ Oh, __nv_bfloat16* __restrict__ Ol)
{
    extern __shared__ char sm[];
    uint32_t sb = smem_u32(sm);
    float* Sarr = (float*)(sm + AS_OFF);
    float* mS   = (float*)(sm + AST);
    float* lS   = mS + 64;
    float* scS  = lS + 64;
    float* mk   = scS + 64;

    int tid  = threadIdx.x;
    int lane = tid & 31;
    int warp = tid >> 5;
    int wm = warp & 3;
    int wn = warp >> 2;
    int qt = blockIdx.x;
    int h  = blockIdx.y;
    int b  = blockIdx.z;
    int kvh = h >> 2;

    const __nv_bfloat16* Qgh = Qh + ((size_t)(b*NH + h) * SEQ + qt*64) * HD;
    const __nv_bfloat16* Qgl = Ql + ((size_t)(b*NH + h) * SEQ + qt*64) * HD;
    const __nv_bfloat16* Kgh = Kh + ((size_t)(b*KVH + kvh) * SEQ) * HD;
    const __nv_bfloat16* Kgl = Kl + ((size_t)(b*KVH + kvh) * SEQ) * HD;
    const __nv_bfloat16* Vgh = Vh + ((size_t)(b*KVH + kvh) * SEQ) * HD;
    const __nv_bfloat16* Vgl = Vl + ((size_t)(b*KVH + kvh) * SEQ) * HD;

    #pragma unroll
    for (int it = 0; it < 4; it++) {
        int idx = it * 256 + tid;
        int r = idx >> 4;
        int c = idx & 15;
        size_t go = (size_t)r * HD + c*8;
        uint32_t so = r * AT_QKV_STRIDE + c*16;
        cp16(sb + AQH + so, Qgh + go);
        cp16(sb + AQL + so, Qgl + go);
    }
    cp_commit();

    auto issueKV = [&](int kt) {
        uint32_t base = sb + AKV + (kt & 1) * AKV_BUF;
        #pragma unroll
        for (int it = 0; it < 4; it++) {
            int idx = it * 256 + tid;
            int r = idx >> 4;
            int c = idx & 15;
            size_t go = (size_t)(kt*64 + r) * HD + c*8;
            uint32_t so = r * AT_QKV_STRIDE + c*16;
            cp16(base + 0     + so, Kgh + go);
            cp16(base + 17408 + so, Kgl + go);
            cp16(base + 34816 + so, Vgh + go);
            cp16(base + 52224 + so, Vgl + go);
        }
        cp_commit();
    };
    issueKV(0);

    if (tid < 64) { mS[tid] = -1e30f; lS[tid] = 0.f; }

    float o[8][4];
    #pragma unroll
    for (int i = 0; i < 8; i++)
        #pragma unroll
        for (int j = 0; j < 4; j++) o[i][j] = 0.f;

    for (int kt = 0; kt <= qt; kt++) {
        if (kt < qt) { issueKV(kt + 1); cp_wait<1>(); }
        else         { cp_wait<0>(); }
        __syncthreads();

        if (tid < 64)
            mk[tid] = (amask[b*SEQ + kt*64 + tid] > 0) ? 0.f : -1e30f;

        uint32_t kvbase = sb + AKV + (kt & 1) * AKV_BUF;

        float sacc[4][4];
        #pragma unroll
        for (int i = 0; i < 4; i++)
            #pragma unroll
            for (int j = 0; j < 4; j++) sacc[i][j] = 0.f;

        #pragma unroll
        for (int kk = 0; kk < 8; kk++) {
            uint32_t aH[4], aL[4];
            uint32_t aoff = (wm*16 + (lane & 15)) * AT_QKV_STRIDE
                          + kk*32 + ((lane >> 4) * 16);
            ldsm_x4(aH, sb + AQH + aoff);
            ldsm_x4(aL, sb + AQL + aoff);
            uint32_t bH[2][4], bL[2][4];
            #pragma unroll
            for (int nt = 0; nt < 2; nt++) {
                uint32_t nrow = wn*32 + nt*16 + (lane & 15);
                uint32_t boff = nrow * AT_QKV_STRIDE + kk*32 + ((lane >> 4) * 16);
                ldsm_x4(bH[nt], kvbase + 0     + boff);
                ldsm_x4(bL[nt], kvbase + 17408 + boff);
            }
            #pragma unroll
            for (int n8 = 0; n8 < 4; n8++) {
                int nt = n8 >> 1;
                int lo = n8 & 1;
                mma_bf16_2(sacc[n8], aH, bH[nt][lo], bH[nt][lo+2]);
                mma_bf16_2(sacc[n8], aH, bL[nt][lo], bL[nt][lo+2]);
                mma_bf16_2(sacc[n8], aL, bH[nt][lo], bH[nt][lo+2]);
            }
        }
        #pragma unroll
        for (int n8 = 0; n8 < 4; n8++) {
            #pragma unroll
            for (int half = 0; half < 2; half++) {
                int r = wm*16 + (lane >> 2) + half*8;
                int c = wn*32 + n8*8 + (lane & 3)*2;
                float2 v;
                v.x = sacc[n8][half*2+0];
                v.y = sacc[n8][half*2+1];
                *(float2*)&Sarr[r*AT_S_STRIDE + c] = v;
            }
        }
        __syncthreads();

        {
            int r = tid >> 2, q = tid & 3;
            int rg = qt*64 + r;
            float mo = mS[r];
            float lold = lS[r];
            float sv[16];
            float mx = mo;
            #pragma unroll
            for (int i = 0; i < 16; i++) {
                int c = q*16 + i;
                float s = Sarr[r*AT_S_STRIDE + c] + mk[c];
                if (kt*64 + c > rg) s = -1e30f;
                sv[i] = s;
                mx = fmaxf(mx, s);
            }
            mx = fmaxf(mx, __shfl_xor_sync(0xffffffff, mx, 1));
            mx = fmaxf(mx, __shfl_xor_sync(0xffffffff, mx, 2));
            float l = 0.f;
            __nv_bfloat16* PhRow = (__nv_bfloat16*)(sm + APH + r*AT_P_STRIDE);
            __nv_bfloat16* PlRow = (__nv_bfloat16*)(sm + APL + r*AT_P_STRIDE);
            #pragma unroll
            for (int i = 0; i < 16; i += 2) {
                float p0 = __expf(sv[i]   - mx);
                float p1 = __expf(sv[i+1] - mx);
                l += p0 + p1;
                __nv_bfloat16 h0 = __float2bfloat16(p0);
                __nv_bfloat16 h1 = __float2bfloat16(p1);
                __nv_bfloat16 l0 = __float2bfloat16(p0 - __bfloat162float(h0));
                __nv_bfloat16 l1 = __float2bfloat16(p1 - __bfloat162float(h1));
                __nv_bfloat162 ph; ph.x = h0; ph.y = h1;
                __nv_bfloat162 pl; pl.x = l0; pl.y = l1;
                *(__nv_bfloat162*)&PhRow[q*16 + i] = ph;
                *(__nv_bfloat162*)&PlRow[q*16 + i] = pl;
            }
            l += __shfl_xor_sync(0xffffffff, l, 1);
            l += __shfl_xor_sync(0xffffffff, l, 2);
            float sc = __expf(mo - mx);
            if (q == 0) {
                mS[r] = mx;
                lS[r] = lold * sc + l;
                scS[r] = sc;
            }
        }
        __syncthreads();

        {
            float sc0 = scS[wm*16 + (lane >> 2)];
            float sc1 = scS[wm*16 + (lane >> 2) + 8];
            #pragma unroll
            for (int n8 = 0; n8 < 8; n8++) {
                o[n8][0] *= sc0; o[n8][1] *= sc0;
                o[n8][2] *= sc1; o[n8][3] *= sc1;
            }
            #pragma unroll
            for (int ks = 0; ks < 4; ks++) {
                uint32_t aPH[4], aPL[4];
                uint32_t poff = (wm*16 + (lane & 15)) * AT_P_STRIDE
                              + ks*32 + ((lane >> 4) * 16);
                ldsm_x4(aPH, sb + APH + poff);
                ldsm_x4(aPL, sb + APL + poff);
                uint32_t vH[4][4], vL[4][4];
                #pragma unroll
                for (int nt = 0; nt < 4; nt++) {
                    uint32_t voff = (uint32_t)(ks*16 + (lane & 15)) * AT_QKV_STRIDE
                                  + (uint32_t)(wn*64 + nt*16)*2 + ((lane >> 4) * 16);
                    ldsm_x4t(vH[nt], kvbase + 34816 + voff);
                    ldsm_x4t(vL[nt], kvbase + 52224 + voff);
                }
                #pragma unroll
                for (int n8 = 0; n8 < 8; n8++) {
                    int nt = n8 >> 1, hf = (n8 & 1) * 2;
                    mma_bf16(o[n8], aPH, &vH[nt][hf]);
                    mma_bf16(o[n8], aPH, &vL[nt][hf]);
                    mma_bf16(o[n8], aPL, &vH[nt][hf]);
                }
            }
        }
        __syncthreads();
    }

    {
        int r0l = wm*16 + (lane >> 2);
        float inv0 = 1.f / lS[r0l];
        float inv1 = 1.f / lS[r0l + 8];
        #pragma unroll
        for (int half = 0; half < 2; half++) {
            int rloc = r0l + half*8;
            int rg = qt*64 + rloc;
            float inv = half ? inv1 : inv0;
            size_t rowoff = (size_t)(b*SEQ + rg) * DM + (size_t)h * HD;
            #pragma unroll
            for (int n8 = 0; n8 < 8; n8++) {
                int c = wn*64 + n8*8 + (lane & 3)*2;
                float f0 = o[n8][half*2+0] * inv;
                float f1 = o[n8][half*2+1] * inv;
                __nv_bfloat16 h0 = __float2bfloat16(f0);
                __nv_bfloat16 h1 = __float2bfloat16(f1);
                __nv_bfloat16 g0 = __float2bfloat16(f0 - __bfloat162float(h0));
                __nv_bfloat16 g1 = __float2bfloat16(f1 - __bfloat162float(h1));
                __nv_bfloat162 ph; ph.x = h0; ph.y = h1;
                __nv_bfloat162 pl; pl.x = g0; pl.y = g1;
                *(__nv_bfloat162*)&Oh[rowoff + c] = ph;
                *(__nv_bfloat162*)&Ol[rowoff + c] = pl;
            }
        }
    }
}

// ---------------------------------------------------------------------------
// kernel_launch
// ---------------------------------------------------------------------------
extern "C" void kernel_launch(void* const* d_in, const int* in_sizes, int n_in,
                              void* d_out, int out_size)
{
    const float* hidden = (const float*)d_in[0];
    const int*   amask  = (const int*)  d_in[1];
    const int*   posids = (const int*)  d_in[2];
    const float* wqkv   = (const float*)d_in[3];
    const float* w_out  = (const float*)d_in[4];
    const float* n1w    = (const float*)d_in[5];
    const float* n2w    = (const float*)d_in[6];
    const float* rsin   = (const float*)d_in[7];
    const float* rcos   = (const float*)d_in[8];
    float* out = (float*)d_out;

    float *p_qkv;
    __nv_bfloat16 *p_xnh, *p_xnl, *p_ath, *p_atl, *p_wqh, *p_wql, *p_woh, *p_wol;
    __nv_bfloat16 *p_qh, *p_ql, *p_kh, *p_kl, *p_vh, *p_vl;
    cudaGetSymbolAddress((void**)&p_qkv,  g_qkv);
    cudaGetSymbolAddress((void**)&p_xnh,  g_xn_h);
    cudaGetSymbolAddress((void**)&p_xnl,  g_xn_l);
    cudaGetSymbolAddress((void**)&p_ath,  g_at_h);
    cudaGetSymbolAddress((void**)&p_atl,  g_at_l);
    cudaGetSymbolAddress((void**)&p_wqh,  g_wq_h);
    cudaGetSymbolAddress((void**)&p_wql,  g_wq_l);
    cudaGetSymbolAddress((void**)&p_woh,  g_wo_h);
    cudaGetSymbolAddress((void**)&p_wol,  g_wo_l);
    cudaGetSymbolAddress((void**)&p_qh,   g_qh);
    cudaGetSymbolAddress((void**)&p_ql,   g_ql);
    cudaGetSymbolAddress((void**)&p_kh,   g_kh);
    cudaGetSymbolAddress((void**)&p_kl,   g_kl);
    cudaGetSymbolAddress((void**)&p_vh,   g_vh);
    cudaGetSymbolAddress((void**)&p_vl,   g_vl);

    cudaFuncSetAttribute(hgemm_kernel<0>,
                         cudaFuncAttributeMaxDynamicSharedMemorySize, HG_SMEM);
    cudaFuncSetAttribute(hgemm_kernel<1>,
                         cudaFuncAttributeMaxDynamicSharedMemorySize, HG_SMEM);
    cudaFuncSetAttribute(attn_mma_kernel,
                         cudaFuncAttributeMaxDynamicSharedMemorySize, ATT_SMEM);

    // 1. pre-norm -> bf16 hi/lo
    rmsnorm_split_kernel<<<BS, 256>>>(hidden, n1w, p_xnh, p_xnl);

    // weight conversions
    split_kernel<<<(DM*QKV_N/4 + 255)/256, 256>>>(wqkv, p_wqh, p_wql, DM*QKV_N/4);
    split_kernel<<<(DM*DM/4 + 255)/256, 256>>>(w_out, p_woh, p_wol, DM*DM/4);

    // 2. QKV projection + clip (HMMA bfx3)
    {
        dim3 grid(QKV_N/256, BS/128);
        hgemm_kernel<0><<<grid, 256, HG_SMEM>>>(p_xnh, p_xnl, p_wqh, p_wql,
                                                nullptr, p_qkv, BS, QKV_N, DM);
    }

    // 3. RoPE + split to bf16 hi/lo
    rope_kernel<<<BS, 256>>>(p_qkv, posids, rsin, rcos,
                             p_qh, p_ql, p_kh, p_kl, p_vh, p_vl);

    // 4. flash attention (HMMA bfx3)
    {
        dim3 grid(SEQ/64, NH, BATCH);
        attn_mma_kernel<<<grid, 256, ATT_SMEM>>>(p_qh, p_ql, p_kh, p_kl,
                                                 p_vh, p_vl, amask, p_ath, p_atl);
    }

    // 5. out-proj + residual add (HMMA bfx3)
    {
        dim3 grid(DM/256, BS/128);
        hgemm_kernel<1><<<grid, 256, HG_SMEM>>>(p_ath, p_atl, p_woh, p_wol,
                                                hidden, out, BS, DM, DM);
    }

    // 6. post-norm
    rmsnorm_kernel<<<BS, 256>>>(out, n2w, out + (size_t)BS * DM);
}

// round 6
// speedup vs baseline: 1.0074x; 1.0074x over previous
#include <cuda_runtime.h>
#include <cuda_bf16.h>
#include <math.h>
#include <stdint.h>

// Problem constants
#define BATCH   2
#define SEQ     2048
#define DM      2048
#define NH      16
#define KVH     4
#define HD      128
#define QKV_N   3072
#define BS      (BATCH*SEQ)   // 4096
#define QSCALE  0.08838834764831845f

// ---------------------------------------------------------------------------
// Scratch
// ---------------------------------------------------------------------------
__device__ float g_qkv [BS * QKV_N];

__device__ __nv_bfloat16 g_xn_h [BS * DM];
__device__ __nv_bfloat16 g_xn_l [BS * DM];
__device__ __nv_bfloat16 g_at_h [BS * DM];
__device__ __nv_bfloat16 g_at_l [BS * DM];
__device__ __nv_bfloat16 g_wq_h [DM * QKV_N];
__device__ __nv_bfloat16 g_wq_l [DM * QKV_N];
__device__ __nv_bfloat16 g_wo_h [DM * DM];
__device__ __nv_bfloat16 g_wo_l [DM * DM];

__device__ __nv_bfloat16 g_qh [BATCH * NH  * SEQ * HD];
__device__ __nv_bfloat16 g_ql [BATCH * NH  * SEQ * HD];
__device__ __nv_bfloat16 g_kh [BATCH * KVH * SEQ * HD];
__device__ __nv_bfloat16 g_kl [BATCH * KVH * SEQ * HD];
__device__ __nv_bfloat16 g_vh [BATCH * KVH * SEQ * HD];
__device__ __nv_bfloat16 g_vl [BATCH * KVH * SEQ * HD];

// ---------------------------------------------------------------------------
// PTX helpers
// ---------------------------------------------------------------------------
__device__ __forceinline__ uint32_t smem_u32(const void* p) {
    uint32_t a;
    asm("{ .reg .u64 t; cvta.to.shared.u64 t, %1; cvt.u32.u64 %0, t; }"
        : "=r"(a) : "l"(p));
    return a;
}
__device__ __forceinline__ void cp16(uint32_t dst, const void* src) {
    asm volatile("cp.async.cg.shared.global [%0], [%1], 16;"
                 :: "r"(dst), "l"(src));
}
__device__ __forceinline__ void cp_commit() {
    asm volatile("cp.async.commit_group;" ::: "memory");
}
template<int N>
__device__ __forceinline__ void cp_wait() {
    asm volatile("cp.async.wait_group %0;" :: "n"(N) : "memory");
}
__device__ __forceinline__ void ldsm_x4(uint32_t* r, uint32_t addr) {
    asm volatile("ldmatrix.sync.aligned.m8n8.x4.shared.b16 {%0,%1,%2,%3}, [%4];"
                 : "=r"(r[0]), "=r"(r[1]), "=r"(r[2]), "=r"(r[3]) : "r"(addr));
}
__device__ __forceinline__ void ldsm_x4t(uint32_t* r, uint32_t addr) {
    asm volatile("ldmatrix.sync.aligned.m8n8.x4.trans.shared.b16 {%0,%1,%2,%3}, [%4];"
                 : "=r"(r[0]), "=r"(r[1]), "=r"(r[2]), "=r"(r[3]) : "r"(addr));
}
__device__ __forceinline__ void mma_bf16(float* d, const uint32_t* a, const uint32_t* b) {
    asm volatile(
        "mma.sync.aligned.m16n8k16.row.col.f32.bf16.bf16.f32 "
        "{%0,%1,%2,%3}, {%4,%5,%6,%7}, {%8,%9}, {%0,%1,%2,%3};"
        : "+f"(d[0]), "+f"(d[1]), "+f"(d[2]), "+f"(d[3])
        : "r"(a[0]), "r"(a[1]), "r"(a[2]), "r"(a[3]), "r"(b[0]), "r"(b[1]));
}
__device__ __forceinline__ void mma_bf16_2(float* d, const uint32_t* a,
                                           uint32_t b0, uint32_t b1) {
    asm volatile(
        "mma.sync.aligned.m16n8k16.row.col.f32.bf16.bf16.f32 "
        "{%0,%1,%2,%3}, {%4,%5,%6,%7}, {%8,%9}, {%0,%1,%2,%3};"
        : "+f"(d[0]), "+f"(d[1]), "+f"(d[2]), "+f"(d[3])
        : "r"(a[0]), "r"(a[1]), "r"(a[2]), "r"(a[3]), "r"(b0), "r"(b1));
}

// ---------------------------------------------------------------------------
// RMSNorm (fp32 out)
// ---------------------------------------------------------------------------
__global__ void rmsnorm_kernel(const float* __restrict__ x,
                               const float* __restrict__ w,
                               float* __restrict__ y)
{
    __shared__ float red[256];
    int row = blockIdx.x;
    const float4* xr = (const float4*)(x + (size_t)row * DM);
    float s = 0.f;
    #pragma unroll
    for (int i = threadIdx.x; i < DM/4; i += 256) {
        float4 v = xr[i];
        s += v.x*v.x + v.y*v.y + v.z*v.z + v.w*v.w;
    }
    red[threadIdx.x] = s;
    __syncthreads();
    for (int st = 128; st > 0; st >>= 1) {
        if (threadIdx.x < st) red[threadIdx.x] += red[threadIdx.x + st];
        __syncthreads();
    }
    float rs = rsqrtf(red[0] * (1.0f/(float)DM) + 1e-5f);
    float4* yr = (float4*)(y + (size_t)row * DM);
    const float4* wr = (const float4*)w;
    #pragma unroll
    for (int i = threadIdx.x; i < DM/4; i += 256) {
        float4 v = xr[i];
        float4 ww = wr[i];
        v.x = v.x * rs * ww.x;
        v.y = v.y * rs * ww.y;
        v.z = v.z * rs * ww.z;
        v.w = v.w * rs * ww.w;
        yr[i] = v;
    }
}

// RMSNorm -> bf16 hi/lo split output
__global__ void rmsnorm_split_kernel(const float* __restrict__ x,
                                     const float* __restrict__ w,
                                     __nv_bfloat16* __restrict__ yh,
                                     __nv_bfloat16* __restrict__ yl)
{
    __shared__ float red[256];
    int row = blockIdx.x;
    const float4* xr = (const float4*)(x + (size_t)row * DM);
    float s = 0.f;
    #pragma unroll
    for (int i = threadIdx.x; i < DM/4; i += 256) {
        float4 v = xr[i];
        s += v.x*v.x + v.y*v.y + v.z*v.z + v.w*v.w;
    }
    red[threadIdx.x] = s;
    __syncthreads();
    for (int st = 128; st > 0; st >>= 1) {
        if (threadIdx.x < st) red[threadIdx.x] += red[threadIdx.x + st];
        __syncthreads();
    }
    float rs = rsqrtf(red[0] * (1.0f/(float)DM) + 1e-5f);
    const float4* wr = (const float4*)w;
    #pragma unroll
    for (int i = threadIdx.x; i < DM/4; i += 256) {
        float4 v = xr[i];
        float4 ww = wr[i];
        float f[4] = {v.x*rs*ww.x, v.y*rs*ww.y, v.z*rs*ww.z, v.w*rs*ww.w};
        __nv_bfloat16 h[4], l[4];
        #pragma unroll
        for (int j = 0; j < 4; j++) {
            h[j] = __float2bfloat16(f[j]);
            l[j] = __float2bfloat16(f[j] - __bfloat162float(h[j]));
        }
        size_t o = (size_t)row * DM + i*4;
        *(ulonglong1*)&yh[o] = *(ulonglong1*)h;
        *(ulonglong1*)&yl[o] = *(ulonglong1*)l;
    }
}

// fp32 -> bf16 hi/lo split
__global__ void split_kernel(const float* __restrict__ x,
                             __nv_bfloat16* __restrict__ xh,
                             __nv_bfloat16* __restrict__ xl, int n4)
{
    int i = blockIdx.x * blockDim.x + threadIdx.x;
    if (i >= n4) return;
    float4 v = ((const float4*)x)[i];
    float f[4] = {v.x, v.y, v.z, v.w};
    __nv_bfloat16 h[4], l[4];
    #pragma unroll
    for (int j = 0; j < 4; j++) {
        h[j] = __float2bfloat16(f[j]);
        l[j] = __float2bfloat16(f[j] - __bfloat162float(h[j]));
    }
    *(ulonglong1*)&xh[(size_t)i*4] = *(ulonglong1*)h;
    *(ulonglong1*)&xl[(size_t)i*4] = *(ulonglong1*)l;
}

// ---------------------------------------------------------------------------
// HMMA GEMM (bfx3), CTA 128x128, k-chunk 32, 2-stage. Term-major MMA order.
// EPI 0: clip. EPI 1: +Resid.
// ---------------------------------------------------------------------------
#define A_STRIDE  80
#define B_STRIDE  272
#define AH_OFF    0
#define AL_OFF    10240
#define BH_OFF    20480
#define BL_OFF    29184
#define CHUNK_SZ  37888
#define HG_SMEM   (2*CHUNK_SZ)

template<int EPI>
__global__ void __launch_bounds__(256)
hgemm_kernel(const __nv_bfloat16* __restrict__ Ah, const __nv_bfloat16* __restrict__ Al,
             const __nv_bfloat16* __restrict__ Bh, const __nv_bfloat16* __restrict__ Bl,
             const float* __restrict__ Resid, float* __restrict__ C,
             int M, int N, int K)
{
    extern __shared__ char sm[];
    uint32_t sb = smem_u32(sm);

    int tid  = threadIdx.x;
    int lane = tid & 31;
    int warp = tid >> 5;
    int warpM = warp & 1;
    int warpN = warp >> 1;
    int rowBase = blockIdx.y * 128;
    int colBase = blockIdx.x * 128;

    float acc[4][4][4];
    #pragma unroll
    for (int i = 0; i < 4; i++)
        #pragma unroll
        for (int j = 0; j < 4; j++)
            #pragma unroll
            for (int q = 0; q < 4; q++) acc[i][j][q] = 0.f;

    int nC = K / 32;

    auto issue = [&](int c) {
        int buf = c & 1;
        uint32_t base = sb + buf * CHUNK_SZ;
        int k0 = c * 32;
        #pragma unroll
        for (int it = 0; it < 2; it++) {
            int idx = it * 256 + tid;
            int r  = idx >> 2;
            int kc = idx & 3;
            size_t go = (size_t)(rowBase + r) * K + k0 + kc*8;
            uint32_t so = r * A_STRIDE + kc * 16;
            cp16(base + AH_OFF + so, Ah + go);
            cp16(base + AL_OFF + so, Al + go);
        }
        #pragma unroll
        for (int it = 0; it < 2; it++) {
            int idx = it * 256 + tid;
            int r   = idx >> 4;
            int c16 = idx & 15;
            size_t go = (size_t)(k0 + r) * N + colBase + c16*8;
            uint32_t so = r * B_STRIDE + c16 * 16;
            cp16(base + BH_OFF + so, Bh + go);
            cp16(base + BL_OFF + so, Bl + go);
        }
        cp_commit();
    };

    issue(0);

    for (int c = 0; c < nC; c++) {
        if (c + 1 < nC) { issue(c + 1); cp_wait<1>(); }
        else            { cp_wait<0>(); }
        __syncthreads();

        uint32_t base = sb + (c & 1) * CHUNK_SZ;

        #pragma unroll
        for (int kk = 0; kk < 2; kk++) {
            uint32_t aR[2][4][4];
            #pragma unroll
            for (int mt = 0; mt < 4; mt++) {
                int r = warpM*64 + mt*16 + (lane & 15);
                uint32_t col = ((lane >> 4) * 16) + kk * 32;
                ldsm_x4(aR[0][mt], base + AH_OFF + r*A_STRIDE + col);
                ldsm_x4(aR[1][mt], base + AL_OFF + r*A_STRIDE + col);
            }
            uint32_t bR[2][2][4];
            #pragma unroll
            for (int nt = 0; nt < 2; nt++) {
                int r = kk*16 + (lane & 15);
                uint32_t col = (uint32_t)(warpN*32 + nt*16) * 2 + ((lane >> 4) * 16);
                ldsm_x4t(bR[0][nt], base + BH_OFF + r*B_STRIDE + col);
                ldsm_x4t(bR[1][nt], base + BL_OFF + r*B_STRIDE + col);
            }
            // Term-major order: consecutive MMAs hit distinct accumulators
            // (reuse distance 16 instead of 1 -> no RAW stalls on D).
            #pragma unroll
            for (int term = 0; term < 3; term++) {
                const uint32_t (*A)[4] = (term == 2) ? aR[1] : aR[0];
                const uint32_t (*B)[4] = (term == 1) ? bR[1] : bR[0];
                #pragma unroll
                for (int mt = 0; mt < 4; mt++) {
                    #pragma unroll
                    for (int n8 = 0; n8 < 4; n8++) {
                        int nt = n8 >> 1, hf = (n8 & 1) * 2;
                        mma_bf16(acc[mt][n8], A[mt], &B[nt][hf]);
                    }
                }
            }
        }
        __syncthreads();
    }

    int rg = lane >> 2;
    int cg = (lane & 3) * 2;
    #pragma unroll
    for (int mt = 0; mt < 4; mt++) {
        #pragma unroll
        for (int n8 = 0; n8 < 4; n8++) {
            int r0 = rowBase + warpM*64 + mt*16 + rg;
            int cc = colBase + warpN*32 + n8*8 + cg;
            #pragma unroll
            for (int half = 0; half < 2; half++) {
                int r = r0 + half * 8;
                float2 v;
                v.x = acc[mt][n8][half*2+0];
                v.y = acc[mt][n8][half*2+1];
                if (EPI == 0) {
                    v.x = fminf(8.f, fmaxf(-8.f, v.x));
                    v.y = fminf(8.f, fmaxf(-8.f, v.y));
                } else {
                    float2 rv = *(const float2*)&Resid[(size_t)r * N + cc];
                    v.x += rv.x; v.y += rv.y;
                }
                *(float2*)&C[(size_t)r * N + cc] = v;
            }
        }
    }
}

// ---------------------------------------------------------------------------
// RoPE + split to bf16 hi/lo Q/K/V
// ---------------------------------------------------------------------------
__global__ void rope_kernel(const float* __restrict__ qkv,
                            const int* __restrict__ posids,
                            const float* __restrict__ rsin,
                            const float* __restrict__ rcos,
                            __nv_bfloat16* __restrict__ Qh, __nv_bfloat16* __restrict__ Ql,
                            __nv_bfloat16* __restrict__ Kh, __nv_bfloat16* __restrict__ Kl,
                            __nv_bfloat16* __restrict__ Vh, __nv_bfloat16* __restrict__ Vl)
{
    int bs = blockIdx.x;
    int b = bs >> 11;
    int s = bs & 2047;
    int pos = posids[bs];
    const float* base = qkv + (size_t)bs * QKV_N;

    for (int idx = threadIdx.x; idx < QKV_N; idx += 256) {
        int head = idx >> 7;
        int d = idx & 127;
        float x = base[idx];
        float val;
        size_t o;
        __nv_bfloat16* Dh;
        __nv_bfloat16* Dl;
        if (head < NH + KVH) {
            float c  = rcos[pos * HD + d];
            float sn = rsin[pos * HD + d];
            float other = (d < 64) ? -base[head*HD + d + 64]
                                   :  base[head*HD + d - 64];
            val = x * c + other * sn;
            if (head < NH) {
                val *= QSCALE;
                o = (((size_t)(b*NH + head)) * SEQ + s) * HD + d;
                Dh = Qh; Dl = Ql;
            } else {
                o = (((size_t)(b*KVH + head - NH)) * SEQ + s) * HD + d;
                Dh = Kh; Dl = Kl;
            }
        } else {
            val = x;
            o = (((size_t)(b*KVH + head - NH - KVH)) * SEQ + s) * HD + d;
            Dh = Vh; Dl = Vl;
        }
        __nv_bfloat16 h = __float2bfloat16(val);
        __nv_bfloat16 l = __float2bfloat16(val - __bfloat162float(h));
        Dh[o] = h;
        Dl[o] = l;
    }
}

// ---------------------------------------------------------------------------
// Flash attention, HMMA bfx3, term-major MMA order.
// ---------------------------------------------------------------------------
#define AT_QKV_STRIDE 272
#define AT_P_STRIDE   144
#define AT_S_STRIDE   66
#define AQH 0
#define AQL 17408
#define AKV 34816
#define AKV_BUF 69632
#define AS_OFF  174080
#define APH 190976
#define APL 200192
#define AST 209408
#define ATT_SMEM 210432

__global__ void __launch_bounds__(256, 1)
attn_mma_kernel(const __nv_bfloat16* __restrict__ Qh, const __nv_bfloat16* __restrict__ Ql,
                const __nv_bfloat16* __restrict__ Kh, const __nv_bfloat16* __restrict__ Kl,
                const __nv_bfloat16* __restrict__ Vh, const __nv_bfloat16* __restrict__ Vl,
                const int* __restrict__ amask,
                __nv_bfloat16* __restrict__ Oh, __nv_bfloat16* __restrict__ Ol)
{
    extern __shared__ char sm[];
    uint32_t sb = smem_u32(sm);
    float* Sarr = (float*)(sm + AS_OFF);
    float* mS   = (float*)(sm + AST);
    float* lS   = mS + 64;
    float* scS  = lS + 64;
    float* mk   = scS + 64;

    int tid  = threadIdx.x;
    int lane = tid & 31;
    int warp = tid >> 5;
    int wm = warp & 3;
    int wn = warp >> 2;
    int qt = blockIdx.x;
    int h  = blockIdx.y;
    int b  = blockIdx.z;
    int kvh = h >> 2;

    const __nv_bfloat16* Qgh = Qh + ((size_t)(b*NH + h) * SEQ + qt*64) * HD;
    const __nv_bfloat16* Qgl = Ql + ((size_t)(b*NH + h) * SEQ + qt*64) * HD;
    const __nv_bfloat16* Kgh = Kh + ((size_t)(b*KVH + kvh) * SEQ) * HD;
    const __nv_bfloat16* Kgl = Kl + ((size_t)(b*KVH + kvh) * SEQ) * HD;
    const __nv_bfloat16* Vgh = Vh + ((size_t)(b*KVH + kvh) * SEQ) * HD;
    const __nv_bfloat16* Vgl = Vl + ((size_t)(b*KVH + kvh) * SEQ) * HD;

    #pragma unroll
    for (int it = 0; it < 4; it++) {
        int idx = it * 256 + tid;
        int r = idx >> 4;
        int c = idx & 15;
        size_t go = (size_t)r * HD + c*8;
        uint32_t so = r * AT_QKV_STRIDE + c*16;
        cp16(sb + AQH + so, Qgh + go);
        cp16(sb + AQL + so, Qgl + go);
    }
    cp_commit();

    auto issueKV = [&](int kt) {
        uint32_t base = sb + AKV + (kt & 1) * AKV_BUF;
        #pragma unroll
        for (int it = 0; it < 4; it++) {
            int idx = it * 256 + tid;
            int r = idx >> 4;
            int c = idx & 15;
            size_t go = (size_t)(kt*64 + r) * HD + c*8;
            uint32_t so = r * AT_QKV_STRIDE + c*16;
            cp16(base + 0     + so, Kgh + go);
            cp16(base + 17408 + so, Kgl + go);
            cp16(base + 34816 + so, Vgh + go);
            cp16(base + 52224 + so, Vgl + go);
        }
        cp_commit();
    };
    issueKV(0);

    if (tid < 64) { mS[tid] = -1e30f; lS[tid] = 0.f; }

    float o[8][4];
    #pragma unroll
    for (int i = 0; i < 8; i++)
        #pragma unroll
        for (int j = 0; j < 4; j++) o[i][j] = 0.f;

    for (int kt = 0; kt <= qt; kt++) {
        if (kt < qt) { issueKV(kt + 1); cp_wait<1>(); }
        else         { cp_wait<0>(); }
        __syncthreads();

        if (tid < 64)
            mk[tid] = (amask[b*SEQ + kt*64 + tid] > 0) ? 0.f : -1e30f;

        uint32_t kvbase = sb + AKV + (kt & 1) * AKV_BUF;

        float sacc[4][4];
        #pragma unroll
        for (int i = 0; i < 4; i++)
            #pragma unroll
            for (int j = 0; j < 4; j++) sacc[i][j] = 0.f;

        #pragma unroll
        for (int kk = 0; kk < 8; kk++) {
            uint32_t aH[4], aL[4];
            uint32_t aoff = (wm*16 + (lane & 15)) * AT_QKV_STRIDE
                          + kk*32 + ((lane >> 4) * 16);
            ldsm_x4(aH, sb + AQH + aoff);
            ldsm_x4(aL, sb + AQL + aoff);
            uint32_t bH[2][4], bL[2][4];
            #pragma unroll
            for (int nt = 0; nt < 2; nt++) {
                uint32_t nrow = wn*32 + nt*16 + (lane & 15);
                uint32_t boff = nrow * AT_QKV_STRIDE + kk*32 + ((lane >> 4) * 16);
                ldsm_x4(bH[nt], kvbase + 0     + boff);
                ldsm_x4(bL[nt], kvbase + 17408 + boff);
            }
            // term-major: distinct accumulators between consecutive MMAs
            #pragma unroll
            for (int term = 0; term < 3; term++) {
                const uint32_t* A = (term == 2) ? aL : aH;
                const uint32_t (*B)[4] = (term == 1) ? bL : bH;
                #pragma unroll
                for (int n8 = 0; n8 < 4; n8++) {
                    int nt = n8 >> 1;
                    int lo = n8 & 1;
                    mma_bf16_2(sacc[n8], A, B[nt][lo], B[nt][lo+2]);
                }
            }
        }
        #pragma unroll
        for (int n8 = 0; n8 < 4; n8++) {
            #pragma unroll
            for (int half = 0; half < 2; half++) {
                int r = wm*16 + (lane >> 2) + half*8;
                int c = wn*32 + n8*8 + (lane & 3)*2;
                float2 v;
                v.x = sacc[n8][half*2+0];
                v.y = sacc[n8][half*2+1];
                *(float2*)&Sarr[r*AT_S_STRIDE + c] = v;
            }
        }
        __syncthreads();

        {
            int r = tid >> 2, q = tid & 3;
            int rg = qt*64 + r;
            float mo = mS[r];
            float lold = lS[r];
            float sv[16];
            float mx = mo;
            #pragma unroll
            for (int i = 0; i < 16; i++) {
                int c = q*16 + i;
                float s = Sarr[r*AT_S_STRIDE + c] + mk[c];
                if (kt*64 + c > rg) s = -1e30f;
                sv[i] = s;
                mx = fmaxf(mx, s);
            }
            mx = fmaxf(mx, __shfl_xor_sync(0xffffffff, mx, 1));
            mx = fmaxf(mx, __shfl_xor_sync(0xffffffff, mx, 2));
            float l = 0.f;
            __nv_bfloat16* PhRow = (__nv_bfloat16*)(sm + APH + r*AT_P_STRIDE);
            __nv_bfloat16* PlRow = (__nv_bfloat16*)(sm + APL + r*AT_P_STRIDE);
            #pragma unroll
            for (int i = 0; i < 16; i += 2) {
                float p0 = __expf(sv[i]   - mx);
                float p1 = __expf(sv[i+1] - mx);
                l += p0 + p1;
                __nv_bfloat16 h0 = __float2bfloat16(p0);
                __nv_bfloat16 h1 = __float2bfloat16(p1);
                __nv_bfloat16 l0 = __float2bfloat16(p0 - __bfloat162float(h0));
                __nv_bfloat16 l1 = __float2bfloat16(p1 - __bfloat162float(h1));
                __nv_bfloat162 ph; ph.x = h0; ph.y = h1;
                __nv_bfloat162 pl; pl.x = l0; pl.y = l1;
                *(__nv_bfloat162*)&PhRow[q*16 + i] = ph;
                *(__nv_bfloat162*)&PlRow[q*16 + i] = pl;
            }
            l += __shfl_xor_sync(0xffffffff, l, 1);
            l += __shfl_xor_sync(0xffffffff, l, 2);
            float sc = __expf(mo - mx);
            if (q == 0) {
                mS[r] = mx;
                lS[r] = lold * sc + l;
                scS[r] = sc;
            }
        }
        __syncthreads();

        {
            float sc0 = scS[wm*16 + (lane >> 2)];
            float sc1 = scS[wm*16 + (lane >> 2) + 8];
            #pragma unroll
            for (int n8 = 0; n8 < 8; n8++) {
                o[n8][0] *= sc0; o[n8][1] *= sc0;
                o[n8][2] *= sc1; o[n8][3] *= sc1;
            }
            #pragma unroll
            for (int ks = 0; ks < 4; ks++) {
                uint32_t aPH[4], aPL[4];
                uint32_t poff = (wm*16 + (lane & 15)) * AT_P_STRIDE
                              + ks*32 + ((lane >> 4) * 16);
                ldsm_x4(aPH, sb + APH + poff);
                ldsm_x4(aPL, sb + APL + poff);
                uint32_t vH[4][4], vL[4][4];
                #pragma unroll
                for (int nt = 0; nt < 4; nt++) {
                    uint32_t voff = (uint32_t)(ks*16 + (lane & 15)) * AT_QKV_STRIDE
                                  + (uint32_t)(wn*64 + nt*16)*2 + ((lane >> 4) * 16);
                    ldsm_x4t(vH[nt], kvbase + 34816 + voff);
                    ldsm_x4t(vL[nt], kvbase + 52224 + voff);
                }
                // term-major
                #pragma unroll
                for (int term = 0; term < 3; term++) {
                    const uint32_t* A = (term == 2) ? aPL : aPH;
                    const uint32_t (*B)[4] = (term == 1) ? vL : vH;
                    #pragma unroll
                    for (int n8 = 0; n8 < 8; n8++) {
                        int nt = n8 >> 1, hf = (n8 & 1) * 2;
                        mma_bf16(o[n8], A, &B[nt][hf]);
                    }
                }
            }
        }
        __syncthreads();
    }

    {
        int r0l = wm*16 + (lane >> 2);
        float inv0 = 1.f / lS[r0l];
        float inv1 = 1.f / lS[r0l + 8];
        #pragma unroll
        for (int half = 0; half < 2; half++) {
            int rloc = r0l + half*8;
            int rg = qt*64 + rloc;
            float inv = half ? inv1 : inv0;
            size_t rowoff = (size_t)(b*SEQ + rg) * DM + (size_t)h * HD;
            #pragma unroll
            for (int n8 = 0; n8 < 8; n8++) {
                int c = wn*64 + n8*8 + (lane & 3)*2;
                float f0 = o[n8][half*2+0] * inv;
                float f1 = o[n8][half*2+1] * inv;
                __nv_bfloat16 h0 = __float2bfloat16(f0);
                __nv_bfloat16 h1 = __float2bfloat16(f1);
                __nv_bfloat16 g0 = __float2bfloat16(f0 - __bfloat162float(h0));
                __nv_bfloat16 g1 = __float2bfloat16(f1 - __bfloat162float(h1));
                __nv_bfloat162 ph; ph.x = h0; ph.y = h1;
                __nv_bfloat162 pl; pl.x = g0; pl.y = g1;
                *(__nv_bfloat162*)&Oh[rowoff + c] = ph;
                *(__nv_bfloat162*)&Ol[rowoff + c] = pl;
            }
        }
    }
}

// ---------------------------------------------------------------------------
// kernel_launch
// ---------------------------------------------------------------------------
extern "C" void kernel_launch(void* const* d_in, const int* in_sizes, int n_in,
                              void* d_out, int out_size)
{
    const float* hidden = (const float*)d_in[0];
    const int*   amask  = (const int*)  d_in[1];
    const int*   posids = (const int*)  d_in[2];
    const float* wqkv   = (const float*)d_in[3];
    const float* w_out  = (const float*)d_in[4];
    const float* n1w    = (const float*)d_in[5];
    const float* n2w    = (const float*)d_in[6];
    const float* rsin   = (const float*)d_in[7];
    const float* rcos   = (const float*)d_in[8];
    float* out = (float*)d_out;

    float *p_qkv;
    __nv_bfloat16 *p_xnh, *p_xnl, *p_ath, *p_atl, *p_wqh, *p_wql, *p_woh, *p_wol;
    __nv_bfloat16 *p_qh, *p_ql, *p_kh, *p_kl, *p_vh, *p_vl;
    cudaGetSymbolAddress((void**)&p_qkv,  g_qkv);
    cudaGetSymbolAddress((void**)&p_xnh,  g_xn_h);
    cudaGetSymbolAddress((void**)&p_xnl,  g_xn_l);
    cudaGetSymbolAddress((void**)&p_ath,  g_at_h);
    cudaGetSymbolAddress((void**)&p_atl,  g_at_l);
    cudaGetSymbolAddress((void**)&p_wqh,  g_wq_h);
    cudaGetSymbolAddress((void**)&p_wql,  g_wq_l);
    cudaGetSymbolAddress((void**)&p_woh,  g_wo_h);
    cudaGetSymbolAddress((void**)&p_wol,  g_wo_l);
    cudaGetSymbolAddress((void**)&p_qh,   g_qh);
    cudaGetSymbolAddress((void**)&p_ql,   g_ql);
    cudaGetSymbolAddress((void**)&p_kh,   g_kh);
    cudaGetSymbolAddress((void**)&p_kl,   g_kl);
    cudaGetSymbolAddress((void**)&p_vh,   g_vh);
    cudaGetSymbolAddress((void**)&p_vl,   g_vl);

    cudaFuncSetAttribute(hgemm_kernel<0>,
                         cudaFuncAttributeMaxDynamicSharedMemorySize, HG_SMEM);
    cudaFuncSetAttribute(hgemm_kernel<1>,
                         cudaFuncAttributeMaxDynamicSharedMemorySize, HG_SMEM);
    cudaFuncSetAttribute(attn_mma_kernel,
                         cudaFuncAttributeMaxDynamicSharedMemorySize, ATT_SMEM);

    // 1. pre-norm -> bf16 hi/lo
    rmsnorm_split_kernel<<<BS, 256>>>(hidden, n1w, p_xnh, p_xnl);

    // weight conversions
    split_kernel<<<(DM*QKV_N/4 + 255)/256, 256>>>(wqkv, p_wqh, p_wql, DM*QKV_N/4);
    split_kernel<<<(DM*DM/4 + 255)/256, 256>>>(w_out, p_woh, p_wol, DM*DM/4);

    // 2. QKV projection + clip (HMMA bfx3)
    {
        dim3 grid(QKV_N/128, BS/128);
        hgemm_kernel<0><<<grid, 256, HG_SMEM>>>(p_xnh, p_xnl, p_wqh, p_wql,
                                                nullptr, p_qkv, BS, QKV_N, DM);
    }

    // 3. RoPE + split to bf16 hi/lo
    rope_kernel<<<BS, 256>>>(p_qkv, posids, rsin, rcos,
                             p_qh, p_ql, p_kh, p_kl, p_vh, p_vl);

    // 4. flash attention (HMMA bfx3)
    {
        dim3 grid(SEQ/64, NH, BATCH);
        attn_mma_kernel<<<grid, 256, ATT_SMEM>>>(p_qh, p_ql, p_kh, p_kl,
                                                 p_vh, p_vl, amask, p_ath, p_atl);
    }

    // 5. out-proj + residual add (HMMA bfx3)
    {
        dim3 grid(DM/128, BS/128);
        hgemm_kernel<1><<<grid, 256, HG_SMEM>>>(p_ath, p_atl, p_woh, p_wol,
                                                hidden, out, BS, DM, DM);
    }

    // 6. post-norm
    rmsnorm_kernel<<<BS, 256>>>(out, n2w, out + (size_t)BS * DM);
}

// round 7
// speedup vs baseline: 1.0837x; 1.0757x over previous
#include <cuda_runtime.h>
#include <cuda_bf16.h>
#include <math.h>
#include <stdint.h>

// Problem constants
#define BATCH   2
#define SEQ     2048
#define DM      2048
#define NH      16
#define KVH     4
#define HD      128
#define QKV_N   3072
#define BS      (BATCH*SEQ)   // 4096
#define QSCALE  0.08838834764831845f

// ---------------------------------------------------------------------------
// Scratch
// ---------------------------------------------------------------------------
__device__ __nv_bfloat16 g_xn_h [BS * DM];
__device__ __nv_bfloat16 g_xn_l [BS * DM];
__device__ __nv_bfloat16 g_at_h [BS * DM];
__device__ __nv_bfloat16 g_at_l [BS * DM];
__device__ __nv_bfloat16 g_wq_h [DM * QKV_N];
__device__ __nv_bfloat16 g_wq_l [DM * QKV_N];
__device__ __nv_bfloat16 g_wo_h [DM * DM];
__device__ __nv_bfloat16 g_wo_l [DM * DM];

__device__ __nv_bfloat16 g_qh [BATCH * NH  * SEQ * HD];
__device__ __nv_bfloat16 g_ql [BATCH * NH  * SEQ * HD];
__device__ __nv_bfloat16 g_kh [BATCH * KVH * SEQ * HD];
__device__ __nv_bfloat16 g_kl [BATCH * KVH * SEQ * HD];
__device__ __nv_bfloat16 g_vh [BATCH * KVH * SEQ * HD];
__device__ __nv_bfloat16 g_vl [BATCH * KVH * SEQ * HD];

// ---------------------------------------------------------------------------
// PTX helpers
// ---------------------------------------------------------------------------
__device__ __forceinline__ uint32_t smem_u32(const void* p) {
    uint32_t a;
    asm("{ .reg .u64 t; cvta.to.shared.u64 t, %1; cvt.u32.u64 %0, t; }"
        : "=r"(a) : "l"(p));
    return a;
}
__device__ __forceinline__ void cp16(uint32_t dst, const void* src) {
    asm volatile("cp.async.cg.shared.global [%0], [%1], 16;"
                 :: "r"(dst), "l"(src));
}
__device__ __forceinline__ void cp_commit() {
    asm volatile("cp.async.commit_group;" ::: "memory");
}
template<int N>
__device__ __forceinline__ void cp_wait() {
    asm volatile("cp.async.wait_group %0;" :: "n"(N) : "memory");
}
__device__ __forceinline__ void ldsm_x4(uint32_t* r, uint32_t addr) {
    asm volatile("ldmatrix.sync.aligned.m8n8.x4.shared.b16 {%0,%1,%2,%3}, [%4];"
                 : "=r"(r[0]), "=r"(r[1]), "=r"(r[2]), "=r"(r[3]) : "r"(addr));
}
__device__ __forceinline__ void ldsm_x4t(uint32_t* r, uint32_t addr) {
    asm volatile("ldmatrix.sync.aligned.m8n8.x4.trans.shared.b16 {%0,%1,%2,%3}, [%4];"
                 : "=r"(r[0]), "=r"(r[1]), "=r"(r[2]), "=r"(r[3]) : "r"(addr));
}
__device__ __forceinline__ void mma_bf16(float* d, const uint32_t* a, const uint32_t* b) {
    asm volatile(
        "mma.sync.aligned.m16n8k16.row.col.f32.bf16.bf16.f32 "
        "{%0,%1,%2,%3}, {%4,%5,%6,%7}, {%8,%9}, {%0,%1,%2,%3};"
        : "+f"(d[0]), "+f"(d[1]), "+f"(d[2]), "+f"(d[3])
        : "r"(a[0]), "r"(a[1]), "r"(a[2]), "r"(a[3]), "r"(b[0]), "r"(b[1]));
}
__device__ __forceinline__ void mma_bf16_2(float* d, const uint32_t* a,
                                           uint32_t b0, uint32_t b1) {
    asm volatile(
        "mma.sync.aligned.m16n8k16.row.col.f32.bf16.bf16.f32 "
        "{%0,%1,%2,%3}, {%4,%5,%6,%7}, {%8,%9}, {%0,%1,%2,%3};"
        : "+f"(d[0]), "+f"(d[1]), "+f"(d[2]), "+f"(d[3])
        : "r"(a[0]), "r"(a[1]), "r"(a[2]), "r"(a[3]), "r"(b0), "r"(b1));
}
__device__ __forceinline__ uint32_t pack_bf16(float a, float b) {
    __nv_bfloat162 p;
    p.x = __float2bfloat16(a);
    p.y = __float2bfloat16(b);
    return *(uint32_t*)&p;
}

// ---------------------------------------------------------------------------
// RMSNorm (fp32 out)
// ---------------------------------------------------------------------------
__global__ void rmsnorm_kernel(const float* __restrict__ x,
                               const float* __restrict__ w,
                               float* __restrict__ y)
{
    __shared__ float red[256];
    int row = blockIdx.x;
    const float4* xr = (const float4*)(x + (size_t)row * DM);
    float s = 0.f;
    #pragma unroll
    for (int i = threadIdx.x; i < DM/4; i += 256) {
        float4 v = xr[i];
        s += v.x*v.x + v.y*v.y + v.z*v.z + v.w*v.w;
    }
    red[threadIdx.x] = s;
    __syncthreads();
    for (int st = 128; st > 0; st >>= 1) {
        if (threadIdx.x < st) red[threadIdx.x] += red[threadIdx.x + st];
        __syncthreads();
    }
    float rs = rsqrtf(red[0] * (1.0f/(float)DM) + 1e-5f);
    float4* yr = (float4*)(y + (size_t)row * DM);
    const float4* wr = (const float4*)w;
    #pragma unroll
    for (int i = threadIdx.x; i < DM/4; i += 256) {
        float4 v = xr[i];
        float4 ww = wr[i];
        v.x = v.x * rs * ww.x;
        v.y = v.y * rs * ww.y;
        v.z = v.z * rs * ww.z;
        v.w = v.w * rs * ww.w;
        yr[i] = v;
    }
}

// RMSNorm -> bf16 hi/lo split output
__global__ void rmsnorm_split_kernel(const float* __restrict__ x,
                                     const float* __restrict__ w,
                                     __nv_bfloat16* __restrict__ yh,
                                     __nv_bfloat16* __restrict__ yl)
{
    __shared__ float red[256];
    int row = blockIdx.x;
    const float4* xr = (const float4*)(x + (size_t)row * DM);
    float s = 0.f;
    #pragma unroll
    for (int i = threadIdx.x; i < DM/4; i += 256) {
        float4 v = xr[i];
        s += v.x*v.x + v.y*v.y + v.z*v.z + v.w*v.w;
    }
    red[threadIdx.x] = s;
    __syncthreads();
    for (int st = 128; st > 0; st >>= 1) {
        if (threadIdx.x < st) red[threadIdx.x] += red[threadIdx.x + st];
        __syncthreads();
    }
    float rs = rsqrtf(red[0] * (1.0f/(float)DM) + 1e-5f);
    const float4* wr = (const float4*)w;
    #pragma unroll
    for (int i = threadIdx.x; i < DM/4; i += 256) {
        float4 v = xr[i];
        float4 ww = wr[i];
        float f[4] = {v.x*rs*ww.x, v.y*rs*ww.y, v.z*rs*ww.z, v.w*rs*ww.w};
        __nv_bfloat16 h[4], l[4];
        #pragma unroll
        for (int j = 0; j < 4; j++) {
            h[j] = __float2bfloat16(f[j]);
            l[j] = __float2bfloat16(f[j] - __bfloat162float(h[j]));
        }
        size_t o = (size_t)row * DM + i*4;
        *(ulonglong1*)&yh[o] = *(ulonglong1*)h;
        *(ulonglong1*)&yl[o] = *(ulonglong1*)l;
    }
}

// fp32 -> bf16 hi/lo split
__global__ void split_kernel(const float* __restrict__ x,
                             __nv_bfloat16* __restrict__ xh,
                             __nv_bfloat16* __restrict__ xl, int n4)
{
    int i = blockIdx.x * blockDim.x + threadIdx.x;
    if (i >= n4) return;
    float4 v = ((const float4*)x)[i];
    float f[4] = {v.x, v.y, v.z, v.w};
    __nv_bfloat16 h[4], l[4];
    #pragma unroll
    for (int j = 0; j < 4; j++) {
        h[j] = __float2bfloat16(f[j]);
        l[j] = __float2bfloat16(f[j] - __bfloat162float(h[j]));
    }
    *(ulonglong1*)&xh[(size_t)i*4] = *(ulonglong1*)h;
    *(ulonglong1*)&xl[(size_t)i*4] = *(ulonglong1*)l;
}

// ---------------------------------------------------------------------------
// Shared GEMM tiling constants (CTA 128x128, k-chunk 32, 2-stage)
// ---------------------------------------------------------------------------
#define A_STRIDE  80
#define B_STRIDE  272
#define AH_OFF    0
#define AL_OFF    10240
#define BH_OFF    20480
#define BL_OFF    29184
#define CHUNK_SZ  37888
#define HG_SMEM   (2*CHUNK_SZ)

// ---------------------------------------------------------------------------
// HMMA GEMM mainloop macro-shared (written inline in both kernels)
// ---------------------------------------------------------------------------

// out-proj GEMM: C = A@B + Resid (fp32 out)
__global__ void __launch_bounds__(256)
hgemm_resid_kernel(const __nv_bfloat16* __restrict__ Ah, const __nv_bfloat16* __restrict__ Al,
                   const __nv_bfloat16* __restrict__ Bh, const __nv_bfloat16* __restrict__ Bl,
                   const float* __restrict__ Resid, float* __restrict__ C,
                   int M, int N, int K)
{
    extern __shared__ char sm[];
    uint32_t sb = smem_u32(sm);

    int tid  = threadIdx.x;
    int lane = tid & 31;
    int warp = tid >> 5;
    int warpM = warp & 1;
    int warpN = warp >> 1;
    int rowBase = blockIdx.y * 128;
    int colBase = blockIdx.x * 128;

    float acc[4][4][4];
    #pragma unroll
    for (int i = 0; i < 4; i++)
        #pragma unroll
        for (int j = 0; j < 4; j++)
            #pragma unroll
            for (int q = 0; q < 4; q++) acc[i][j][q] = 0.f;

    int nC = K / 32;

    auto issue = [&](int c) {
        int buf = c & 1;
        uint32_t base = sb + buf * CHUNK_SZ;
        int k0 = c * 32;
        #pragma unroll
        for (int it = 0; it < 2; it++) {
            int idx = it * 256 + tid;
            int r  = idx >> 2;
            int kc = idx & 3;
            size_t go = (size_t)(rowBase + r) * K + k0 + kc*8;
            uint32_t so = r * A_STRIDE + kc * 16;
            cp16(base + AH_OFF + so, Ah + go);
            cp16(base + AL_OFF + so, Al + go);
        }
        #pragma unroll
        for (int it = 0; it < 2; it++) {
            int idx = it * 256 + tid;
            int r   = idx >> 4;
            int c16 = idx & 15;
            size_t go = (size_t)(k0 + r) * N + colBase + c16*8;
            uint32_t so = r * B_STRIDE + c16 * 16;
            cp16(base + BH_OFF + so, Bh + go);
            cp16(base + BL_OFF + so, Bl + go);
        }
        cp_commit();
    };

    issue(0);

    for (int c = 0; c < nC; c++) {
        if (c + 1 < nC) { issue(c + 1); cp_wait<1>(); }
        else            { cp_wait<0>(); }
        __syncthreads();

        uint32_t base = sb + (c & 1) * CHUNK_SZ;

        #pragma unroll
        for (int kk = 0; kk < 2; kk++) {
            uint32_t aR[2][4][4];
            #pragma unroll
            for (int mt = 0; mt < 4; mt++) {
                int r = warpM*64 + mt*16 + (lane & 15);
                uint32_t col = ((lane >> 4) * 16) + kk * 32;
                ldsm_x4(aR[0][mt], base + AH_OFF + r*A_STRIDE + col);
                ldsm_x4(aR[1][mt], base + AL_OFF + r*A_STRIDE + col);
            }
            uint32_t bR[2][2][4];
            #pragma unroll
            for (int nt = 0; nt < 2; nt++) {
                int r = kk*16 + (lane & 15);
                uint32_t col = (uint32_t)(warpN*32 + nt*16) * 2 + ((lane >> 4) * 16);
                ldsm_x4t(bR[0][nt], base + BH_OFF + r*B_STRIDE + col);
                ldsm_x4t(bR[1][nt], base + BL_OFF + r*B_STRIDE + col);
            }
            #pragma unroll
            for (int term = 0; term < 3; term++) {
                const uint32_t (*A)[4] = (term == 2) ? aR[1] : aR[0];
                const uint32_t (*B)[4] = (term == 1) ? bR[1] : bR[0];
                #pragma unroll
                for (int mt = 0; mt < 4; mt++) {
                    #pragma unroll
                    for (int n8 = 0; n8 < 4; n8++) {
                        int nt = n8 >> 1, hf = (n8 & 1) * 2;
                        mma_bf16(acc[mt][n8], A[mt], &B[nt][hf]);
                    }
                }
            }
        }
        __syncthreads();
    }

    int rg = lane >> 2;
    int cg = (lane & 3) * 2;
    #pragma unroll
    for (int mt = 0; mt < 4; mt++) {
        #pragma unroll
        for (int n8 = 0; n8 < 4; n8++) {
            int r0 = rowBase + warpM*64 + mt*16 + rg;
            int cc = colBase + warpN*32 + n8*8 + cg;
            #pragma unroll
            for (int half = 0; half < 2; half++) {
                int r = r0 + half * 8;
                float2 v;
                v.x = acc[mt][n8][half*2+0];
                v.y = acc[mt][n8][half*2+1];
                float2 rv = *(const float2*)&Resid[(size_t)r * N + cc];
                v.x += rv.x; v.y += rv.y;
                *(float2*)&C[(size_t)r * N + cc] = v;
            }
        }
    }
}

// QKV GEMM with fused clip + RoPE + hi/lo split epilogue.
// Column tile == one head (128 cols). N = QKV_N, K = DM fixed.
#define CT_STRIDE 132
__global__ void __launch_bounds__(256)
hgemm_qkv_kernel(const __nv_bfloat16* __restrict__ Ah, const __nv_bfloat16* __restrict__ Al,
                 const __nv_bfloat16* __restrict__ Bh, const __nv_bfloat16* __restrict__ Bl,
                 const int* __restrict__ posids,
                 const float* __restrict__ rsin, const float* __restrict__ rcos,
                 __nv_bfloat16* __restrict__ Qh, __nv_bfloat16* __restrict__ Ql,
                 __nv_bfloat16* __restrict__ Kh, __nv_bfloat16* __restrict__ Kl,
                 __nv_bfloat16* __restrict__ Vh, __nv_bfloat16* __restrict__ Vl)
{
    extern __shared__ char sm[];
    uint32_t sb = smem_u32(sm);

    const int N = QKV_N, K = DM;
    int tid  = threadIdx.x;
    int lane = tid & 31;
    int warp = tid >> 5;
    int warpM = warp & 1;
    int warpN = warp >> 1;
    int rowBase = blockIdx.y * 128;
    int colBase = blockIdx.x * 128;

    float acc[4][4][4];
    #pragma unroll
    for (int i = 0; i < 4; i++)
        #pragma unroll
        for (int j = 0; j < 4; j++)
            #pragma unroll
            for (int q = 0; q < 4; q++) acc[i][j][q] = 0.f;

    int nC = K / 32;

    auto issue = [&](int c) {
        int buf = c & 1;
        uint32_t base = sb + buf * CHUNK_SZ;
        int k0 = c * 32;
        #pragma unroll
        for (int it = 0; it < 2; it++) {
            int idx = it * 256 + tid;
            int r  = idx >> 2;
            int kc = idx & 3;
            size_t go = (size_t)(rowBase + r) * K + k0 + kc*8;
            uint32_t so = r * A_STRIDE + kc * 16;
            cp16(base + AH_OFF + so, Ah + go);
            cp16(base + AL_OFF + so, Al + go);
        }
        #pragma unroll
        for (int it = 0; it < 2; it++) {
            int idx = it * 256 + tid;
            int r   = idx >> 4;
            int c16 = idx & 15;
            size_t go = (size_t)(k0 + r) * N + colBase + c16*8;
            uint32_t so = r * B_STRIDE + c16 * 16;
            cp16(base + BH_OFF + so, Bh + go);
            cp16(base + BL_OFF + so, Bl + go);
        }
        cp_commit();
    };

    issue(0);

    for (int c = 0; c < nC; c++) {
        if (c + 1 < nC) { issue(c + 1); cp_wait<1>(); }
        else            { cp_wait<0>(); }
        __syncthreads();

        uint32_t base = sb + (c & 1) * CHUNK_SZ;

        #pragma unroll
        for (int kk = 0; kk < 2; kk++) {
            uint32_t aR[2][4][4];
            #pragma unroll
            for (int mt = 0; mt < 4; mt++) {
                int r = warpM*64 + mt*16 + (lane & 15);
                uint32_t col = ((lane >> 4) * 16) + kk * 32;
                ldsm_x4(aR[0][mt], base + AH_OFF + r*A_STRIDE + col);
                ldsm_x4(aR[1][mt], base + AL_OFF + r*A_STRIDE + col);
            }
            uint32_t bR[2][2][4];
            #pragma unroll
            for (int nt = 0; nt < 2; nt++) {
                int r = kk*16 + (lane & 15);
                uint32_t col = (uint32_t)(warpN*32 + nt*16) * 2 + ((lane >> 4) * 16);
                ldsm_x4t(bR[0][nt], base + BH_OFF + r*B_STRIDE + col);
                ldsm_x4t(bR[1][nt], base + BL_OFF + r*B_STRIDE + col);
            }
            #pragma unroll
            for (int term = 0; term < 3; term++) {
                const uint32_t (*A)[4] = (term == 2) ? aR[1] : aR[0];
                const uint32_t (*B)[4] = (term == 1) ? bR[1] : bR[0];
                #pragma unroll
                for (int mt = 0; mt < 4; mt++) {
                    #pragma unroll
                    for (int n8 = 0; n8 < 4; n8++) {
                        int nt = n8 >> 1, hf = (n8 & 1) * 2;
                        mma_bf16(acc[mt][n8], A[mt], &B[nt][hf]);
                    }
                }
            }
        }
        __syncthreads();
    }

    // Stage clipped tile to smem (reuse cp buffers: mainloop fully drained)
    float* Ct = (float*)sm;
    int rg = lane >> 2;
    int cg = (lane & 3) * 2;
    #pragma unroll
    for (int mt = 0; mt < 4; mt++) {
        #pragma unroll
        for (int n8 = 0; n8 < 4; n8++) {
            int r0 = warpM*64 + mt*16 + rg;
            int cl = warpN*32 + n8*8 + cg;
            #pragma unroll
            for (int half = 0; half < 2; half++) {
                int r = r0 + half * 8;
                float vx = fminf(8.f, fmaxf(-8.f, acc[mt][n8][half*2+0]));
                float vy = fminf(8.f, fmaxf(-8.f, acc[mt][n8][half*2+1]));
                Ct[r*CT_STRIDE + cl]     = vx;
                Ct[r*CT_STRIDE + cl + 1] = vy;
            }
        }
    }
    __syncthreads();

    // RoPE + split + scatter
    int head = blockIdx.x;            // 0..23
    for (int idx = tid; idx < 128*128; idx += 256) {
        int r = idx >> 7;
        int d = idx & 127;
        int token = rowBase + r;
        int b = token >> 11;
        int s = token & 2047;
        float x = Ct[r*CT_STRIDE + d];
        float val;
        size_t o;
        __nv_bfloat16 *Dh, *Dl;
        if (head < NH + KVH) {
            int pos = posids[token];
            float cz  = rcos[pos * HD + d];
            float sn  = rsin[pos * HD + d];
            float other = (d < 64) ? -Ct[r*CT_STRIDE + d + 64]
                                   :  Ct[r*CT_STRIDE + d - 64];
            val = x * cz + other * sn;
            if (head < NH) {
                val *= QSCALE;
                o = (((size_t)(b*NH + head)) * SEQ + s) * HD + d;
                Dh = Qh; Dl = Ql;
            } else {
                o = (((size_t)(b*KVH + head - NH)) * SEQ + s) * HD + d;
                Dh = Kh; Dl = Kl;
            }
        } else {
            val = x;
            o = (((size_t)(b*KVH + head - NH - KVH)) * SEQ + s) * HD + d;
            Dh = Vh; Dl = Vl;
        }
        __nv_bfloat16 h = __float2bfloat16(val);
        __nv_bfloat16 l = __float2bfloat16(val - __bfloat162float(h));
        Dh[o] = h;
        Dl[o] = l;
    }
}

// ---------------------------------------------------------------------------
// FlashAttention-2: BM=128, BN=64, 8 warps (warp = 16 rows x full 64 cols).
// S and P register-resident; softmax via quad shuffles; one sync per k-tile.
// ---------------------------------------------------------------------------
#define AT_STRIDE 272           // 128 bf16 + 16B pad
#define AQH 0
#define AQL 34816
#define AKV 69632
#define AKV_BUF 69632           // per buf: KH 0 | KL 17408 | VH 34816 | VL 52224
#define AMK (AKV + 2*AKV_BUF)   // 208896: mask 2x64 ints
#define ATT_SMEM (AMK + 512)

__global__ void __launch_bounds__(256, 1)
attn_fa2_kernel(const __nv_bfloat16* __restrict__ Qh, const __nv_bfloat16* __restrict__ Ql,
                const __nv_bfloat16* __restrict__ Kh, const __nv_bfloat16* __restrict__ Kl,
                const __nv_bfloat16* __restrict__ Vh, const __nv_bfloat16* __restrict__ Vl,
                const int* __restrict__ amask,
                __nv_bfloat16* __restrict__ Oh, __nv_bfloat16* __restrict__ Ol)
{
    extern __shared__ char sm[];
    uint32_t sb = smem_u32(sm);
    int* mk = (int*)(sm + AMK);

    int tid  = threadIdx.x;
    int lane = tid & 31;
    int warp = tid >> 5;            // 0..7 = row group (16 rows)
    int qt = gridDim.x - 1 - blockIdx.x;   // descending for load balance
    int h  = blockIdx.y;
    int b  = blockIdx.z;
    int kvh = h >> 2;

    const __nv_bfloat16* Qgh = Qh + ((size_t)(b*NH + h) * SEQ + qt*128) * HD;
    const __nv_bfloat16* Qgl = Ql + ((size_t)(b*NH + h) * SEQ + qt*128) * HD;
    const __nv_bfloat16* Kgh = Kh + ((size_t)(b*KVH + kvh) * SEQ) * HD;
    const __nv_bfloat16* Kgl = Kl + ((size_t)(b*KVH + kvh) * SEQ) * HD;
    const __nv_bfloat16* Vgh = Vh + ((size_t)(b*KVH + kvh) * SEQ) * HD;
    const __nv_bfloat16* Vgl = Vl + ((size_t)(b*KVH + kvh) * SEQ) * HD;

    // Q tile: 128 rows hi/lo
    #pragma unroll
    for (int it = 0; it < 8; it++) {
        int idx = it * 256 + tid;
        int r = idx >> 4;
        int c = idx & 15;
        size_t go = (size_t)r * HD + c*8;
        uint32_t so = r * AT_STRIDE + c*16;
        cp16(sb + AQH + so, Qgh + go);
        cp16(sb + AQL + so, Qgl + go);
    }
    cp_commit();

    auto issueKV = [&](int kt) {
        uint32_t base = sb + AKV + (kt & 1) * AKV_BUF;
        #pragma unroll
        for (int it = 0; it < 4; it++) {
            int idx = it * 256 + tid;
            int r = idx >> 4;
            int c = idx & 15;
            size_t go = (size_t)(kt*64 + r) * HD + c*8;
            uint32_t so = r * AT_STRIDE + c*16;
            cp16(base + 0     + so, Kgh + go);
            cp16(base + 17408 + so, Kgl + go);
            cp16(base + 34816 + so, Vgh + go);
            cp16(base + 52224 + so, Vgl + go);
        }
        cp_commit();
    };
    issueKV(0);

    float m0 = -1e30f, m1 = -1e30f, l0 = 0.f, l1 = 0.f;
    float o[16][4];
    #pragma unroll
    for (int i = 0; i < 16; i++)
        #pragma unroll
        for (int j = 0; j < 4; j++) o[i][j] = 0.f;

    int ktLast = 2*qt + 1;
    int rloc = (lane >> 2);             // 0..7

    for (int kt = 0; kt <= ktLast; kt++) {
        if (tid < 64)
            mk[(kt & 1)*64 + tid] = (amask[b*SEQ + kt*64 + tid] > 0) ? 0 : 1;
        cp_wait<0>();
        __syncthreads();
        if (kt < ktLast) issueKV(kt + 1);

        uint32_t kvbase = sb + AKV + (kt & 1) * AKV_BUF;
        const int* mkc = mk + (kt & 1)*64;

        // skip warp-tiles fully above the diagonal
        bool active = !(kt == ktLast && warp < 4);
        if (active) {
            // ---- S = Q @ K^T : 16 x 64 per warp ----
            float sacc[8][4];
            #pragma unroll
            for (int i = 0; i < 8; i++)
                #pragma unroll
                for (int j = 0; j < 4; j++) sacc[i][j] = 0.f;

            #pragma unroll
            for (int kk = 0; kk < 8; kk++) {
                uint32_t aH[4], aL[4];
                uint32_t aoff = (warp*16 + (lane & 15)) * AT_STRIDE
                              + kk*32 + ((lane >> 4) * 16);
                ldsm_x4(aH, sb + AQH + aoff);
                ldsm_x4(aL, sb + AQL + aoff);
                uint32_t bH[4][4], bL[4][4];
                #pragma unroll
                for (int nt = 0; nt < 4; nt++) {
                    uint32_t nrow = nt*16 + (lane & 15);
                    uint32_t boff = nrow * AT_STRIDE + kk*32 + ((lane >> 4) * 16);
                    ldsm_x4(bH[nt], kvbase + 0     + boff);
                    ldsm_x4(bL[nt], kvbase + 17408 + boff);
                }
                #pragma unroll
                for (int term = 0; term < 3; term++) {
                    const uint32_t* A = (term == 2) ? aL : aH;
                    const uint32_t (*B)[4] = (term == 1) ? bL : bH;
                    #pragma unroll
                    for (int n8 = 0; n8 < 8; n8++) {
                        int nt = n8 >> 1;
                        int lo = n8 & 1;
                        mma_bf16_2(sacc[n8], A, B[nt][lo], B[nt][lo+2]);
                    }
                }
            }

            // ---- mask + in-register online softmax ----
            bool needCausal = (kt >= 2*qt);
            int rg0 = qt*128 + warp*16 + rloc;    // half0 row
            #pragma unroll
            for (int n8 = 0; n8 < 8; n8++) {
                int c0 = n8*8 + (lane & 3)*2;
                float mb0 = mkc[c0]   ? -1e30f : 0.f;
                float mb1 = mkc[c0+1] ? -1e30f : 0.f;
                sacc[n8][0] += mb0; sacc[n8][1] += mb1;
                sacc[n8][2] += mb0; sacc[n8][3] += mb1;
                if (needCausal) {
                    int cga = kt*64 + c0;
                    if (cga     > rg0)     sacc[n8][0] = -1e30f;
                    if (cga + 1 > rg0)     sacc[n8][1] = -1e30f;
                    if (cga     > rg0 + 8) sacc[n8][2] = -1e30f;
                    if (cga + 1 > rg0 + 8) sacc[n8][3] = -1e30f;
                }
            }
            float mx0 = m0, mx1 = m1;
            #pragma unroll
            for (int n8 = 0; n8 < 8; n8++) {
                mx0 = fmaxf(mx0, fmaxf(sacc[n8][0], sacc[n8][1]));
                mx1 = fmaxf(mx1, fmaxf(sacc[n8][2], sacc[n8][3]));
            }
            mx0 = fmaxf(mx0, __shfl_xor_sync(0xffffffff, mx0, 1));
            mx0 = fmaxf(mx0, __shfl_xor_sync(0xffffffff, mx0, 2));
            mx1 = fmaxf(mx1, __shfl_xor_sync(0xffffffff, mx1, 1));
            mx1 = fmaxf(mx1, __shfl_xor_sync(0xffffffff, mx1, 2));
            float ls0 = 0.f, ls1 = 0.f;
            #pragma unroll
            for (int n8 = 0; n8 < 8; n8++) {
                sacc[n8][0] = __expf(sacc[n8][0] - mx0);
                sacc[n8][1] = __expf(sacc[n8][1] - mx0);
                sacc[n8][2] = __expf(sacc[n8][2] - mx1);
                sacc[n8][3] = __expf(sacc[n8][3] - mx1);
                ls0 += sacc[n8][0] + sacc[n8][1];
                ls1 += sacc[n8][2] + sacc[n8][3];
            }
            ls0 += __shfl_xor_sync(0xffffffff, ls0, 1);
            ls0 += __shfl_xor_sync(0xffffffff, ls0, 2);
            ls1 += __shfl_xor_sync(0xffffffff, ls1, 1);
            ls1 += __shfl_xor_sync(0xffffffff, ls1, 2);
            float sc0 = __expf(m0 - mx0);
            float sc1 = __expf(m1 - mx1);
            m0 = mx0; m1 = mx1;
            l0 = l0 * sc0 + ls0;
            l1 = l1 * sc1 + ls1;

            // repack P (hi/lo) into A-fragments: layout identity, no smem
            uint32_t ph[8][2], pl[8][2];
            #pragma unroll
            for (int n8 = 0; n8 < 8; n8++) {
                float p0 = sacc[n8][0], p1 = sacc[n8][1];
                float p2 = sacc[n8][2], p3 = sacc[n8][3];
                __nv_bfloat16 h0 = __float2bfloat16(p0);
                __nv_bfloat16 h1 = __float2bfloat16(p1);
                __nv_bfloat16 h2 = __float2bfloat16(p2);
                __nv_bfloat16 h3 = __float2bfloat16(p3);
                __nv_bfloat162 t;
                t.x = h0; t.y = h1; ph[n8][0] = *(uint32_t*)&t;
                t.x = h2; t.y = h3; ph[n8][1] = *(uint32_t*)&t;
                t.x = __float2bfloat16(p0 - __bfloat162float(h0));
                t.y = __float2bfloat16(p1 - __bfloat162float(h1));
                pl[n8][0] = *(uint32_t*)&t;
                t.x = __float2bfloat16(p2 - __bfloat162float(h2));
                t.y = __float2bfloat16(p3 - __bfloat162float(h3));
                pl[n8][1] = *(uint32_t*)&t;
            }

            // rescale O
            #pragma unroll
            for (int n8 = 0; n8 < 16; n8++) {
                o[n8][0] *= sc0; o[n8][1] *= sc0;
                o[n8][2] *= sc1; o[n8][3] *= sc1;
            }

            // ---- O += P @ V ----
            #pragma unroll
            for (int ks = 0; ks < 4; ks++) {
                uint32_t aPH[4] = {ph[2*ks][0], ph[2*ks][1], ph[2*ks+1][0], ph[2*ks+1][1]};
                uint32_t aPL[4] = {pl[2*ks][0], pl[2*ks][1], pl[2*ks+1][0], pl[2*ks+1][1]};
                uint32_t vH[8][4], vL[8][4];
                #pragma unroll
                for (int nt = 0; nt < 8; nt++) {
                    uint32_t voff = (uint32_t)(ks*16 + (lane & 15)) * AT_STRIDE
                                  + (uint32_t)(nt*16)*2 + ((lane >> 4) * 16);
                    ldsm_x4t(vH[nt], kvbase + 34816 + voff);
                    ldsm_x4t(vL[nt], kvbase + 52224 + voff);
                }
                #pragma unroll
                for (int term = 0; term < 3; term++) {
                    const uint32_t* A = (term == 2) ? aPL : aPH;
                    const uint32_t (*B)[4] = (term == 1) ? vL : vH;
                    #pragma unroll
                    for (int n8 = 0; n8 < 16; n8++) {
                        int nt = n8 >> 1, hf = (n8 & 1) * 2;
                        mma_bf16(o[n8], A, &B[nt][hf]);
                    }
                }
            }
        }
    }

    // ---- epilogue: O /= l, write bf16 hi/lo ----
    {
        float inv0 = 1.f / l0;
        float inv1 = 1.f / l1;
        #pragma unroll
        for (int half = 0; half < 2; half++) {
            int rg = qt*128 + warp*16 + rloc + half*8;
            float inv = half ? inv1 : inv0;
            size_t rowoff = (size_t)(b*SEQ + rg) * DM + (size_t)h * HD;
            #pragma unroll
            for (int n8 = 0; n8 < 16; n8++) {
                int c = n8*8 + (lane & 3)*2;
                float f0 = o[n8][half*2+0] * inv;
                float f1 = o[n8][half*2+1] * inv;
                __nv_bfloat16 h0 = __float2bfloat16(f0);
                __nv_bfloat16 h1 = __float2bfloat16(f1);
                __nv_bfloat16 g0 = __float2bfloat16(f0 - __bfloat162float(h0));
                __nv_bfloat16 g1 = __float2bfloat16(f1 - __bfloat162float(h1));
                __nv_bfloat162 pp; pp.x = h0; pp.y = h1;
                __nv_bfloat162 qq; qq.x = g0; qq.y = g1;
                *(__nv_bfloat162*)&Oh[rowoff + c] = pp;
                *(__nv_bfloat162*)&Ol[rowoff + c] = qq;
            }
        }
    }
}

// ---------------------------------------------------------------------------
// kernel_launch
// ---------------------------------------------------------------------------
extern "C" void kernel_launch(void* const* d_in, const int* in_sizes, int n_in,
                              void* d_out, int out_size)
{
    const float* hidden = (const float*)d_in[0];
    const int*   amask  = (const int*)  d_in[1];
    const int*   posids = (const int*)  d_in[2];
    const float* wqkv   = (const float*)d_in[3];
    const float* w_out  = (const float*)d_in[4];
    const float* n1w    = (const float*)d_in[5];
    const float* n2w    = (const float*)d_in[6];
    const float* rsin   = (const float*)d_in[7];
    const float* rcos   = (const float*)d_in[8];
    float* out = (float*)d_out;

    __nv_bfloat16 *p_xnh, *p_xnl, *p_ath, *p_atl, *p_wqh, *p_wql, *p_woh, *p_wol;
    __nv_bfloat16 *p_qh, *p_ql, *p_kh, *p_kl, *p_vh, *p_vl;
    cudaGetSymbolAddress((void**)&p_xnh,  g_xn_h);
    cudaGetSymbolAddress((void**)&p_xnl,  g_xn_l);
    cudaGetSymbolAddress((void**)&p_ath,  g_at_h);
    cudaGetSymbolAddress((void**)&p_atl,  g_at_l);
    cudaGetSymbolAddress((void**)&p_wqh,  g_wq_h);
    cudaGetSymbolAddress((void**)&p_wql,  g_wq_l);
    cudaGetSymbolAddress((void**)&p_woh,  g_wo_h);
    cudaGetSymbolAddress((void**)&p_wol,  g_wo_l);
    cudaGetSymbolAddress((void**)&p_qh,   g_qh);
    cudaGetSymbolAddress((void**)&p_ql,   g_ql);
    cudaGetSymbolAddress((void**)&p_kh,   g_kh);
    cudaGetSymbolAddress((void**)&p_kl,   g_kl);
    cudaGetSymbolAddress((void**)&p_vh,   g_vh);
    cudaGetSymbolAddress((void**)&p_vl,   g_vl);

    cudaFuncSetAttribute(hgemm_qkv_kernel,
                         cudaFuncAttributeMaxDynamicSharedMemorySize, HG_SMEM);
    cudaFuncSetAttribute(hgemm_resid_kernel,
                         cudaFuncAttributeMaxDynamicSharedMemorySize, HG_SMEM);
    cudaFuncSetAttribute(attn_fa2_kernel,
                         cudaFuncAttributeMaxDynamicSharedMemorySize, ATT_SMEM);

    // 1. pre-norm -> bf16 hi/lo
    rmsnorm_split_kernel<<<BS, 256>>>(hidden, n1w, p_xnh, p_xnl);

    // weight conversions
    split_kernel<<<(DM*QKV_N/4 + 255)/256, 256>>>(wqkv, p_wqh, p_wql, DM*QKV_N/4);
    split_kernel<<<(DM*DM/4 + 255)/256, 256>>>(w_out, p_woh, p_wol, DM*DM/4);

    // 2. QKV projection + clip + RoPE + split (fused)
    {
        dim3 grid(QKV_N/128, BS/128);
        hgemm_qkv_kernel<<<grid, 256, HG_SMEM>>>(p_xnh, p_xnl, p_wqh, p_wql,
                                                 posids, rsin, rcos,
                                                 p_qh, p_ql, p_kh, p_kl, p_vh, p_vl);
    }

    // 3. flash attention (FA2, HMMA bfx3)
    {
        dim3 grid(SEQ/128, NH, BATCH);
        attn_fa2_kernel<<<grid, 256, ATT_SMEM>>>(p_qh, p_ql, p_kh, p_kl,
                                                 p_vh, p_vl, amask, p_ath, p_atl);
    }

    // 4. out-proj + residual add
    {
        dim3 grid(DM/128, BS/128);
        hgemm_resid_kernel<<<grid, 256, HG_SMEM>>>(p_ath, p_atl, p_woh, p_wol,
                                                   hidden, out, BS, DM, DM);
    }

    // 5. post-norm
    rmsnorm_kernel<<<BS, 256>>>(out, n2w, out + (size_t)BS * DM);
}

// round 8
// speedup vs baseline: 1.5430x; 1.4239x over previous
#include <cuda_runtime.h>
#include <cuda_fp16.h>
#include <math.h>
#include <stdint.h>

// Problem constants
#define BATCH   2
#define SEQ     2048
#define DM      2048
#define NH      16
#define KVH     4
#define HD      128
#define QKV_N   3072
#define BS      (BATCH*SEQ)   // 4096
#define QSCALE  0.08838834764831845f

// ---------------------------------------------------------------------------
// Scratch (fp16; A-side operands keep only hi, B-side keeps hi+lo)
// ---------------------------------------------------------------------------
__device__ __half g_xn_h [BS * DM];
__device__ __half g_at_h [BS * DM];
__device__ __half g_wq_h [DM * QKV_N];
__device__ __half g_wq_l [DM * QKV_N];
__device__ __half g_wo_h [DM * DM];
__device__ __half g_wo_l [DM * DM];

__device__ __half g_qh [BATCH * NH  * SEQ * HD];
__device__ __half g_kh [BATCH * KVH * SEQ * HD];
__device__ __half g_kl [BATCH * KVH * SEQ * HD];
__device__ __half g_vh [BATCH * KVH * SEQ * HD];
__device__ __half g_vl [BATCH * KVH * SEQ * HD];

// ---------------------------------------------------------------------------
// PTX helpers
// ---------------------------------------------------------------------------
__device__ __forceinline__ uint32_t smem_u32(const void* p) {
    uint32_t a;
    asm("{ .reg .u64 t; cvta.to.shared.u64 t, %1; cvt.u32.u64 %0, t; }"
        : "=r"(a) : "l"(p));
    return a;
}
__device__ __forceinline__ void cp16(uint32_t dst, const void* src) {
    asm volatile("cp.async.cg.shared.global [%0], [%1], 16;"
                 :: "r"(dst), "l"(src));
}
__device__ __forceinline__ void cp_commit() {
    asm volatile("cp.async.commit_group;" ::: "memory");
}
template<int N>
__device__ __forceinline__ void cp_wait() {
    asm volatile("cp.async.wait_group %0;" :: "n"(N) : "memory");
}
__device__ __forceinline__ void ldsm_x4(uint32_t* r, uint32_t addr) {
    asm volatile("ldmatrix.sync.aligned.m8n8.x4.shared.b16 {%0,%1,%2,%3}, [%4];"
                 : "=r"(r[0]), "=r"(r[1]), "=r"(r[2]), "=r"(r[3]) : "r"(addr));
}
__device__ __forceinline__ void ldsm_x4t(uint32_t* r, uint32_t addr) {
    asm volatile("ldmatrix.sync.aligned.m8n8.x4.trans.shared.b16 {%0,%1,%2,%3}, [%4];"
                 : "=r"(r[0]), "=r"(r[1]), "=r"(r[2]), "=r"(r[3]) : "r"(addr));
}
__device__ __forceinline__ void mma_f16(float* d, const uint32_t* a, const uint32_t* b) {
    asm volatile(
        "mma.sync.aligned.m16n8k16.row.col.f32.f16.f16.f32 "
        "{%0,%1,%2,%3}, {%4,%5,%6,%7}, {%8,%9}, {%0,%1,%2,%3};"
        : "+f"(d[0]), "+f"(d[1]), "+f"(d[2]), "+f"(d[3])
        : "r"(a[0]), "r"(a[1]), "r"(a[2]), "r"(a[3]), "r"(b[0]), "r"(b[1]));
}
__device__ __forceinline__ void mma_f16_2(float* d, const uint32_t* a,
                                          uint32_t b0, uint32_t b1) {
    asm volatile(
        "mma.sync.aligned.m16n8k16.row.col.f32.f16.f16.f32 "
        "{%0,%1,%2,%3}, {%4,%5,%6,%7}, {%8,%9}, {%0,%1,%2,%3};"
        : "+f"(d[0]), "+f"(d[1]), "+f"(d[2]), "+f"(d[3])
        : "r"(a[0]), "r"(a[1]), "r"(a[2]), "r"(a[3]), "r"(b0), "r"(b1));
}

// ---------------------------------------------------------------------------
// RMSNorm (fp32 out)
// ---------------------------------------------------------------------------
__global__ void rmsnorm_kernel(const float* __restrict__ x,
                               const float* __restrict__ w,
                               float* __restrict__ y)
{
    __shared__ float red[256];
    int row = blockIdx.x;
    const float4* xr = (const float4*)(x + (size_t)row * DM);
    float s = 0.f;
    #pragma unroll
    for (int i = threadIdx.x; i < DM/4; i += 256) {
        float4 v = xr[i];
        s += v.x*v.x + v.y*v.y + v.z*v.z + v.w*v.w;
    }
    red[threadIdx.x] = s;
    __syncthreads();
    for (int st = 128; st > 0; st >>= 1) {
        if (threadIdx.x < st) red[threadIdx.x] += red[threadIdx.x + st];
        __syncthreads();
    }
    float rs = rsqrtf(red[0] * (1.0f/(float)DM) + 1e-5f);
    float4* yr = (float4*)(y + (size_t)row * DM);
    const float4* wr = (const float4*)w;
    #pragma unroll
    for (int i = threadIdx.x; i < DM/4; i += 256) {
        float4 v = xr[i];
        float4 ww = wr[i];
        v.x = v.x * rs * ww.x;
        v.y = v.y * rs * ww.y;
        v.z = v.z * rs * ww.z;
        v.w = v.w * rs * ww.w;
        yr[i] = v;
    }
}

// RMSNorm -> fp16 (hi only; A-side of QKV GEMM)
__global__ void rmsnorm_h_kernel(const float* __restrict__ x,
                                 const float* __restrict__ w,
                                 __half* __restrict__ yh)
{
    __shared__ float red[256];
    int row = blockIdx.x;
    const float4* xr = (const float4*)(x + (size_t)row * DM);
    float s = 0.f;
    #pragma unroll
    for (int i = threadIdx.x; i < DM/4; i += 256) {
        float4 v = xr[i];
        s += v.x*v.x + v.y*v.y + v.z*v.z + v.w*v.w;
    }
    red[threadIdx.x] = s;
    __syncthreads();
    for (int st = 128; st > 0; st >>= 1) {
        if (threadIdx.x < st) red[threadIdx.x] += red[threadIdx.x + st];
        __syncthreads();
    }
    float rs = rsqrtf(red[0] * (1.0f/(float)DM) + 1e-5f);
    const float4* wr = (const float4*)w;
    #pragma unroll
    for (int i = threadIdx.x; i < DM/4; i += 256) {
        float4 v = xr[i];
        float4 ww = wr[i];
        __half h[4];
        h[0] = __float2half(v.x*rs*ww.x);
        h[1] = __float2half(v.y*rs*ww.y);
        h[2] = __float2half(v.z*rs*ww.z);
        h[3] = __float2half(v.w*rs*ww.w);
        *(ulonglong1*)&yh[(size_t)row * DM + i*4] = *(ulonglong1*)h;
    }
}

// fp32 -> fp16 hi/lo split (weights: B-side)
__global__ void split_kernel(const float* __restrict__ x,
                             __half* __restrict__ xh,
                             __half* __restrict__ xl, int n4)
{
    int i = blockIdx.x * blockDim.x + threadIdx.x;
    if (i >= n4) return;
    float4 v = ((const float4*)x)[i];
    float f[4] = {v.x, v.y, v.z, v.w};
    __half h[4], l[4];
    #pragma unroll
    for (int j = 0; j < 4; j++) {
        h[j] = __float2half(f[j]);
        l[j] = __float2half(f[j] - __half2float(h[j]));
    }
    *(ulonglong1*)&xh[(size_t)i*4] = *(ulonglong1*)h;
    *(ulonglong1*)&xl[(size_t)i*4] = *(ulonglong1*)l;
}

// ---------------------------------------------------------------------------
// GEMM tiling: CTA 128x128, k-chunk 32, 2-stage. A hi-only; B hi+lo.
// ---------------------------------------------------------------------------
#define A_STRIDE  80
#define B_STRIDE  272
#define AH_OFF    0
#define BH_OFF    10240      // 128*80
#define BL_OFF    18944      // +32*272
#define CHUNK_SZ  27648
#define HG_SMEM   (2*CHUNK_SZ)   // 55296
#define CT_STRIDE 132
#define HGQ_SMEM  67584          // 128*132*4 (epilogue staging)

// out-proj GEMM: C = A@B + Resid (fp32 out)
__global__ void __launch_bounds__(256)
hgemm_resid_kernel(const __half* __restrict__ Ah,
                   const __half* __restrict__ Bh, const __half* __restrict__ Bl,
                   const float* __restrict__ Resid, float* __restrict__ C,
                   int M, int N, int K)
{
    extern __shared__ char sm[];
    uint32_t sb = smem_u32(sm);

    int tid  = threadIdx.x;
    int lane = tid & 31;
    int warp = tid >> 5;
    int warpM = warp & 1;
    int warpN = warp >> 1;
    int rowBase = blockIdx.y * 128;
    int colBase = blockIdx.x * 128;

    float acc[4][4][4];
    #pragma unroll
    for (int i = 0; i < 4; i++)
        #pragma unroll
        for (int j = 0; j < 4; j++)
            #pragma unroll
            for (int q = 0; q < 4; q++) acc[i][j][q] = 0.f;

    int nC = K / 32;

    auto issue = [&](int c) {
        uint32_t base = sb + (c & 1) * CHUNK_SZ;
        int k0 = c * 32;
        #pragma unroll
        for (int it = 0; it < 2; it++) {
            int idx = it * 256 + tid;
            int r  = idx >> 2;
            int kc = idx & 3;
            cp16(base + AH_OFF + r * A_STRIDE + kc * 16,
                 Ah + (size_t)(rowBase + r) * K + k0 + kc*8);
        }
        #pragma unroll
        for (int it = 0; it < 2; it++) {
            int idx = it * 256 + tid;
            int r   = idx >> 4;
            int c16 = idx & 15;
            size_t go = (size_t)(k0 + r) * N + colBase + c16*8;
            uint32_t so = r * B_STRIDE + c16 * 16;
            cp16(base + BH_OFF + so, Bh + go);
            cp16(base + BL_OFF + so, Bl + go);
        }
        cp_commit();
    };

    issue(0);

    for (int c = 0; c < nC; c++) {
        if (c + 1 < nC) { issue(c + 1); cp_wait<1>(); }
        else            { cp_wait<0>(); }
        __syncthreads();

        uint32_t base = sb + (c & 1) * CHUNK_SZ;

        #pragma unroll
        for (int kk = 0; kk < 2; kk++) {
            uint32_t aR[4][4];
            #pragma unroll
            for (int mt = 0; mt < 4; mt++) {
                int r = warpM*64 + mt*16 + (lane & 15);
                uint32_t col = ((lane >> 4) * 16) + kk * 32;
                ldsm_x4(aR[mt], base + AH_OFF + r*A_STRIDE + col);
            }
            uint32_t bR[2][2][4];
            #pragma unroll
            for (int nt = 0; nt < 2; nt++) {
                int r = kk*16 + (lane & 15);
                uint32_t col = (uint32_t)(warpN*32 + nt*16) * 2 + ((lane >> 4) * 16);
                ldsm_x4t(bR[0][nt], base + BH_OFF + r*B_STRIDE + col);
                ldsm_x4t(bR[1][nt], base + BL_OFF + r*B_STRIDE + col);
            }
            #pragma unroll
            for (int term = 0; term < 2; term++) {
                const uint32_t (*B)[4] = bR[term];
                #pragma unroll
                for (int mt = 0; mt < 4; mt++) {
                    #pragma unroll
                    for (int n8 = 0; n8 < 4; n8++) {
                        int nt = n8 >> 1, hf = (n8 & 1) * 2;
                        mma_f16(acc[mt][n8], aR[mt], &B[nt][hf]);
                    }
                }
            }
        }
        __syncthreads();
    }

    int rg = lane >> 2;
    int cg = (lane & 3) * 2;
    #pragma unroll
    for (int mt = 0; mt < 4; mt++) {
        #pragma unroll
        for (int n8 = 0; n8 < 4; n8++) {
            int r0 = rowBase + warpM*64 + mt*16 + rg;
            int cc = colBase + warpN*32 + n8*8 + cg;
            #pragma unroll
            for (int half = 0; half < 2; half++) {
                int r = r0 + half * 8;
                float2 v;
                v.x = acc[mt][n8][half*2+0];
                v.y = acc[mt][n8][half*2+1];
                float2 rv = *(const float2*)&Resid[(size_t)r * N + cc];
                v.x += rv.x; v.y += rv.y;
                *(float2*)&C[(size_t)r * N + cc] = v;
            }
        }
    }
}

// QKV GEMM with fused clip + RoPE + fp16 split epilogue.
__global__ void __launch_bounds__(256)
hgemm_qkv_kernel(const __half* __restrict__ Ah,
                 const __half* __restrict__ Bh, const __half* __restrict__ Bl,
                 const int* __restrict__ posids,
                 const float* __restrict__ rsin, const float* __restrict__ rcos,
                 __half* __restrict__ Qh,
                 __half* __restrict__ Kh, __half* __restrict__ Kl,
                 __half* __restrict__ Vh, __half* __restrict__ Vl)
{
    extern __shared__ char sm[];
    uint32_t sb = smem_u32(sm);

    const int N = QKV_N, K = DM;
    int tid  = threadIdx.x;
    int lane = tid & 31;
    int warp = tid >> 5;
    int warpM = warp & 1;
    int warpN = warp >> 1;
    int rowBase = blockIdx.y * 128;
    int colBase = blockIdx.x * 128;

    float acc[4][4][4];
    #pragma unroll
    for (int i = 0; i < 4; i++)
        #pragma unroll
        for (int j = 0; j < 4; j++)
            #pragma unroll
            for (int q = 0; q < 4; q++) acc[i][j][q] = 0.f;

    int nC = K / 32;

    auto issue = [&](int c) {
        uint32_t base = sb + (c & 1) * CHUNK_SZ;
        int k0 = c * 32;
        #pragma unroll
        for (int it = 0; it < 2; it++) {
            int idx = it * 256 + tid;
            int r  = idx >> 2;
            int kc = idx & 3;
            cp16(base + AH_OFF + r * A_STRIDE + kc * 16,
                 Ah + (size_t)(rowBase + r) * K + k0 + kc*8);
        }
        #pragma unroll
        for (int it = 0; it < 2; it++) {
            int idx = it * 256 + tid;
            int r   = idx >> 4;
            int c16 = idx & 15;
            size_t go = (size_t)(k0 + r) * N + colBase + c16*8;
            uint32_t so = r * B_STRIDE + c16 * 16;
            cp16(base + BH_OFF + so, Bh + go);
            cp16(base + BL_OFF + so, Bl + go);
        }
        cp_commit();
    };

    issue(0);

    for (int c = 0; c < nC; c++) {
        if (c + 1 < nC) { issue(c + 1); cp_wait<1>(); }
        else            { cp_wait<0>(); }
        __syncthreads();

        uint32_t base = sb + (c & 1) * CHUNK_SZ;

        #pragma unroll
        for (int kk = 0; kk < 2; kk++) {
            uint32_t aR[4][4];
            #pragma unroll
            for (int mt = 0; mt < 4; mt++) {
                int r = warpM*64 + mt*16 + (lane & 15);
                uint32_t col = ((lane >> 4) * 16) + kk * 32;
                ldsm_x4(aR[mt], base + AH_OFF + r*A_STRIDE + col);
            }
            uint32_t bR[2][2][4];
            #pragma unroll
            for (int nt = 0; nt < 2; nt++) {
                int r = kk*16 + (lane & 15);
                uint32_t col = (uint32_t)(warpN*32 + nt*16) * 2 + ((lane >> 4) * 16);
                ldsm_x4t(bR[0][nt], base + BH_OFF + r*B_STRIDE + col);
                ldsm_x4t(bR[1][nt], base + BL_OFF + r*B_STRIDE + col);
            }
            #pragma unroll
            for (int term = 0; term < 2; term++) {
                const uint32_t (*B)[4] = bR[term];
                #pragma unroll
                for (int mt = 0; mt < 4; mt++) {
                    #pragma unroll
                    for (int n8 = 0; n8 < 4; n8++) {
                        int nt = n8 >> 1, hf = (n8 & 1) * 2;
                        mma_f16(acc[mt][n8], aR[mt], &B[nt][hf]);
                    }
                }
            }
        }
        __syncthreads();
    }

    // Stage clipped tile in smem (cp buffers fully drained)
    float* Ct = (float*)sm;
    int rg = lane >> 2;
    int cg = (lane & 3) * 2;
    #pragma unroll
    for (int mt = 0; mt < 4; mt++) {
        #pragma unroll
        for (int n8 = 0; n8 < 4; n8++) {
            int r0 = warpM*64 + mt*16 + rg;
            int cl = warpN*32 + n8*8 + cg;
            #pragma unroll
            for (int half = 0; half < 2; half++) {
                int r = r0 + half * 8;
                Ct[r*CT_STRIDE + cl]     = fminf(8.f, fmaxf(-8.f, acc[mt][n8][half*2+0]));
                Ct[r*CT_STRIDE + cl + 1] = fminf(8.f, fmaxf(-8.f, acc[mt][n8][half*2+1]));
            }
        }
    }
    __syncthreads();

    // RoPE + split + scatter (Q hi only; K/V hi+lo)
    int head = blockIdx.x;            // 0..23
    for (int idx = tid; idx < 128*128; idx += 256) {
        int r = idx >> 7;
        int d = idx & 127;
        int token = rowBase + r;
        int b = token >> 11;
        int s = token & 2047;
        float x = Ct[r*CT_STRIDE + d];
        if (head < NH) {
            int pos = posids[token];
            float cz = rcos[pos * HD + d];
            float sn = rsin[pos * HD + d];
            float other = (d < 64) ? -Ct[r*CT_STRIDE + d + 64]
                                   :  Ct[r*CT_STRIDE + d - 64];
            float val = (x * cz + other * sn) * QSCALE;
            Qh[(((size_t)(b*NH + head)) * SEQ + s) * HD + d] = __float2half(val);
        } else if (head < NH + KVH) {
            int pos = posids[token];
            float cz = rcos[pos * HD + d];
            float sn = rsin[pos * HD + d];
            float other = (d < 64) ? -Ct[r*CT_STRIDE + d + 64]
                                   :  Ct[r*CT_STRIDE + d - 64];
            float val = x * cz + other * sn;
            size_t o = (((size_t)(b*KVH + head - NH)) * SEQ + s) * HD + d;
            __half h = __float2half(val);
            Kh[o] = h;
            Kl[o] = __float2half(val - __half2float(h));
        } else {
            size_t o = (((size_t)(b*KVH + head - NH - KVH)) * SEQ + s) * HD + d;
            __half h = __float2half(x);
            Vh[o] = h;
            Vl[o] = __float2half(x - __half2float(h));
        }
    }
}

// ---------------------------------------------------------------------------
// FlashAttention-2: BM=128, BN=64, 8 warps. Q/P hi only; K/V hi+lo.
// ---------------------------------------------------------------------------
#define AT_STRIDE 272
#define AQH 0
#define AKV 34816
#define AKV_BUF 69632          // per buf: KH 0 | KL 17408 | VH 34816 | VL 52224
#define AMK (AKV + 2*AKV_BUF)  // 174080
#define ATT_SMEM (AMK + 512)

__global__ void __launch_bounds__(256, 1)
attn_fa2_kernel(const __half* __restrict__ Qh,
                const __half* __restrict__ Kh, const __half* __restrict__ Kl,
                const __half* __restrict__ Vh, const __half* __restrict__ Vl,
                const int* __restrict__ amask,
                __half* __restrict__ Oh)
{
    extern __shared__ char sm[];
    uint32_t sb = smem_u32(sm);
    int* mk = (int*)(sm + AMK);

    int tid  = threadIdx.x;
    int lane = tid & 31;
    int warp = tid >> 5;
    int qt = gridDim.x - 1 - blockIdx.x;
    int h  = blockIdx.y;
    int b  = blockIdx.z;
    int kvh = h >> 2;

    const __half* Qg  = Qh + ((size_t)(b*NH + h) * SEQ + qt*128) * HD;
    const __half* Kgh = Kh + ((size_t)(b*KVH + kvh) * SEQ) * HD;
    const __half* Kgl = Kl + ((size_t)(b*KVH + kvh) * SEQ) * HD;
    const __half* Vgh = Vh + ((size_t)(b*KVH + kvh) * SEQ) * HD;
    const __half* Vgl = Vl + ((size_t)(b*KVH + kvh) * SEQ) * HD;

    #pragma unroll
    for (int it = 0; it < 8; it++) {
        int idx = it * 256 + tid;
        int r = idx >> 4;
        int c = idx & 15;
        cp16(sb + AQH + r * AT_STRIDE + c*16, Qg + (size_t)r * HD + c*8);
    }
    cp_commit();

    auto issueKV = [&](int kt) {
        uint32_t base = sb + AKV + (kt & 1) * AKV_BUF;
        #pragma unroll
        for (int it = 0; it < 4; it++) {
            int idx = it * 256 + tid;
            int r = idx >> 4;
            int c = idx & 15;
            size_t go = (size_t)(kt*64 + r) * HD + c*8;
            uint32_t so = r * AT_STRIDE + c*16;
            cp16(base + 0     + so, Kgh + go);
            cp16(base + 17408 + so, Kgl + go);
            cp16(base + 34816 + so, Vgh + go);
            cp16(base + 52224 + so, Vgl + go);
        }
        cp_commit();
    };
    issueKV(0);

    float m0 = -1e30f, m1 = -1e30f, l0 = 0.f, l1 = 0.f;
    float o[16][4];
    #pragma unroll
    for (int i = 0; i < 16; i++)
        #pragma unroll
        for (int j = 0; j < 4; j++) o[i][j] = 0.f;

    int ktLast = 2*qt + 1;
    int rloc = (lane >> 2);

    for (int kt = 0; kt <= ktLast; kt++) {
        if (tid < 64)
            mk[(kt & 1)*64 + tid] = (amask[b*SEQ + kt*64 + tid] > 0) ? 0 : 1;
        cp_wait<0>();
        __syncthreads();
        if (kt < ktLast) issueKV(kt + 1);

        uint32_t kvbase = sb + AKV + (kt & 1) * AKV_BUF;
        const int* mkc = mk + (kt & 1)*64;

        bool active = !(kt == ktLast && warp < 4);
        if (active) {
            // ---- S = Q @ K^T ----
            float sacc[8][4];
            #pragma unroll
            for (int i = 0; i < 8; i++)
                #pragma unroll
                for (int j = 0; j < 4; j++) sacc[i][j] = 0.f;

            #pragma unroll
            for (int kk = 0; kk < 8; kk++) {
                uint32_t aQ[4];
                uint32_t aoff = (warp*16 + (lane & 15)) * AT_STRIDE
                              + kk*32 + ((lane >> 4) * 16);
                ldsm_x4(aQ, sb + AQH + aoff);
                uint32_t bH[4][4], bL[4][4];
                #pragma unroll
                for (int nt = 0; nt < 4; nt++) {
                    uint32_t boff = (uint32_t)(nt*16 + (lane & 15)) * AT_STRIDE
                                  + kk*32 + ((lane >> 4) * 16);
                    ldsm_x4(bH[nt], kvbase + 0     + boff);
                    ldsm_x4(bL[nt], kvbase + 17408 + boff);
                }
                #pragma unroll
                for (int term = 0; term < 2; term++) {
                    const uint32_t (*B)[4] = term ? bL : bH;
                    #pragma unroll
                    for (int n8 = 0; n8 < 8; n8++) {
                        int nt = n8 >> 1;
                        int lo = n8 & 1;
                        mma_f16_2(sacc[n8], aQ, B[nt][lo], B[nt][lo+2]);
                    }
                }
            }

            // ---- mask + online softmax ----
            bool needCausal = (kt >= 2*qt);
            int rg0 = qt*128 + warp*16 + rloc;
            #pragma unroll
            for (int n8 = 0; n8 < 8; n8++) {
                int c0 = n8*8 + (lane & 3)*2;
                float mb0 = mkc[c0]   ? -1e30f : 0.f;
                float mb1 = mkc[c0+1] ? -1e30f : 0.f;
                sacc[n8][0] += mb0; sacc[n8][1] += mb1;
                sacc[n8][2] += mb0; sacc[n8][3] += mb1;
                if (needCausal) {
                    int cga = kt*64 + c0;
                    if (cga     > rg0)     sacc[n8][0] = -1e30f;
                    if (cga + 1 > rg0)     sacc[n8][1] = -1e30f;
                    if (cga     > rg0 + 8) sacc[n8][2] = -1e30f;
                    if (cga + 1 > rg0 + 8) sacc[n8][3] = -1e30f;
                }
            }
            float mx0 = m0, mx1 = m1;
            #pragma unroll
            for (int n8 = 0; n8 < 8; n8++) {
                mx0 = fmaxf(mx0, fmaxf(sacc[n8][0], sacc[n8][1]));
                mx1 = fmaxf(mx1, fmaxf(sacc[n8][2], sacc[n8][3]));
            }
            mx0 = fmaxf(mx0, __shfl_xor_sync(0xffffffff, mx0, 1));
            mx0 = fmaxf(mx0, __shfl_xor_sync(0xffffffff, mx0, 2));
            mx1 = fmaxf(mx1, __shfl_xor_sync(0xffffffff, mx1, 1));
            mx1 = fmaxf(mx1, __shfl_xor_sync(0xffffffff, mx1, 2));
            float ls0 = 0.f, ls1 = 0.f;
            #pragma unroll
            for (int n8 = 0; n8 < 8; n8++) {
                sacc[n8][0] = __expf(sacc[n8][0] - mx0);
                sacc[n8][1] = __expf(sacc[n8][1] - mx0);
                sacc[n8][2] = __expf(sacc[n8][2] - mx1);
                sacc[n8][3] = __expf(sacc[n8][3] - mx1);
                ls0 += sacc[n8][0] + sacc[n8][1];
                ls1 += sacc[n8][2] + sacc[n8][3];
            }
            ls0 += __shfl_xor_sync(0xffffffff, ls0, 1);
            ls0 += __shfl_xor_sync(0xffffffff, ls0, 2);
            ls1 += __shfl_xor_sync(0xffffffff, ls1, 1);
            ls1 += __shfl_xor_sync(0xffffffff, ls1, 2);
            float sc0 = __expf(m0 - mx0);
            float sc1 = __expf(m1 - mx1);
            m0 = mx0; m1 = mx1;
            l0 = l0 * sc0 + ls0;
            l1 = l1 * sc1 + ls1;

            // repack P (hi only) into A-fragments
            uint32_t ph[8][2];
            #pragma unroll
            for (int n8 = 0; n8 < 8; n8++) {
                __half2 t;
                t.x = __float2half(sacc[n8][0]);
                t.y = __float2half(sacc[n8][1]);
                ph[n8][0] = *(uint32_t*)&t;
                t.x = __float2half(sacc[n8][2]);
                t.y = __float2half(sacc[n8][3]);
                ph[n8][1] = *(uint32_t*)&t;
            }

            // rescale O
            #pragma unroll
            for (int n8 = 0; n8 < 16; n8++) {
                o[n8][0] *= sc0; o[n8][1] *= sc0;
                o[n8][2] *= sc1; o[n8][3] *= sc1;
            }

            // ---- O += P @ V ----
            #pragma unroll
            for (int ks = 0; ks < 4; ks++) {
                uint32_t aP[4] = {ph[2*ks][0], ph[2*ks][1], ph[2*ks+1][0], ph[2*ks+1][1]};
                uint32_t vH[8][4], vL[8][4];
                #pragma unroll
                for (int nt = 0; nt < 8; nt++) {
                    uint32_t voff = (uint32_t)(ks*16 + (lane & 15)) * AT_STRIDE
                                  + (uint32_t)(nt*16)*2 + ((lane >> 4) * 16);
                    ldsm_x4t(vH[nt], kvbase + 34816 + voff);
                    ldsm_x4t(vL[nt], kvbase + 52224 + voff);
                }
                #pragma unroll
                for (int term = 0; term < 2; term++) {
                    const uint32_t (*B)[4] = term ? vL : vH;
                    #pragma unroll
                    for (int n8 = 0; n8 < 16; n8++) {
                        int nt = n8 >> 1, hf = (n8 & 1) * 2;
                        mma_f16(o[n8], aP, &B[nt][hf]);
                    }
                }
            }
        }
    }

    // ---- epilogue: O /= l, write fp16 hi ----
    {
        float inv0 = 1.f / l0;
        float inv1 = 1.f / l1;
        #pragma unroll
        for (int half = 0; half < 2; half++) {
            int rg = qt*128 + warp*16 + rloc + half*8;
            float inv = half ? inv1 : inv0;
            size_t rowoff = (size_t)(b*SEQ + rg) * DM + (size_t)h * HD;
            #pragma unroll
            for (int n8 = 0; n8 < 16; n8++) {
                int c = n8*8 + (lane & 3)*2;
                __half2 pp;
                pp.x = __float2half(o[n8][half*2+0] * inv);
                pp.y = __float2half(o[n8][half*2+1] * inv);
                *(__half2*)&Oh[rowoff + c] = pp;
            }
        }
    }
}

// ---------------------------------------------------------------------------
// kernel_launch
// ---------------------------------------------------------------------------
extern "C" void kernel_launch(void* const* d_in, const int* in_sizes, int n_in,
                              void* d_out, int out_size)
{
    const float* hidden = (const float*)d_in[0];
    const int*   amask  = (const int*)  d_in[1];
    const int*   posids = (const int*)  d_in[2];
    const float* wqkv   = (const float*)d_in[3];
    const float* w_out  = (const float*)d_in[4];
    const float* n1w    = (const float*)d_in[5];
    const float* n2w    = (const float*)d_in[6];
    const float* rsin   = (const float*)d_in[7];
    const float* rcos   = (const float*)d_in[8];
    float* out = (float*)d_out;

    __half *p_xnh, *p_ath, *p_wqh, *p_wql, *p_woh, *p_wol;
    __half *p_qh, *p_kh, *p_kl, *p_vh, *p_vl;
    cudaGetSymbolAddress((void**)&p_xnh,  g_xn_h);
    cudaGetSymbolAddress((void**)&p_ath,  g_at_h);
    cudaGetSymbolAddress((void**)&p_wqh,  g_wq_h);
    cudaGetSymbolAddress((void**)&p_wql,  g_wq_l);
    cudaGetSymbolAddress((void**)&p_woh,  g_wo_h);
    cudaGetSymbolAddress((void**)&p_wol,  g_wo_l);
    cudaGetSymbolAddress((void**)&p_qh,   g_qh);
    cudaGetSymbolAddress((void**)&p_kh,   g_kh);
    cudaGetSymbolAddress((void**)&p_kl,   g_kl);
    cudaGetSymbolAddress((void**)&p_vh,   g_vh);
    cudaGetSymbolAddress((void**)&p_vl,   g_vl);

    cudaFuncSetAttribute(hgemm_qkv_kernel,
                         cudaFuncAttributeMaxDynamicSharedMemorySize, HGQ_SMEM);
    cudaFuncSetAttribute(hgemm_resid_kernel,
                         cudaFuncAttributeMaxDynamicSharedMemorySize, HG_SMEM);
    cudaFuncSetAttribute(attn_fa2_kernel,
                         cudaFuncAttributeMaxDynamicSharedMemorySize, ATT_SMEM);

    // 1. pre-norm -> fp16 (A-side: hi only)
    rmsnorm_h_kernel<<<BS, 256>>>(hidden, n1w, p_xnh);

    // weight conversions (B-side: hi+lo)
    split_kernel<<<(DM*QKV_N/4 + 255)/256, 256>>>(wqkv, p_wqh, p_wql, DM*QKV_N/4);
    split_kernel<<<(DM*DM/4 + 255)/256, 256>>>(w_out, p_woh, p_wol, DM*DM/4);

    // 2. QKV projection + clip + RoPE + split (fused, fp16x2)
    {
        dim3 grid(QKV_N/128, BS/128);
        hgemm_qkv_kernel<<<grid, 256, HGQ_SMEM>>>(p_xnh, p_wqh, p_wql,
                                                  posids, rsin, rcos,
                                                  p_qh, p_kh, p_kl, p_vh, p_vl);
    }

    // 3. flash attention (FA2, fp16x2)
    {
        dim3 grid(SEQ/128, NH, BATCH);
        attn_fa2_kernel<<<grid, 256, ATT_SMEM>>>(p_qh, p_kh, p_kl,
                                                 p_vh, p_vl, amask, p_ath);
    }

    // 4. out-proj + residual add (fp16x2)
    {
        dim3 grid(DM/128, BS/128);
        hgemm_resid_kernel<<<grid, 256, HG_SMEM>>>(p_ath, p_woh, p_wol,
                                                   hidden, out, BS, DM, DM);
    }

    // 5. post-norm
    rmsnorm_kernel<<<BS, 256>>>(out, n2w, out + (size_t)BS * DM);
}

// round 9
// speedup vs baseline: 2.2789x; 1.4769x over previous
#include <cuda_runtime.h>
#include <cuda_fp16.h>
#include <math.h>
#include <stdint.h>

// Problem constants
#define BATCH   2
#define SEQ     2048
#define DM      2048
#define NH      16
#define KVH     4
#define HD      128
#define QKV_N   3072
#define BS      (BATCH*SEQ)   // 4096
#define QSCALE  0.08838834764831845f

// ---------------------------------------------------------------------------
// Scratch (pure fp16)
// ---------------------------------------------------------------------------
__device__ __half g_xn [BS * DM];
__device__ __half g_at [BS * DM];
__device__ __half g_wq [DM * QKV_N];
__device__ __half g_wo [DM * DM];

__device__ __half g_q [BATCH * NH  * SEQ * HD];
__device__ __half g_k [BATCH * KVH * SEQ * HD];
__device__ __half g_v [BATCH * KVH * SEQ * HD];

// ---------------------------------------------------------------------------
// PTX helpers
// ---------------------------------------------------------------------------
__device__ __forceinline__ uint32_t smem_u32(const void* p) {
    uint32_t a;
    asm("{ .reg .u64 t; cvta.to.shared.u64 t, %1; cvt.u32.u64 %0, t; }"
        : "=r"(a) : "l"(p));
    return a;
}
__device__ __forceinline__ void cp16(uint32_t dst, const void* src) {
    asm volatile("cp.async.cg.shared.global [%0], [%1], 16;"
                 :: "r"(dst), "l"(src));
}
__device__ __forceinline__ void cp_commit() {
    asm volatile("cp.async.commit_group;" ::: "memory");
}
template<int N>
__device__ __forceinline__ void cp_wait() {
    asm volatile("cp.async.wait_group %0;" :: "n"(N) : "memory");
}
__device__ __forceinline__ void ldsm_x4(uint32_t* r, uint32_t addr) {
    asm volatile("ldmatrix.sync.aligned.m8n8.x4.shared.b16 {%0,%1,%2,%3}, [%4];"
                 : "=r"(r[0]), "=r"(r[1]), "=r"(r[2]), "=r"(r[3]) : "r"(addr));
}
__device__ __forceinline__ void ldsm_x4t(uint32_t* r, uint32_t addr) {
    asm volatile("ldmatrix.sync.aligned.m8n8.x4.trans.shared.b16 {%0,%1,%2,%3}, [%4];"
                 : "=r"(r[0]), "=r"(r[1]), "=r"(r[2]), "=r"(r[3]) : "r"(addr));
}
__device__ __forceinline__ void mma_f16(float* d, const uint32_t* a, const uint32_t* b) {
    asm volatile(
        "mma.sync.aligned.m16n8k16.row.col.f32.f16.f16.f32 "
        "{%0,%1,%2,%3}, {%4,%5,%6,%7}, {%8,%9}, {%0,%1,%2,%3};"
        : "+f"(d[0]), "+f"(d[1]), "+f"(d[2]), "+f"(d[3])
        : "r"(a[0]), "r"(a[1]), "r"(a[2]), "r"(a[3]), "r"(b[0]), "r"(b[1]));
}
__device__ __forceinline__ void mma_f16_2(float* d, const uint32_t* a,
                                          uint32_t b0, uint32_t b1) {
    asm volatile(
        "mma.sync.aligned.m16n8k16.row.col.f32.f16.f16.f32 "
        "{%0,%1,%2,%3}, {%4,%5,%6,%7}, {%8,%9}, {%0,%1,%2,%3};"
        : "+f"(d[0]), "+f"(d[1]), "+f"(d[2]), "+f"(d[3])
        : "r"(a[0]), "r"(a[1]), "r"(a[2]), "r"(a[3]), "r"(b0), "r"(b1));
}

// ---------------------------------------------------------------------------
// RMSNorm (fp32 out)
// ---------------------------------------------------------------------------
__global__ void rmsnorm_kernel(const float* __restrict__ x,
                               const float* __restrict__ w,
                               float* __restrict__ y)
{
    __shared__ float red[256];
    int row = blockIdx.x;
    const float4* xr = (const float4*)(x + (size_t)row * DM);
    float s = 0.f;
    #pragma unroll
    for (int i = threadIdx.x; i < DM/4; i += 256) {
        float4 v = xr[i];
        s += v.x*v.x + v.y*v.y + v.z*v.z + v.w*v.w;
    }
    red[threadIdx.x] = s;
    __syncthreads();
    for (int st = 128; st > 0; st >>= 1) {
        if (threadIdx.x < st) red[threadIdx.x] += red[threadIdx.x + st];
        __syncthreads();
    }
    float rs = rsqrtf(red[0] * (1.0f/(float)DM) + 1e-5f);
    float4* yr = (float4*)(y + (size_t)row * DM);
    const float4* wr = (const float4*)w;
    #pragma unroll
    for (int i = threadIdx.x; i < DM/4; i += 256) {
        float4 v = xr[i];
        float4 ww = wr[i];
        v.x = v.x * rs * ww.x;
        v.y = v.y * rs * ww.y;
        v.z = v.z * rs * ww.z;
        v.w = v.w * rs * ww.w;
        yr[i] = v;
    }
}

// RMSNorm -> fp16
__global__ void rmsnorm_h_kernel(const float* __restrict__ x,
                                 const float* __restrict__ w,
                                 __half* __restrict__ yh)
{
    __shared__ float red[256];
    int row = blockIdx.x;
    const float4* xr = (const float4*)(x + (size_t)row * DM);
    float s = 0.f;
    #pragma unroll
    for (int i = threadIdx.x; i < DM/4; i += 256) {
        float4 v = xr[i];
        s += v.x*v.x + v.y*v.y + v.z*v.z + v.w*v.w;
    }
    red[threadIdx.x] = s;
    __syncthreads();
    for (int st = 128; st > 0; st >>= 1) {
        if (threadIdx.x < st) red[threadIdx.x] += red[threadIdx.x + st];
        __syncthreads();
    }
    float rs = rsqrtf(red[0] * (1.0f/(float)DM) + 1e-5f);
    const float4* wr = (const float4*)w;
    #pragma unroll
    for (int i = threadIdx.x; i < DM/4; i += 256) {
        float4 v = xr[i];
        float4 ww = wr[i];
        __half h[4];
        h[0] = __float2half(v.x*rs*ww.x);
        h[1] = __float2half(v.y*rs*ww.y);
        h[2] = __float2half(v.z*rs*ww.z);
        h[3] = __float2half(v.w*rs*ww.w);
        *(ulonglong1*)&yh[(size_t)row * DM + i*4] = *(ulonglong1*)h;
    }
}

// fp32 -> fp16 convert
__global__ void cvt_h_kernel(const float* __restrict__ x,
                             __half* __restrict__ xh, int n4)
{
    int i = blockIdx.x * blockDim.x + threadIdx.x;
    if (i >= n4) return;
    float4 v = ((const float4*)x)[i];
    __half h[4];
    h[0] = __float2half(v.x);
    h[1] = __float2half(v.y);
    h[2] = __float2half(v.z);
    h[3] = __float2half(v.w);
    *(ulonglong1*)&xh[(size_t)i*4] = *(ulonglong1*)h;
}

// ---------------------------------------------------------------------------
// GEMM tiling: CTA 128x128, k-chunk 32, 2-stage, pure fp16.
// ---------------------------------------------------------------------------
#define A_STRIDE  80
#define B_STRIDE  272
#define AH_OFF    0
#define BH_OFF    10240      // 128*80
#define CHUNK_SZ  18944      // + 32*272
#define HG_SMEM   (2*CHUNK_SZ)   // 37888
#define CT_STRIDE 132
#define HGQ_SMEM  67584          // epilogue staging 128*132*4

// out-proj GEMM: C = A@B + Resid (fp32 out)
__global__ void __launch_bounds__(256)
hgemm_resid_kernel(const __half* __restrict__ Ah,
                   const __half* __restrict__ Bh,
                   const float* __restrict__ Resid, float* __restrict__ C,
                   int M, int N, int K)
{
    extern __shared__ char sm[];
    uint32_t sb = smem_u32(sm);

    int tid  = threadIdx.x;
    int lane = tid & 31;
    int warp = tid >> 5;
    int warpM = warp & 1;
    int warpN = warp >> 1;
    int rowBase = blockIdx.y * 128;
    int colBase = blockIdx.x * 128;

    float acc[4][4][4];
    #pragma unroll
    for (int i = 0; i < 4; i++)
        #pragma unroll
        for (int j = 0; j < 4; j++)
            #pragma unroll
            for (int q = 0; q < 4; q++) acc[i][j][q] = 0.f;

    int nC = K / 32;

    auto issue = [&](int c) {
        uint32_t base = sb + (c & 1) * CHUNK_SZ;
        int k0 = c * 32;
        #pragma unroll
        for (int it = 0; it < 2; it++) {
            int idx = it * 256 + tid;
            int r  = idx >> 2;
            int kc = idx & 3;
            cp16(base + AH_OFF + r * A_STRIDE + kc * 16,
                 Ah + (size_t)(rowBase + r) * K + k0 + kc*8);
        }
        #pragma unroll
        for (int it = 0; it < 2; it++) {
            int idx = it * 256 + tid;
            int r   = idx >> 4;
            int c16 = idx & 15;
            cp16(base + BH_OFF + r * B_STRIDE + c16 * 16,
                 Bh + (size_t)(k0 + r) * N + colBase + c16*8);
        }
        cp_commit();
    };

    issue(0);

    for (int c = 0; c < nC; c++) {
        if (c + 1 < nC) { issue(c + 1); cp_wait<1>(); }
        else            { cp_wait<0>(); }
        __syncthreads();

        uint32_t base = sb + (c & 1) * CHUNK_SZ;

        #pragma unroll
        for (int kk = 0; kk < 2; kk++) {
            uint32_t aR[4][4];
            #pragma unroll
            for (int mt = 0; mt < 4; mt++) {
                int r = warpM*64 + mt*16 + (lane & 15);
                uint32_t col = ((lane >> 4) * 16) + kk * 32;
                ldsm_x4(aR[mt], base + AH_OFF + r*A_STRIDE + col);
            }
            uint32_t bR[2][4];
            #pragma unroll
            for (int nt = 0; nt < 2; nt++) {
                int r = kk*16 + (lane & 15);
                uint32_t col = (uint32_t)(warpN*32 + nt*16) * 2 + ((lane >> 4) * 16);
                ldsm_x4t(bR[nt], base + BH_OFF + r*B_STRIDE + col);
            }
            #pragma unroll
            for (int mt = 0; mt < 4; mt++) {
                #pragma unroll
                for (int n8 = 0; n8 < 4; n8++) {
                    int nt = n8 >> 1, hf = (n8 & 1) * 2;
                    mma_f16(acc[mt][n8], aR[mt], &bR[nt][hf]);
                }
            }
        }
        __syncthreads();
    }

    int rg = lane >> 2;
    int cg = (lane & 3) * 2;
    #pragma unroll
    for (int mt = 0; mt < 4; mt++) {
        #pragma unroll
        for (int n8 = 0; n8 < 4; n8++) {
            int r0 = rowBase + warpM*64 + mt*16 + rg;
            int cc = colBase + warpN*32 + n8*8 + cg;
            #pragma unroll
            for (int half = 0; half < 2; half++) {
                int r = r0 + half * 8;
                float2 v;
                v.x = acc[mt][n8][half*2+0];
                v.y = acc[mt][n8][half*2+1];
                float2 rv = *(const float2*)&Resid[(size_t)r * N + cc];
                v.x += rv.x; v.y += rv.y;
                *(float2*)&C[(size_t)r * N + cc] = v;
            }
        }
    }
}

// QKV GEMM with fused clip + RoPE + fp16 epilogue.
__global__ void __launch_bounds__(256)
hgemm_qkv_kernel(const __half* __restrict__ Ah,
                 const __half* __restrict__ Bh,
                 const int* __restrict__ posids,
                 const float* __restrict__ rsin, const float* __restrict__ rcos,
                 __half* __restrict__ Qo,
                 __half* __restrict__ Ko,
                 __half* __restrict__ Vo)
{
    extern __shared__ char sm[];
    uint32_t sb = smem_u32(sm);

    const int N = QKV_N, K = DM;
    int tid  = threadIdx.x;
    int lane = tid & 31;
    int warp = tid >> 5;
    int warpM = warp & 1;
    int warpN = warp >> 1;
    int rowBase = blockIdx.y * 128;
    int colBase = blockIdx.x * 128;

    float acc[4][4][4];
    #pragma unroll
    for (int i = 0; i < 4; i++)
        #pragma unroll
        for (int j = 0; j < 4; j++)
            #pragma unroll
            for (int q = 0; q < 4; q++) acc[i][j][q] = 0.f;

    int nC = K / 32;

    auto issue = [&](int c) {
        uint32_t base = sb + (c & 1) * CHUNK_SZ;
        int k0 = c * 32;
        #pragma unroll
        for (int it = 0; it < 2; it++) {
            int idx = it * 256 + tid;
            int r  = idx >> 2;
            int kc = idx & 3;
            cp16(base + AH_OFF + r * A_STRIDE + kc * 16,
                 Ah + (size_t)(rowBase + r) * K + k0 + kc*8);
        }
        #pragma unroll
        for (int it = 0; it < 2; it++) {
            int idx = it * 256 + tid;
            int r   = idx >> 4;
            int c16 = idx & 15;
            cp16(base + BH_OFF + r * B_STRIDE + c16 * 16,
                 Bh + (size_t)(k0 + r) * N + colBase + c16*8);
        }
        cp_commit();
    };

    issue(0);

    for (int c = 0; c < nC; c++) {
        if (c + 1 < nC) { issue(c + 1); cp_wait<1>(); }
        else            { cp_wait<0>(); }
        __syncthreads();

        uint32_t base = sb + (c & 1) * CHUNK_SZ;

        #pragma unroll
        for (int kk = 0; kk < 2; kk++) {
            uint32_t aR[4][4];
            #pragma unroll
            for (int mt = 0; mt < 4; mt++) {
                int r = warpM*64 + mt*16 + (lane & 15);
                uint32_t col = ((lane >> 4) * 16) + kk * 32;
                ldsm_x4(aR[mt], base + AH_OFF + r*A_STRIDE + col);
            }
            uint32_t bR[2][4];
            #pragma unroll
            for (int nt = 0; nt < 2; nt++) {
                int r = kk*16 + (lane & 15);
                uint32_t col = (uint32_t)(warpN*32 + nt*16) * 2 + ((lane >> 4) * 16);
                ldsm_x4t(bR[nt], base + BH_OFF + r*B_STRIDE + col);
            }
            #pragma unroll
            for (int mt = 0; mt < 4; mt++) {
                #pragma unroll
                for (int n8 = 0; n8 < 4; n8++) {
                    int nt = n8 >> 1, hf = (n8 & 1) * 2;
                    mma_f16(acc[mt][n8], aR[mt], &bR[nt][hf]);
                }
            }
        }
        __syncthreads();
    }

    // Stage clipped tile in smem
    float* Ct = (float*)sm;
    int rg = lane >> 2;
    int cg = (lane & 3) * 2;
    #pragma unroll
    for (int mt = 0; mt < 4; mt++) {
        #pragma unroll
        for (int n8 = 0; n8 < 4; n8++) {
            int r0 = warpM*64 + mt*16 + rg;
            int cl = warpN*32 + n8*8 + cg;
            #pragma unroll
            for (int half = 0; half < 2; half++) {
                int r = r0 + half * 8;
                Ct[r*CT_STRIDE + cl]     = fminf(8.f, fmaxf(-8.f, acc[mt][n8][half*2+0]));
                Ct[r*CT_STRIDE + cl + 1] = fminf(8.f, fmaxf(-8.f, acc[mt][n8][half*2+1]));
            }
        }
    }
    __syncthreads();

    // RoPE + scatter (fp16)
    int head = blockIdx.x;            // 0..23
    for (int idx = tid; idx < 128*128; idx += 256) {
        int r = idx >> 7;
        int d = idx & 127;
        int token = rowBase + r;
        int b = token >> 11;
        int s = token & 2047;
        float x = Ct[r*CT_STRIDE + d];
        if (head < NH + KVH) {
            int pos = posids[token];
            float cz = rcos[pos * HD + d];
            float sn = rsin[pos * HD + d];
            float other = (d < 64) ? -Ct[r*CT_STRIDE + d + 64]
                                   :  Ct[r*CT_STRIDE + d - 64];
            float val = x * cz + other * sn;
            if (head < NH) {
                Qo[(((size_t)(b*NH + head)) * SEQ + s) * HD + d] =
                    __float2half(val * QSCALE);
            } else {
                Ko[(((size_t)(b*KVH + head - NH)) * SEQ + s) * HD + d] =
                    __float2half(val);
            }
        } else {
            Vo[(((size_t)(b*KVH + head - NH - KVH)) * SEQ + s) * HD + d] =
                __float2half(x);
        }
    }
}

// ---------------------------------------------------------------------------
// FlashAttention-2: BM=128, BN=64, 8 warps, pure fp16.
// ---------------------------------------------------------------------------
#define AT_STRIDE 272
#define AQH 0
#define AKV 34816
#define AKV_BUF 34816          // per buf: KH 0 | VH 17408
#define AMK (AKV + 2*AKV_BUF)  // 104448
#define ATT_SMEM (AMK + 512)

__global__ void __launch_bounds__(256, 1)
attn_fa2_kernel(const __half* __restrict__ Qh,
                const __half* __restrict__ Kh,
                const __half* __restrict__ Vh,
                const int* __restrict__ amask,
                __half* __restrict__ Oh)
{
    extern __shared__ char sm[];
    uint32_t sb = smem_u32(sm);
    int* mk = (int*)(sm + AMK);

    int tid  = threadIdx.x;
    int lane = tid & 31;
    int warp = tid >> 5;
    int qt = gridDim.x - 1 - blockIdx.x;
    int h  = blockIdx.y;
    int b  = blockIdx.z;
    int kvh = h >> 2;

    const __half* Qg  = Qh + ((size_t)(b*NH + h) * SEQ + qt*128) * HD;
    const __half* Kg  = Kh + ((size_t)(b*KVH + kvh) * SEQ) * HD;
    const __half* Vg  = Vh + ((size_t)(b*KVH + kvh) * SEQ) * HD;

    #pragma unroll
    for (int it = 0; it < 8; it++) {
        int idx = it * 256 + tid;
        int r = idx >> 4;
        int c = idx & 15;
        cp16(sb + AQH + r * AT_STRIDE + c*16, Qg + (size_t)r * HD + c*8);
    }
    cp_commit();

    auto issueKV = [&](int kt) {
        uint32_t base = sb + AKV + (kt & 1) * AKV_BUF;
        #pragma unroll
        for (int it = 0; it < 4; it++) {
            int idx = it * 256 + tid;
            int r = idx >> 4;
            int c = idx & 15;
            size_t go = (size_t)(kt*64 + r) * HD + c*8;
            uint32_t so = r * AT_STRIDE + c*16;
            cp16(base + 0     + so, Kg + go);
            cp16(base + 17408 + so, Vg + go);
        }
        cp_commit();
    };
    issueKV(0);

    float m0 = -1e30f, m1 = -1e30f, l0 = 0.f, l1 = 0.f;
    float o[16][4];
    #pragma unroll
    for (int i = 0; i < 16; i++)
        #pragma unroll
        for (int j = 0; j < 4; j++) o[i][j] = 0.f;

    int ktLast = 2*qt + 1;
    int rloc = (lane >> 2);

    for (int kt = 0; kt <= ktLast; kt++) {
        if (tid < 64)
            mk[(kt & 1)*64 + tid] = (amask[b*SEQ + kt*64 + tid] > 0) ? 0 : 1;
        cp_wait<0>();
        __syncthreads();
        if (kt < ktLast) issueKV(kt + 1);

        uint32_t kvbase = sb + AKV + (kt & 1) * AKV_BUF;
        const int* mkc = mk + (kt & 1)*64;

        bool active = !(kt == ktLast && warp < 4);
        if (active) {
            // ---- S = Q @ K^T ----
            float sacc[8][4];
            #pragma unroll
            for (int i = 0; i < 8; i++)
                #pragma unroll
                for (int j = 0; j < 4; j++) sacc[i][j] = 0.f;

            #pragma unroll
            for (int kk = 0; kk < 8; kk++) {
                uint32_t aQ[4];
                uint32_t aoff = (warp*16 + (lane & 15)) * AT_STRIDE
                              + kk*32 + ((lane >> 4) * 16);
                ldsm_x4(aQ, sb + AQH + aoff);
                uint32_t bK[4][4];
                #pragma unroll
                for (int nt = 0; nt < 4; nt++) {
                    uint32_t boff = (uint32_t)(nt*16 + (lane & 15)) * AT_STRIDE
                                  + kk*32 + ((lane >> 4) * 16);
                    ldsm_x4(bK[nt], kvbase + boff);
                }
                #pragma unroll
                for (int n8 = 0; n8 < 8; n8++) {
                    int nt = n8 >> 1;
                    int lo = n8 & 1;
                    mma_f16_2(sacc[n8], aQ, bK[nt][lo], bK[nt][lo+2]);
                }
            }

            // ---- mask + online softmax ----
            bool needCausal = (kt >= 2*qt);
            int rg0 = qt*128 + warp*16 + rloc;
            #pragma unroll
            for (int n8 = 0; n8 < 8; n8++) {
                int c0 = n8*8 + (lane & 3)*2;
                float mb0 = mkc[c0]   ? -1e30f : 0.f;
                float mb1 = mkc[c0+1] ? -1e30f : 0.f;
                sacc[n8][0] += mb0; sacc[n8][1] += mb1;
                sacc[n8][2] += mb0; sacc[n8][3] += mb1;
                if (needCausal) {
                    int cga = kt*64 + c0;
                    if (cga     > rg0)     sacc[n8][0] = -1e30f;
                    if (cga + 1 > rg0)     sacc[n8][1] = -1e30f;
                    if (cga     > rg0 + 8) sacc[n8][2] = -1e30f;
                    if (cga + 1 > rg0 + 8) sacc[n8][3] = -1e30f;
                }
            }
            float mx0 = m0, mx1 = m1;
            #pragma unroll
            for (int n8 = 0; n8 < 8; n8++) {
                mx0 = fmaxf(mx0, fmaxf(sacc[n8][0], sacc[n8][1]));
                mx1 = fmaxf(mx1, fmaxf(sacc[n8][2], sacc[n8][3]));
            }
            mx0 = fmaxf(mx0, __shfl_xor_sync(0xffffffff, mx0, 1));
            mx0 = fmaxf(mx0, __shfl_xor_sync(0xffffffff, mx0, 2));
            mx1 = fmaxf(mx1, __shfl_xor_sync(0xffffffff, mx1, 1));
            mx1 = fmaxf(mx1, __shfl_xor_sync(0xffffffff, mx1, 2));
            float ls0 = 0.f, ls1 = 0.f;
            #pragma unroll
            for (int n8 = 0; n8 < 8; n8++) {
                sacc[n8][0] = __expf(sacc[n8][0] - mx0);
                sacc[n8][1] = __expf(sacc[n8][1] - mx0);
                sacc[n8][2] = __expf(sacc[n8][2] - mx1);
                sacc[n8][3] = __expf(sacc[n8][3] - mx1);
                ls0 += sacc[n8][0] + sacc[n8][1];
                ls1 += sacc[n8][2] + sacc[n8][3];
            }
            ls0 += __shfl_xor_sync(0xffffffff, ls0, 1);
            ls0 += __shfl_xor_sync(0xffffffff, ls0, 2);
            ls1 += __shfl_xor_sync(0xffffffff, ls1, 1);
            ls1 += __shfl_xor_sync(0xffffffff, ls1, 2);
            float sc0 = __expf(m0 - mx0);
            float sc1 = __expf(m1 - mx1);
            m0 = mx0; m1 = mx1;
            l0 = l0 * sc0 + ls0;
            l1 = l1 * sc1 + ls1;

            // repack P into A-fragments
            uint32_t ph[8][2];
            #pragma unroll
            for (int n8 = 0; n8 < 8; n8++) {
                __half2 t;
                t.x = __float2half(sacc[n8][0]);
                t.y = __float2half(sacc[n8][1]);
                ph[n8][0] = *(uint32_t*)&t;
                t.x = __float2half(sacc[n8][2]);
                t.y = __float2half(sacc[n8][3]);
                ph[n8][1] = *(uint32_t*)&t;
            }

            // rescale O
            #pragma unroll
            for (int n8 = 0; n8 < 16; n8++) {
                o[n8][0] *= sc0; o[n8][1] *= sc0;
                o[n8][2] *= sc1; o[n8][3] *= sc1;
            }

            // ---- O += P @ V ----
            #pragma unroll
            for (int ks = 0; ks < 4; ks++) {
                uint32_t aP[4] = {ph[2*ks][0], ph[2*ks][1], ph[2*ks+1][0], ph[2*ks+1][1]};
                uint32_t vV[8][4];
                #pragma unroll
                for (int nt = 0; nt < 8; nt++) {
                    uint32_t voff = (uint32_t)(ks*16 + (lane & 15)) * AT_STRIDE
                                  + (uint32_t)(nt*16)*2 + ((lane >> 4) * 16);
                    ldsm_x4t(vV[nt], kvbase + 17408 + voff);
                }
                #pragma unroll
                for (int n8 = 0; n8 < 16; n8++) {
                    int nt = n8 >> 1, hf = (n8 & 1) * 2;
                    mma_f16(o[n8], aP, &vV[nt][hf]);
                }
            }
        }
    }

    // ---- epilogue: O /= l, write fp16 ----
    {
        float inv0 = 1.f / l0;
        float inv1 = 1.f / l1;
        #pragma unroll
        for (int half = 0; half < 2; half++) {
            int rg = qt*128 + warp*16 + rloc + half*8;
            float inv = half ? inv1 : inv0;
            size_t rowoff = (size_t)(b*SEQ + rg) * DM + (size_t)h * HD;
            #pragma unroll
            for (int n8 = 0; n8 < 16; n8++) {
                int c = n8*8 + (lane & 3)*2;
                __half2 pp;
                pp.x = __float2half(o[n8][half*2+0] * inv);
                pp.y = __float2half(o[n8][half*2+1] * inv);
                *(__half2*)&Oh[rowoff + c] = pp;
            }
        }
    }
}

// ---------------------------------------------------------------------------
// kernel_launch
// ---------------------------------------------------------------------------
extern "C" void kernel_launch(void* const* d_in, const int* in_sizes, int n_in,
                              void* d_out, int out_size)
{
    const float* hidden = (const float*)d_in[0];
    const int*   amask  = (const int*)  d_in[1];
    const int*   posids = (const int*)  d_in[2];
    const float* wqkv   = (const float*)d_in[3];
    const float* w_out  = (const float*)d_in[4];
    const float* n1w    = (const float*)d_in[5];
    const float* n2w    = (const float*)d_in[6];
    const float* rsin   = (const float*)d_in[7];
    const float* rcos   = (const float*)d_in[8];
    float* out = (float*)d_out;

    __half *p_xn, *p_at, *p_wq, *p_wo, *p_q, *p_k, *p_v;
    cudaGetSymbolAddress((void**)&p_xn,  g_xn);
    cudaGetSymbolAddress((void**)&p_at,  g_at);
    cudaGetSymbolAddress((void**)&p_wq,  g_wq);
    cudaGetSymbolAddress((void**)&p_wo,  g_wo);
    cudaGetSymbolAddress((void**)&p_q,   g_q);
    cudaGetSymbolAddress((void**)&p_k,   g_k);
    cudaGetSymbolAddress((void**)&p_v,   g_v);

    cudaFuncSetAttribute(hgemm_qkv_kernel,
                         cudaFuncAttributeMaxDynamicSharedMemorySize, HGQ_SMEM);
    cudaFuncSetAttribute(hgemm_resid_kernel,
                         cudaFuncAttributeMaxDynamicSharedMemorySize, HG_SMEM);
    cudaFuncSetAttribute(attn_fa2_kernel,
                         cudaFuncAttributeMaxDynamicSharedMemorySize, ATT_SMEM);

    // 1. pre-norm -> fp16
    rmsnorm_h_kernel<<<BS, 256>>>(hidden, n1w, p_xn);

    // weight conversions (fp16)
    cvt_h_kernel<<<(DM*QKV_N/4 + 255)/256, 256>>>(wqkv, p_wq, DM*QKV_N/4);
    cvt_h_kernel<<<(DM*DM/4 + 255)/256, 256>>>(w_out, p_wo, DM*DM/4);

    // 2. QKV projection + clip + RoPE (fused, fp16)
    {
        dim3 grid(QKV_N/128, BS/128);
        hgemm_qkv_kernel<<<grid, 256, HGQ_SMEM>>>(p_xn, p_wq,
                                                  posids, rsin, rcos,
                                                  p_q, p_k, p_v);
    }

    // 3. flash attention (FA2, fp16)
    {
        dim3 grid(SEQ/128, NH, BATCH);
        attn_fa2_kernel<<<grid, 256, ATT_SMEM>>>(p_q, p_k, p_v, amask, p_at);
    }

    // 4. out-proj + residual add (fp16)
    {
        dim3 grid(DM/128, BS/128);
        hgemm_resid_kernel<<<grid, 256, HG_SMEM>>>(p_at, p_wo,
                                                   hidden, out, BS, DM, DM);
    }

    // 5. post-norm
    rmsnorm_kernel<<<BS, 256>>>(out, n2w, out + (size_t)BS * DM);
}

// round 10
// speedup vs baseline: 2.3962x; 1.0515x over previous
#include <cuda_runtime.h>
#include <cuda_fp16.h>
#include <math.h>
#include <stdint.h>

// Problem constants
#define BATCH   2
#define SEQ     2048
#define DM      2048
#define NH      16
#define KVH     4
#define HD      128
#define QKV_N   3072
#define BS      (BATCH*SEQ)   // 4096
#define QSCALE  0.08838834764831845f

// ---------------------------------------------------------------------------
// Scratch (pure fp16)
// ---------------------------------------------------------------------------
__device__ __half g_xn [BS * DM];
__device__ __half g_at [BS * DM];
__device__ __half g_wq [DM * QKV_N];
__device__ __half g_wo [DM * DM];

__device__ __half g_q [BATCH * NH  * SEQ * HD];
__device__ __half g_k [BATCH * KVH * SEQ * HD];
__device__ __half g_v [BATCH * KVH * SEQ * HD];

// ---------------------------------------------------------------------------
// PTX helpers
// ---------------------------------------------------------------------------
__device__ __forceinline__ uint32_t smem_u32(const void* p) {
    uint32_t a;
    asm("{ .reg .u64 t; cvta.to.shared.u64 t, %1; cvt.u32.u64 %0, t; }"
        : "=r"(a) : "l"(p));
    return a;
}
__device__ __forceinline__ void cp16(uint32_t dst, const void* src) {
    asm volatile("cp.async.cg.shared.global [%0], [%1], 16;"
                 :: "r"(dst), "l"(src));
}
__device__ __forceinline__ void cp_commit() {
    asm volatile("cp.async.commit_group;" ::: "memory");
}
template<int N>
__device__ __forceinline__ void cp_wait() {
    asm volatile("cp.async.wait_group %0;" :: "n"(N) : "memory");
}
__device__ __forceinline__ void ldsm_x4(uint32_t* r, uint32_t addr) {
    asm volatile("ldmatrix.sync.aligned.m8n8.x4.shared.b16 {%0,%1,%2,%3}, [%4];"
                 : "=r"(r[0]), "=r"(r[1]), "=r"(r[2]), "=r"(r[3]) : "r"(addr));
}
__device__ __forceinline__ void ldsm_x4t(uint32_t* r, uint32_t addr) {
    asm volatile("ldmatrix.sync.aligned.m8n8.x4.trans.shared.b16 {%0,%1,%2,%3}, [%4];"
                 : "=r"(r[0]), "=r"(r[1]), "=r"(r[2]), "=r"(r[3]) : "r"(addr));
}
__device__ __forceinline__ void mma_f16(float* d, const uint32_t* a, const uint32_t* b) {
    asm volatile(
        "mma.sync.aligned.m16n8k16.row.col.f32.f16.f16.f32 "
        "{%0,%1,%2,%3}, {%4,%5,%6,%7}, {%8,%9}, {%0,%1,%2,%3};"
        : "+f"(d[0]), "+f"(d[1]), "+f"(d[2]), "+f"(d[3])
        : "r"(a[0]), "r"(a[1]), "r"(a[2]), "r"(a[3]), "r"(b[0]), "r"(b[1]));
}
__device__ __forceinline__ void mma_f16_2(float* d, const uint32_t* a,
                                          uint32_t b0, uint32_t b1) {
    asm volatile(
        "mma.sync.aligned.m16n8k16.row.col.f32.f16.f16.f32 "
        "{%0,%1,%2,%3}, {%4,%5,%6,%7}, {%8,%9}, {%0,%1,%2,%3};"
        : "+f"(d[0]), "+f"(d[1]), "+f"(d[2]), "+f"(d[3])
        : "r"(a[0]), "r"(a[1]), "r"(a[2]), "r"(a[3]), "r"(b0), "r"(b1));
}

// ---------------------------------------------------------------------------
// RMSNorm (fp32 out)
// ---------------------------------------------------------------------------
__global__ void rmsnorm_kernel(const float* __restrict__ x,
                               const float* __restrict__ w,
                               float* __restrict__ y)
{
    __shared__ float red[256];
    int row = blockIdx.x;
    const float4* xr = (const float4*)(x + (size_t)row * DM);
    float s = 0.f;
    #pragma unroll
    for (int i = threadIdx.x; i < DM/4; i += 256) {
        float4 v = xr[i];
        s += v.x*v.x + v.y*v.y + v.z*v.z + v.w*v.w;
    }
    red[threadIdx.x] = s;
    __syncthreads();
    for (int st = 128; st > 0; st >>= 1) {
        if (threadIdx.x < st) red[threadIdx.x] += red[threadIdx.x + st];
        __syncthreads();
    }
    float rs = rsqrtf(red[0] * (1.0f/(float)DM) + 1e-5f);
    float4* yr = (float4*)(y + (size_t)row * DM);
    const float4* wr = (const float4*)w;
    #pragma unroll
    for (int i = threadIdx.x; i < DM/4; i += 256) {
        float4 v = xr[i];
        float4 ww = wr[i];
        v.x = v.x * rs * ww.x;
        v.y = v.y * rs * ww.y;
        v.z = v.z * rs * ww.z;
        v.w = v.w * rs * ww.w;
        yr[i] = v;
    }
}

// RMSNorm -> fp16
__global__ void rmsnorm_h_kernel(const float* __restrict__ x,
                                 const float* __restrict__ w,
                                 __half* __restrict__ yh)
{
    __shared__ float red[256];
    int row = blockIdx.x;
    const float4* xr = (const float4*)(x + (size_t)row * DM);
    float s = 0.f;
    #pragma unroll
    for (int i = threadIdx.x; i < DM/4; i += 256) {
        float4 v = xr[i];
        s += v.x*v.x + v.y*v.y + v.z*v.z + v.w*v.w;
    }
    red[threadIdx.x] = s;
    __syncthreads();
    for (int st = 128; st > 0; st >>= 1) {
        if (threadIdx.x < st) red[threadIdx.x] += red[threadIdx.x + st];
        __syncthreads();
    }
    float rs = rsqrtf(red[0] * (1.0f/(float)DM) + 1e-5f);
    const float4* wr = (const float4*)w;
    #pragma unroll
    for (int i = threadIdx.x; i < DM/4; i += 256) {
        float4 v = xr[i];
        float4 ww = wr[i];
        __half h[4];
        h[0] = __float2half(v.x*rs*ww.x);
        h[1] = __float2half(v.y*rs*ww.y);
        h[2] = __float2half(v.z*rs*ww.z);
        h[3] = __float2half(v.w*rs*ww.w);
        *(ulonglong1*)&yh[(size_t)row * DM + i*4] = *(ulonglong1*)h;
    }
}

// fp32 -> fp16 convert
__global__ void cvt_h_kernel(const float* __restrict__ x,
                             __half* __restrict__ xh, int n4)
{
    int i = blockIdx.x * blockDim.x + threadIdx.x;
    if (i >= n4) return;
    float4 v = ((const float4*)x)[i];
    __half h[4];
    h[0] = __float2half(v.x);
    h[1] = __float2half(v.y);
    h[2] = __float2half(v.z);
    h[3] = __float2half(v.w);
    *(ulonglong1*)&xh[(size_t)i*4] = *(ulonglong1*)h;
}

// ---------------------------------------------------------------------------
// GEMM tiling: CTA 128x128, k-chunk 32, 3-stage cp.async, one sync/chunk.
// ---------------------------------------------------------------------------
#define A_STRIDE  80
#define B_STRIDE  272
#define AH_OFF    0
#define BH_OFF    10240      // 128*80
#define CHUNK_SZ  18944      // + 32*272
#define HG_SMEM   (3*CHUNK_SZ)   // 56832
#define CT_STRIDE 136            // fp16 epilogue staging: 128 data + 8 pad
// 128*136*2 = 34816 <= HG_SMEM (reuse)

// 3-stage multistage mainloop + per-kernel epilogue.
// Per-chunk compute (shared by both GEMM kernels)
#define GEMM_COMPUTE_CHUNK(base)                                              \
    do {                                                                      \
        _Pragma("unroll")                                                     \
        for (int kk = 0; kk < 2; kk++) {                                      \
            uint32_t aR[4][4];                                                \
            _Pragma("unroll")                                                 \
            for (int mt = 0; mt < 4; mt++) {                                  \
                int r = warpM*64 + mt*16 + (lane & 15);                       \
                uint32_t col = ((lane >> 4) * 16) + kk * 32;                  \
                ldsm_x4(aR[mt], (base) + AH_OFF + r*A_STRIDE + col);          \
            }                                                                 \
            uint32_t bR[2][4];                                                \
            _Pragma("unroll")                                                 \
            for (int nt = 0; nt < 2; nt++) {                                  \
                int r = kk*16 + (lane & 15);                                  \
                uint32_t col = (uint32_t)(warpN*32 + nt*16) * 2               \
                             + ((lane >> 4) * 16);                            \
                ldsm_x4t(bR[nt], (base) + BH_OFF + r*B_STRIDE + col);         \
            }                                                                 \
            _Pragma("unroll")                                                 \
            for (int mt = 0; mt < 4; mt++) {                                  \
                _Pragma("unroll")                                             \
                for (int n8 = 0; n8 < 4; n8++) {                              \
                    int nt = n8 >> 1, hf = (n8 & 1) * 2;                      \
                    mma_f16(acc[mt][n8], aR[mt], &bR[nt][hf]);                \
                }                                                             \
            }                                                                 \
        }                                                                     \
    } while (0)

// out-proj GEMM: C = A@B + Resid (fp32 out)
__global__ void __launch_bounds__(256, 2)
hgemm_resid_kernel(const __half* __restrict__ Ah,
                   const __half* __restrict__ Bh,
                   const float* __restrict__ Resid, float* __restrict__ C,
                   int M, int N, int K)
{
    extern __shared__ char sm[];
    uint32_t sb = smem_u32(sm);

    int tid  = threadIdx.x;
    int lane = tid & 31;
    int warp = tid >> 5;
    int warpM = warp & 1;
    int warpN = warp >> 1;
    int rowBase = blockIdx.y * 128;
    int colBase = blockIdx.x * 128;

    float acc[4][4][4];
    #pragma unroll
    for (int i = 0; i < 4; i++)
        #pragma unroll
        for (int j = 0; j < 4; j++)
            #pragma unroll
            for (int q = 0; q < 4; q++) acc[i][j][q] = 0.f;

    int nC = K / 32;

    auto issue = [&](int c) {
        uint32_t base = sb + (uint32_t)(c % 3) * CHUNK_SZ;
        int k0 = c * 32;
        #pragma unroll
        for (int it = 0; it < 2; it++) {
            int idx = it * 256 + tid;
            int r  = idx >> 2;
            int kc = idx & 3;
            cp16(base + AH_OFF + r * A_STRIDE + kc * 16,
                 Ah + (size_t)(rowBase + r) * K + k0 + kc*8);
        }
        #pragma unroll
        for (int it = 0; it < 2; it++) {
            int idx = it * 256 + tid;
            int r   = idx >> 4;
            int c16 = idx & 15;
            cp16(base + BH_OFF + r * B_STRIDE + c16 * 16,
                 Bh + (size_t)(k0 + r) * N + colBase + c16*8);
        }
        cp_commit();
    };

    issue(0);
    if (nC > 1) issue(1);

    for (int c = 0; c < nC; c++) {
        if (c + 1 < nC) { cp_wait<1>(); }
        else            { cp_wait<0>(); }
        __syncthreads();
        uint32_t base = sb + (uint32_t)(c % 3) * CHUNK_SZ;
        GEMM_COMPUTE_CHUNK(base);
        if (c + 2 < nC) issue(c + 2);
    }

    int rg = lane >> 2;
    int cg = (lane & 3) * 2;
    #pragma unroll
    for (int mt = 0; mt < 4; mt++) {
        #pragma unroll
        for (int n8 = 0; n8 < 4; n8++) {
            int r0 = rowBase + warpM*64 + mt*16 + rg;
            int cc = colBase + warpN*32 + n8*8 + cg;
            #pragma unroll
            for (int half = 0; half < 2; half++) {
                int r = r0 + half * 8;
                float2 v;
                v.x = acc[mt][n8][half*2+0];
                v.y = acc[mt][n8][half*2+1];
                float2 rv = *(const float2*)&Resid[(size_t)r * N + cc];
                v.x += rv.x; v.y += rv.y;
                *(float2*)&C[(size_t)r * N + cc] = v;
            }
        }
    }
}

// QKV GEMM with fused clip + RoPE + fp16 epilogue.
__global__ void __launch_bounds__(256, 2)
hgemm_qkv_kernel(const __half* __restrict__ Ah,
                 const __half* __restrict__ Bh,
                 const int* __restrict__ posids,
                 const float* __restrict__ rsin, const float* __restrict__ rcos,
                 __half* __restrict__ Qo,
                 __half* __restrict__ Ko,
                 __half* __restrict__ Vo)
{
    extern __shared__ char sm[];
    uint32_t sb = smem_u32(sm);

    const int N = QKV_N, K = DM;
    int tid  = threadIdx.x;
    int lane = tid & 31;
    int warp = tid >> 5;
    int warpM = warp & 1;
    int warpN = warp >> 1;
    int rowBase = blockIdx.y * 128;
    int colBase = blockIdx.x * 128;

    float acc[4][4][4];
    #pragma unroll
    for (int i = 0; i < 4; i++)
        #pragma unroll
        for (int j = 0; j < 4; j++)
            #pragma unroll
            for (int q = 0; q < 4; q++) acc[i][j][q] = 0.f;

    int nC = K / 32;

    auto issue = [&](int c) {
        uint32_t base = sb + (uint32_t)(c % 3) * CHUNK_SZ;
        int k0 = c * 32;
        #pragma unroll
        for (int it = 0; it < 2; it++) {
            int idx = it * 256 + tid;
            int r  = idx >> 2;
            int kc = idx & 3;
            cp16(base + AH_OFF + r * A_STRIDE + kc * 16,
                 Ah + (size_t)(rowBase + r) * K + k0 + kc*8);
        }
        #pragma unroll
        for (int it = 0; it < 2; it++) {
            int idx = it * 256 + tid;
            int r   = idx >> 4;
            int c16 = idx & 15;
            cp16(base + BH_OFF + r * B_STRIDE + c16 * 16,
                 Bh + (size_t)(k0 + r) * N + colBase + c16*8);
        }
        cp_commit();
    };

    issue(0);
    if (nC > 1) issue(1);

    for (int c = 0; c < nC; c++) {
        if (c + 1 < nC) { cp_wait<1>(); }
        else            { cp_wait<0>(); }
        __syncthreads();
        uint32_t base = sb + (uint32_t)(c % 3) * CHUNK_SZ;
        GEMM_COMPUTE_CHUNK(base);
        if (c + 2 < nC) issue(c + 2);
    }
    __syncthreads();

    // Stage clipped tile in smem as fp16 (all cp.async drained)
    __half* Ct = (__half*)sm;
    int rg = lane >> 2;
    int cg = (lane & 3) * 2;
    #pragma unroll
    for (int mt = 0; mt < 4; mt++) {
        #pragma unroll
        for (int n8 = 0; n8 < 4; n8++) {
            int r0 = warpM*64 + mt*16 + rg;
            int cl = warpN*32 + n8*8 + cg;
            #pragma unroll
            for (int half = 0; half < 2; half++) {
                int r = r0 + half * 8;
                __half2 hv;
                hv.x = __float2half(fminf(8.f, fmaxf(-8.f, acc[mt][n8][half*2+0])));
                hv.y = __float2half(fminf(8.f, fmaxf(-8.f, acc[mt][n8][half*2+1])));
                *(__half2*)&Ct[r*CT_STRIDE + cl] = hv;
            }
        }
    }
    __syncthreads();

    // RoPE + scatter (fp16)
    int head = blockIdx.x;            // 0..23
    for (int idx = tid; idx < 128*128; idx += 256) {
        int r = idx >> 7;
        int d = idx & 127;
        int token = rowBase + r;
        int b = token >> 11;
        int s = token & 2047;
        float x = __half2float(Ct[r*CT_STRIDE + d]);
        if (head < NH + KVH) {
            int pos = posids[token];
            float cz = rcos[pos * HD + d];
            float sn = rsin[pos * HD + d];
            float other = (d < 64) ? -__half2float(Ct[r*CT_STRIDE + d + 64])
                                   :  __half2float(Ct[r*CT_STRIDE + d - 64]);
            float val = x * cz + other * sn;
            if (head < NH) {
                Qo[(((size_t)(b*NH + head)) * SEQ + s) * HD + d] =
                    __float2half(val * QSCALE);
            } else {
                Ko[(((size_t)(b*KVH + head - NH)) * SEQ + s) * HD + d] =
                    __float2half(val);
            }
        } else {
            Vo[(((size_t)(b*KVH + head - NH - KVH)) * SEQ + s) * HD + d] =
                __float2half(x);
        }
    }
}

// ---------------------------------------------------------------------------
// FlashAttention-2: BM=128, BN=64, 8 warps, pure fp16.
// ---------------------------------------------------------------------------
#define AT_STRIDE 272
#define AQH 0
#define AKV 34816
#define AKV_BUF 34816          // per buf: KH 0 | VH 17408
#define AMK (AKV + 2*AKV_BUF)  // 104448
#define ATT_SMEM (AMK + 512)

__global__ void __launch_bounds__(256, 1)
attn_fa2_kernel(const __half* __restrict__ Qh,
                const __half* __restrict__ Kh,
                const __half* __restrict__ Vh,
                const int* __restrict__ amask,
                __half* __restrict__ Oh)
{
    extern __shared__ char sm[];
    uint32_t sb = smem_u32(sm);
    int* mk = (int*)(sm + AMK);

    int tid  = threadIdx.x;
    int lane = tid & 31;
    int warp = tid >> 5;
    int qt = gridDim.x - 1 - blockIdx.x;
    int h  = blockIdx.y;
    int b  = blockIdx.z;
    int kvh = h >> 2;

    const __half* Qg  = Qh + ((size_t)(b*NH + h) * SEQ + qt*128) * HD;
    const __half* Kg  = Kh + ((size_t)(b*KVH + kvh) * SEQ) * HD;
    const __half* Vg  = Vh + ((size_t)(b*KVH + kvh) * SEQ) * HD;

    #pragma unroll
    for (int it = 0; it < 8; it++) {
        int idx = it * 256 + tid;
        int r = idx >> 4;
        int c = idx & 15;
        cp16(sb + AQH + r * AT_STRIDE + c*16, Qg + (size_t)r * HD + c*8);
    }
    cp_commit();

    auto issueKV = [&](int kt) {
        uint32_t base = sb + AKV + (kt & 1) * AKV_BUF;
        #pragma unroll
        for (int it = 0; it < 4; it++) {
            int idx = it * 256 + tid;
            int r = idx >> 4;
            int c = idx & 15;
            size_t go = (size_t)(kt*64 + r) * HD + c*8;
            uint32_t so = r * AT_STRIDE + c*16;
            cp16(base + 0     + so, Kg + go);
            cp16(base + 17408 + so, Vg + go);
        }
        cp_commit();
    };
    issueKV(0);

    float m0 = -1e30f, m1 = -1e30f, l0 = 0.f, l1 = 0.f;
    float o[16][4];
    #pragma unroll
    for (int i = 0; i < 16; i++)
        #pragma unroll
        for (int j = 0; j < 4; j++) o[i][j] = 0.f;

    int ktLast = 2*qt + 1;
    int rloc = (lane >> 2);

    for (int kt = 0; kt <= ktLast; kt++) {
        if (tid < 64)
            mk[(kt & 1)*64 + tid] = (amask[b*SEQ + kt*64 + tid] > 0) ? 0 : 1;
        cp_wait<0>();
        __syncthreads();
        if (kt < ktLast) issueKV(kt + 1);

        uint32_t kvbase = sb + AKV + (kt & 1) * AKV_BUF;
        const int* mkc = mk + (kt & 1)*64;

        bool active = !(kt == ktLast && warp < 4);
        if (active) {
            // ---- S = Q @ K^T ----
            float sacc[8][4];
            #pragma unroll
            for (int i = 0; i < 8; i++)
                #pragma unroll
                for (int j = 0; j < 4; j++) sacc[i][j] = 0.f;

            #pragma unroll
            for (int kk = 0; kk < 8; kk++) {
                uint32_t aQ[4];
                uint32_t aoff = (warp*16 + (lane & 15)) * AT_STRIDE
                              + kk*32 + ((lane >> 4) * 16);
                ldsm_x4(aQ, sb + AQH + aoff);
                uint32_t bK[4][4];
                #pragma unroll
                for (int nt = 0; nt < 4; nt++) {
                    uint32_t boff = (uint32_t)(nt*16 + (lane & 15)) * AT_STRIDE
                                  + kk*32 + ((lane >> 4) * 16);
                    ldsm_x4(bK[nt], kvbase + boff);
                }
                #pragma unroll
                for (int n8 = 0; n8 < 8; n8++) {
                    int nt = n8 >> 1;
                    int lo = n8 & 1;
                    mma_f16_2(sacc[n8], aQ, bK[nt][lo], bK[nt][lo+2]);
                }
            }

            // ---- mask + online softmax ----
            bool needCausal = (kt >= 2*qt);
            int rg0 = qt*128 + warp*16 + rloc;
            #pragma unroll
            for (int n8 = 0; n8 < 8; n8++) {
                int c0 = n8*8 + (lane & 3)*2;
                float mb0 = mkc[c0]   ? -1e30f : 0.f;
                float mb1 = mkc[c0+1] ? -1e30f : 0.f;
                sacc[n8][0] += mb0; sacc[n8][1] += mb1;
                sacc[n8][2] += mb0; sacc[n8][3] += mb1;
                if (needCausal) {
                    int cga = kt*64 + c0;
                    if (cga     > rg0)     sacc[n8][0] = -1e30f;
                    if (cga + 1 > rg0)     sacc[n8][1] = -1e30f;
                    if (cga     > rg0 + 8) sacc[n8][2] = -1e30f;
                    if (cga + 1 > rg0 + 8) sacc[n8][3] = -1e30f;
                }
            }
            float mx0 = m0, mx1 = m1;
            #pragma unroll
            for (int n8 = 0; n8 < 8; n8++) {
                mx0 = fmaxf(mx0, fmaxf(sacc[n8][0], sacc[n8][1]));
                mx1 = fmaxf(mx1, fmaxf(sacc[n8][2], sacc[n8][3]));
            }
            mx0 = fmaxf(mx0, __shfl_xor_sync(0xffffffff, mx0, 1));
            mx0 = fmaxf(mx0, __shfl_xor_sync(0xffffffff, mx0, 2));
            mx1 = fmaxf(mx1, __shfl_xor_sync(0xffffffff, mx1, 1));
            mx1 = fmaxf(mx1, __shfl_xor_sync(0xffffffff, mx1, 2));
            float ls0 = 0.f, ls1 = 0.f;
            #pragma unroll
            for (int n8 = 0; n8 < 8; n8++) {
                sacc[n8][0] = __expf(sacc[n8][0] - mx0);
                sacc[n8][1] = __expf(sacc[n8][1] - mx0);
                sacc[n8][2] = __expf(sacc[n8][2] - mx1);
                sacc[n8][3] = __expf(sacc[n8][3] - mx1);
                ls0 += sacc[n8][0] + sacc[n8][1];
                ls1 += sacc[n8][2] + sacc[n8][3];
            }
            ls0 += __shfl_xor_sync(0xffffffff, ls0, 1);
            ls0 += __shfl_xor_sync(0xffffffff, ls0, 2);
            ls1 += __shfl_xor_sync(0xffffffff, ls1, 1);
            ls1 += __shfl_xor_sync(0xffffffff, ls1, 2);
            float sc0 = __expf(m0 - mx0);
            float sc1 = __expf(m1 - mx1);
            m0 = mx0; m1 = mx1;
            l0 = l0 * sc0 + ls0;
            l1 = l1 * sc1 + ls1;

            // repack P into A-fragments
            uint32_t ph[8][2];
            #pragma unroll
            for (int n8 = 0; n8 < 8; n8++) {
                __half2 t;
                t.x = __float2half(sacc[n8][0]);
                t.y = __float2half(sacc[n8][1]);
                ph[n8][0] = *(uint32_t*)&t;
                t.x = __float2half(sacc[n8][2]);
                t.y = __float2half(sacc[n8][3]);
                ph[n8][1] = *(uint32_t*)&t;
            }

            // rescale O
            #pragma unroll
            for (int n8 = 0; n8 < 16; n8++) {
                o[n8][0] *= sc0; o[n8][1] *= sc0;
                o[n8][2] *= sc1; o[n8][3] *= sc1;
            }

            // ---- O += P @ V ----
            #pragma unroll
            for (int ks = 0; ks < 4; ks++) {
                uint32_t aP[4] = {ph[2*ks][0], ph[2*ks][1], ph[2*ks+1][0], ph[2*ks+1][1]};
                uint32_t vV[8][4];
                #pragma unroll
                for (int nt = 0; nt < 8; nt++) {
                    uint32_t voff = (uint32_t)(ks*16 + (lane & 15)) * AT_STRIDE
                                  + (uint32_t)(nt*16)*2 + ((lane >> 4) * 16);
                    ldsm_x4t(vV[nt], kvbase + 17408 + voff);
                }
                #pragma unroll
                for (int n8 = 0; n8 < 16; n8++) {
                    int nt = n8 >> 1, hf = (n8 & 1) * 2;
                    mma_f16(o[n8], aP, &vV[nt][hf]);
                }
            }
        }
    }

    // ---- epilogue: O /= l, write fp16 ----
    {
        float inv0 = 1.f / l0;
        float inv1 = 1.f / l1;
        #pragma unroll
        for (int half = 0; half < 2; half++) {
            int rg = qt*128 + warp*16 + rloc + half*8;
            float inv = half ? inv1 : inv0;
            size_t rowoff = (size_t)(b*SEQ + rg) * DM + (size_t)h * HD;
            #pragma unroll
            for (int n8 = 0; n8 < 16; n8++) {
                int c = n8*8 + (lane & 3)*2;
                __half2 pp;
                pp.x = __float2half(o[n8][half*2+0] * inv);
                pp.y = __float2half(o[n8][half*2+1] * inv);
                *(__half2*)&Oh[rowoff + c] = pp;
            }
        }
    }
}

// ---------------------------------------------------------------------------
// kernel_launch
// ---------------------------------------------------------------------------
extern "C" void kernel_launch(void* const* d_in, const int* in_sizes, int n_in,
                              void* d_out, int out_size)
{
    const float* hidden = (const float*)d_in[0];
    const int*   amask  = (const int*)  d_in[1];
    const int*   posids = (const int*)  d_in[2];
    const float* wqkv   = (const float*)d_in[3];
    const float* w_out  = (const float*)d_in[4];
    const float* n1w    = (const float*)d_in[5];
    const float* n2w    = (const float*)d_in[6];
    const float* rsin   = (const float*)d_in[7];
    const float* rcos   = (const float*)d_in[8];
    float* out = (float*)d_out;

    __half *p_xn, *p_at, *p_wq, *p_wo, *p_q, *p_k, *p_v;
    cudaGetSymbolAddress((void**)&p_xn,  g_xn);
    cudaGetSymbolAddress((void**)&p_at,  g_at);
    cudaGetSymbolAddress((void**)&p_wq,  g_wq);
    cudaGetSymbolAddress((void**)&p_wo,  g_wo);
    cudaGetSymbolAddress((void**)&p_q,   g_q);
    cudaGetSymbolAddress((void**)&p_k,   g_k);
    cudaGetSymbolAddress((void**)&p_v,   g_v);

    cudaFuncSetAttribute(hgemm_qkv_kernel,
                         cudaFuncAttributeMaxDynamicSharedMemorySize, HG_SMEM);
    cudaFuncSetAttribute(hgemm_resid_kernel,
                         cudaFuncAttributeMaxDynamicSharedMemorySize, HG_SMEM);
    cudaFuncSetAttribute(attn_fa2_kernel,
                         cudaFuncAttributeMaxDynamicSharedMemorySize, ATT_SMEM);

    // 1. pre-norm -> fp16
    rmsnorm_h_kernel<<<BS, 256>>>(hidden, n1w, p_xn);

    // weight conversions (fp16)
    cvt_h_kernel<<<(DM*QKV_N/4 + 255)/256, 256>>>(wqkv, p_wq, DM*QKV_N/4);
    cvt_h_kernel<<<(DM*DM/4 + 255)/256, 256>>>(w_out, p_wo, DM*DM/4);

    // 2. QKV projection + clip + RoPE (fused, fp16)
    {
        dim3 grid(QKV_N/128, BS/128);
        hgemm_qkv_kernel<<<grid, 256, HG_SMEM>>>(p_xn, p_wq,
                                                 posids, rsin, rcos,
                                                 p_q, p_k, p_v);
    }

    // 3. flash attention (FA2, fp16)
    {
        dim3 grid(SEQ/128, NH, BATCH);
        attn_fa2_kernel<<<grid, 256, ATT_SMEM>>>(p_q, p_k, p_v, amask, p_at);
    }

    // 4. out-proj + residual add (fp16)
    {
        dim3 grid(DM/128, BS/128);
        hgemm_resid_kernel<<<grid, 256, HG_SMEM>>>(p_at, p_wo,
                                                   hidden, out, BS, DM, DM);
    }

    // 5. post-norm
    rmsnorm_kernel<<<BS, 256>>>(out, n2w, out + (size_t)BS * DM);
}

// round 11
// speedup vs baseline: 2.4779x; 1.0341x over previous
#include <cuda_runtime.h>
#include <cuda_fp16.h>
#include <math.h>
#include <stdint.h>

// Problem constants
#define BATCH   2
#define SEQ     2048
#define DM      2048
#define NH      16
#define KVH     4
#define HD      128
#define QKV_N   3072
#define BS      (BATCH*SEQ)   // 4096
#define QSCALE  0.08838834764831845f

// ---------------------------------------------------------------------------
// Scratch (pure fp16)
// ---------------------------------------------------------------------------
__device__ __half g_xn [BS * DM];
__device__ __half g_at [BS * DM];
__device__ __half g_wq [DM * QKV_N];
__device__ __half g_wo [DM * DM];

__device__ __half g_q [BATCH * NH  * SEQ * HD];
__device__ __half g_k [BATCH * KVH * SEQ * HD];
__device__ __half g_v [BATCH * KVH * SEQ * HD];

// ---------------------------------------------------------------------------
// PTX helpers
// ---------------------------------------------------------------------------
__device__ __forceinline__ uint32_t smem_u32(const void* p) {
    uint32_t a;
    asm("{ .reg .u64 t; cvta.to.shared.u64 t, %1; cvt.u32.u64 %0, t; }"
        : "=r"(a) : "l"(p));
    return a;
}
__device__ __forceinline__ void cp16(uint32_t dst, const void* src) {
    asm volatile("cp.async.cg.shared.global [%0], [%1], 16;"
                 :: "r"(dst), "l"(src));
}
__device__ __forceinline__ void cp_commit() {
    asm volatile("cp.async.commit_group;" ::: "memory");
}
template<int N>
__device__ __forceinline__ void cp_wait() {
    asm volatile("cp.async.wait_group %0;" :: "n"(N) : "memory");
}
__device__ __forceinline__ void ldsm_x4(uint32_t* r, uint32_t addr) {
    asm volatile("ldmatrix.sync.aligned.m8n8.x4.shared.b16 {%0,%1,%2,%3}, [%4];"
                 : "=r"(r[0]), "=r"(r[1]), "=r"(r[2]), "=r"(r[3]) : "r"(addr));
}
__device__ __forceinline__ void ldsm_x4t(uint32_t* r, uint32_t addr) {
    asm volatile("ldmatrix.sync.aligned.m8n8.x4.trans.shared.b16 {%0,%1,%2,%3}, [%4];"
                 : "=r"(r[0]), "=r"(r[1]), "=r"(r[2]), "=r"(r[3]) : "r"(addr));
}
__device__ __forceinline__ void mma_f16(float* d, const uint32_t* a, const uint32_t* b) {
    asm volatile(
        "mma.sync.aligned.m16n8k16.row.col.f32.f16.f16.f32 "
        "{%0,%1,%2,%3}, {%4,%5,%6,%7}, {%8,%9}, {%0,%1,%2,%3};"
        : "+f"(d[0]), "+f"(d[1]), "+f"(d[2]), "+f"(d[3])
        : "r"(a[0]), "r"(a[1]), "r"(a[2]), "r"(a[3]), "r"(b[0]), "r"(b[1]));
}
__device__ __forceinline__ void mma_f16_2(float* d, const uint32_t* a,
                                          uint32_t b0, uint32_t b1) {
    asm volatile(
        "mma.sync.aligned.m16n8k16.row.col.f32.f16.f16.f32 "
        "{%0,%1,%2,%3}, {%4,%5,%6,%7}, {%8,%9}, {%0,%1,%2,%3};"
        : "+f"(d[0]), "+f"(d[1]), "+f"(d[2]), "+f"(d[3])
        : "r"(a[0]), "r"(a[1]), "r"(a[2]), "r"(a[3]), "r"(b0), "r"(b1));
}

// ---------------------------------------------------------------------------
// RMSNorm (fp32 out)
// ---------------------------------------------------------------------------
__global__ void rmsnorm_kernel(const float* __restrict__ x,
                               const float* __restrict__ w,
                               float* __restrict__ y)
{
    __shared__ float red[256];
    int row = blockIdx.x;
    const float4* xr = (const float4*)(x + (size_t)row * DM);
    float s = 0.f;
    #pragma unroll
    for (int i = threadIdx.x; i < DM/4; i += 256) {
        float4 v = xr[i];
        s += v.x*v.x + v.y*v.y + v.z*v.z + v.w*v.w;
    }
    red[threadIdx.x] = s;
    __syncthreads();
    for (int st = 128; st > 0; st >>= 1) {
        if (threadIdx.x < st) red[threadIdx.x] += red[threadIdx.x + st];
        __syncthreads();
    }
    float rs = rsqrtf(red[0] * (1.0f/(float)DM) + 1e-5f);
    float4* yr = (float4*)(y + (size_t)row * DM);
    const float4* wr = (const float4*)w;
    #pragma unroll
    for (int i = threadIdx.x; i < DM/4; i += 256) {
        float4 v = xr[i];
        float4 ww = wr[i];
        v.x = v.x * rs * ww.x;
        v.y = v.y * rs * ww.y;
        v.z = v.z * rs * ww.z;
        v.w = v.w * rs * ww.w;
        yr[i] = v;
    }
}

// RMSNorm -> fp16
__global__ void rmsnorm_h_kernel(const float* __restrict__ x,
                                 const float* __restrict__ w,
                                 __half* __restrict__ yh)
{
    __shared__ float red[256];
    int row = blockIdx.x;
    const float4* xr = (const float4*)(x + (size_t)row * DM);
    float s = 0.f;
    #pragma unroll
    for (int i = threadIdx.x; i < DM/4; i += 256) {
        float4 v = xr[i];
        s += v.x*v.x + v.y*v.y + v.z*v.z + v.w*v.w;
    }
    red[threadIdx.x] = s;
    __syncthreads();
    for (int st = 128; st > 0; st >>= 1) {
        if (threadIdx.x < st) red[threadIdx.x] += red[threadIdx.x + st];
        __syncthreads();
    }
    float rs = rsqrtf(red[0] * (1.0f/(float)DM) + 1e-5f);
    const float4* wr = (const float4*)w;
    #pragma unroll
    for (int i = threadIdx.x; i < DM/4; i += 256) {
        float4 v = xr[i];
        float4 ww = wr[i];
        __half h[4];
        h[0] = __float2half(v.x*rs*ww.x);
        h[1] = __float2half(v.y*rs*ww.y);
        h[2] = __float2half(v.z*rs*ww.z);
        h[3] = __float2half(v.w*rs*ww.w);
        *(ulonglong1*)&yh[(size_t)row * DM + i*4] = *(ulonglong1*)h;
    }
}

// fp32 -> fp16 convert
__global__ void cvt_h_kernel(const float* __restrict__ x,
                             __half* __restrict__ xh, int n4)
{
    int i = blockIdx.x * blockDim.x + threadIdx.x;
    if (i >= n4) return;
    float4 v = ((const float4*)x)[i];
    __half h[4];
    h[0] = __float2half(v.x);
    h[1] = __float2half(v.y);
    h[2] = __float2half(v.z);
    h[3] = __float2half(v.w);
    *(ulonglong1*)&xh[(size_t)i*4] = *(ulonglong1*)h;
}

// ---------------------------------------------------------------------------
// GEMM tiling: CTA 128x128, k-chunk 64, 3-stage cp.async, one sync/chunk.
// ---------------------------------------------------------------------------
#define A_STRIDE  144        // 128B data + 16B pad (conflict-free: 9r mod 32 distinct)
#define B_STRIDE  272
#define AH_OFF    0
#define BH_OFF    18432      // 128*144
#define CHUNK_SZ  35840      // + 64*272
#define HG_SMEM   (3*CHUNK_SZ)   // 107520 -> 2 CTAs/SM (215 KB)
#define CT_STRIDE 136            // fp16 epilogue staging: 128 data + 8 pad
// 128*136*2 = 34816 <= HG_SMEM (reuse)

// Per-chunk compute (K=64: kk loop of 4)
#define GEMM_COMPUTE_CHUNK(base)                                              \
    do {                                                                      \
        _Pragma("unroll")                                                     \
        for (int kk = 0; kk < 4; kk++) {                                      \
            uint32_t aR[4][4];                                                \
            _Pragma("unroll")                                                 \
            for (int mt = 0; mt < 4; mt++) {                                  \
                int r = warpM*64 + mt*16 + (lane & 15);                       \
                uint32_t col = ((lane >> 4) * 16) + kk * 32;                  \
                ldsm_x4(aR[mt], (base) + AH_OFF + r*A_STRIDE + col);          \
            }                                                                 \
            uint32_t bR[2][4];                                                \
            _Pragma("unroll")                                                 \
            for (int nt = 0; nt < 2; nt++) {                                  \
                int r = kk*16 + (lane & 15);                                  \
                uint32_t col = (uint32_t)(warpN*32 + nt*16) * 2               \
                             + ((lane >> 4) * 16);                            \
                ldsm_x4t(bR[nt], (base) + BH_OFF + r*B_STRIDE + col);         \
            }                                                                 \
            _Pragma("unroll")                                                 \
            for (int mt = 0; mt < 4; mt++) {                                  \
                _Pragma("unroll")                                             \
                for (int n8 = 0; n8 < 4; n8++) {                              \
                    int nt = n8 >> 1, hf = (n8 & 1) * 2;                      \
                    mma_f16(acc[mt][n8], aR[mt], &bR[nt][hf]);                \
                }                                                             \
            }                                                                 \
        }                                                                     \
    } while (0)

// Loader for one k-chunk (64 wide)
#define GEMM_ISSUE_CHUNK(Aptr, Bptr, Ncols)                                   \
    auto issue = [&](int c) {                                                 \
        uint32_t base = sb + (uint32_t)(c % 3) * CHUNK_SZ;                    \
        int k0 = c * 64;                                                      \
        _Pragma("unroll")                                                     \
        for (int it = 0; it < 4; it++) {                                      \
            int idx = it * 256 + tid;                                         \
            int r  = idx >> 3;                                                \
            int kc = idx & 7;                                                 \
            cp16(base + AH_OFF + r * A_STRIDE + kc * 16,                      \
                 (Aptr) + (size_t)(rowBase + r) * K + k0 + kc*8);             \
        }                                                                     \
        _Pragma("unroll")                                                     \
        for (int it = 0; it < 4; it++) {                                      \
            int idx = it * 256 + tid;                                         \
            int r   = idx >> 4;                                               \
            int c16 = idx & 15;                                               \
            cp16(base + BH_OFF + r * B_STRIDE + c16 * 16,                     \
                 (Bptr) + (size_t)(k0 + r) * (Ncols) + colBase + c16*8);      \
        }                                                                     \
        cp_commit();                                                          \
    }

// out-proj GEMM: C = A@B + Resid (fp32 out)
__global__ void __launch_bounds__(256, 2)
hgemm_resid_kernel(const __half* __restrict__ Ah,
                   const __half* __restrict__ Bh,
                   const float* __restrict__ Resid, float* __restrict__ C,
                   int M, int N, int K)
{
    extern __shared__ char sm[];
    uint32_t sb = smem_u32(sm);

    int tid  = threadIdx.x;
    int lane = tid & 31;
    int warp = tid >> 5;
    int warpM = warp & 1;
    int warpN = warp >> 1;
    int rowBase = blockIdx.y * 128;
    int colBase = blockIdx.x * 128;

    float acc[4][4][4];
    #pragma unroll
    for (int i = 0; i < 4; i++)
        #pragma unroll
        for (int j = 0; j < 4; j++)
            #pragma unroll
            for (int q = 0; q < 4; q++) acc[i][j][q] = 0.f;

    int nC = K / 64;
    GEMM_ISSUE_CHUNK(Ah, Bh, N);

    issue(0);
    if (nC > 1) issue(1);

    for (int c = 0; c < nC; c++) {
        if (c + 1 < nC) { cp_wait<1>(); }
        else            { cp_wait<0>(); }
        __syncthreads();
        uint32_t base = sb + (uint32_t)(c % 3) * CHUNK_SZ;
        GEMM_COMPUTE_CHUNK(base);
        if (c + 2 < nC) issue(c + 2);
    }

    int rg = lane >> 2;
    int cg = (lane & 3) * 2;
    #pragma unroll
    for (int mt = 0; mt < 4; mt++) {
        #pragma unroll
        for (int n8 = 0; n8 < 4; n8++) {
            int r0 = rowBase + warpM*64 + mt*16 + rg;
            int cc = colBase + warpN*32 + n8*8 + cg;
            #pragma unroll
            for (int half = 0; half < 2; half++) {
                int r = r0 + half * 8;
                float2 v;
                v.x = acc[mt][n8][half*2+0];
                v.y = acc[mt][n8][half*2+1];
                float2 rv = *(const float2*)&Resid[(size_t)r * N + cc];
                v.x += rv.x; v.y += rv.y;
                *(float2*)&C[(size_t)r * N + cc] = v;
            }
        }
    }
}

// QKV GEMM with fused clip + RoPE + fp16 epilogue.
__global__ void __launch_bounds__(256, 2)
hgemm_qkv_kernel(const __half* __restrict__ Ah,
                 const __half* __restrict__ Bh,
                 const int* __restrict__ posids,
                 const float* __restrict__ rsin, const float* __restrict__ rcos,
                 __half* __restrict__ Qo,
                 __half* __restrict__ Ko,
                 __half* __restrict__ Vo)
{
    extern __shared__ char sm[];
    uint32_t sb = smem_u32(sm);

    const int N = QKV_N, K = DM;
    int tid  = threadIdx.x;
    int lane = tid & 31;
    int warp = tid >> 5;
    int warpM = warp & 1;
    int warpN = warp >> 1;
    int rowBase = blockIdx.y * 128;
    int colBase = blockIdx.x * 128;

    float acc[4][4][4];
    #pragma unroll
    for (int i = 0; i < 4; i++)
        #pragma unroll
        for (int j = 0; j < 4; j++)
            #pragma unroll
            for (int q = 0; q < 4; q++) acc[i][j][q] = 0.f;

    int nC = K / 64;
    GEMM_ISSUE_CHUNK(Ah, Bh, N);

    issue(0);
    if (nC > 1) issue(1);

    for (int c = 0; c < nC; c++) {
        if (c + 1 < nC) { cp_wait<1>(); }
        else            { cp_wait<0>(); }
        __syncthreads();
        uint32_t base = sb + (uint32_t)(c % 3) * CHUNK_SZ;
        GEMM_COMPUTE_CHUNK(base);
        if (c + 2 < nC) issue(c + 2);
    }
    __syncthreads();

    // Stage clipped tile in smem as fp16 (all cp.async drained)
    __half* Ct = (__half*)sm;
    int rg = lane >> 2;
    int cg = (lane & 3) * 2;
    #pragma unroll
    for (int mt = 0; mt < 4; mt++) {
        #pragma unroll
        for (int n8 = 0; n8 < 4; n8++) {
            int r0 = warpM*64 + mt*16 + rg;
            int cl = warpN*32 + n8*8 + cg;
            #pragma unroll
            for (int half = 0; half < 2; half++) {
                int r = r0 + half * 8;
                __half2 hv;
                hv.x = __float2half(fminf(8.f, fmaxf(-8.f, acc[mt][n8][half*2+0])));
                hv.y = __float2half(fminf(8.f, fmaxf(-8.f, acc[mt][n8][half*2+1])));
                *(__half2*)&Ct[r*CT_STRIDE + cl] = hv;
            }
        }
    }
    __syncthreads();

    // RoPE + scatter (fp16)
    int head = blockIdx.x;            // 0..23
    for (int idx = tid; idx < 128*128; idx += 256) {
        int r = idx >> 7;
        int d = idx & 127;
        int token = rowBase + r;
        int b = token >> 11;
        int s = token & 2047;
        float x = __half2float(Ct[r*CT_STRIDE + d]);
        if (head < NH + KVH) {
            int pos = posids[token];
            float cz = rcos[pos * HD + d];
            float sn = rsin[pos * HD + d];
            float other = (d < 64) ? -__half2float(Ct[r*CT_STRIDE + d + 64])
                                   :  __half2float(Ct[r*CT_STRIDE + d - 64]);
            float val = x * cz + other * sn;
            if (head < NH) {
                Qo[(((size_t)(b*NH + head)) * SEQ + s) * HD + d] =
                    __float2half(val * QSCALE);
            } else {
                Ko[(((size_t)(b*KVH + head - NH)) * SEQ + s) * HD + d] =
                    __float2half(val);
            }
        } else {
            Vo[(((size_t)(b*KVH + head - NH - KVH)) * SEQ + s) * HD + d] =
                __float2half(x);
        }
    }
}

// ---------------------------------------------------------------------------
// FlashAttention-2: BM=128, BN=64, 8 warps, pure fp16.
// ---------------------------------------------------------------------------
#define AT_STRIDE 272
#define AQH 0
#define AKV 34816
#define AKV_BUF 34816          // per buf: KH 0 | VH 17408
#define AMK (AKV + 2*AKV_BUF)  // 104448
#define ATT_SMEM (AMK + 512)

__global__ void __launch_bounds__(256, 1)
attn_fa2_kernel(const __half* __restrict__ Qh,
                const __half* __restrict__ Kh,
                const __half* __restrict__ Vh,
                const int* __restrict__ amask,
                __half* __restrict__ Oh)
{
    extern __shared__ char sm[];
    uint32_t sb = smem_u32(sm);
    int* mk = (int*)(sm + AMK);

    int tid  = threadIdx.x;
    int lane = tid & 31;
    int warp = tid >> 5;
    int qt = gridDim.x - 1 - blockIdx.x;
    int h  = blockIdx.y;
    int b  = blockIdx.z;
    int kvh = h >> 2;

    const __half* Qg  = Qh + ((size_t)(b*NH + h) * SEQ + qt*128) * HD;
    const __half* Kg  = Kh + ((size_t)(b*KVH + kvh) * SEQ) * HD;
    const __half* Vg  = Vh + ((size_t)(b*KVH + kvh) * SEQ) * HD;

    #pragma unroll
    for (int it = 0; it < 8; it++) {
        int idx = it * 256 + tid;
        int r = idx >> 4;
        int c = idx & 15;
        cp16(sb + AQH + r * AT_STRIDE + c*16, Qg + (size_t)r * HD + c*8);
    }
    cp_commit();

    auto issueKV = [&](int kt) {
        uint32_t base = sb + AKV + (kt & 1) * AKV_BUF;
        #pragma unroll
        for (int it = 0; it < 4; it++) {
            int idx = it * 256 + tid;
            int r = idx >> 4;
            int c = idx & 15;
            size_t go = (size_t)(kt*64 + r) * HD + c*8;
            uint32_t so = r * AT_STRIDE + c*16;
            cp16(base + 0     + so, Kg + go);
            cp16(base + 17408 + so, Vg + go);
        }
        cp_commit();
    };
    issueKV(0);

    float m0 = -1e30f, m1 = -1e30f, l0 = 0.f, l1 = 0.f;
    float o[16][4];
    #pragma unroll
    for (int i = 0; i < 16; i++)
        #pragma unroll
        for (int j = 0; j < 4; j++) o[i][j] = 0.f;

    int ktLast = 2*qt + 1;
    int rloc = (lane >> 2);

    for (int kt = 0; kt <= ktLast; kt++) {
        if (tid < 64)
            mk[(kt & 1)*64 + tid] = (amask[b*SEQ + kt*64 + tid] > 0) ? 0 : 1;
        cp_wait<0>();
        __syncthreads();
        if (kt < ktLast) issueKV(kt + 1);

        uint32_t kvbase = sb + AKV + (kt & 1) * AKV_BUF;
        const int* mkc = mk + (kt & 1)*64;

        bool active = !(kt == ktLast && warp < 4);
        if (active) {
            // ---- S = Q @ K^T ----
            float sacc[8][4];
            #pragma unroll
            for (int i = 0; i < 8; i++)
                #pragma unroll
                for (int j = 0; j < 4; j++) sacc[i][j] = 0.f;

            #pragma unroll
            for (int kk = 0; kk < 8; kk++) {
                uint32_t aQ[4];
                uint32_t aoff = (warp*16 + (lane & 15)) * AT_STRIDE
                              + kk*32 + ((lane >> 4) * 16);
                ldsm_x4(aQ, sb + AQH + aoff);
                uint32_t bK[4][4];
                #pragma unroll
                for (int nt = 0; nt < 4; nt++) {
                    uint32_t boff = (uint32_t)(nt*16 + (lane & 15)) * AT_STRIDE
                                  + kk*32 + ((lane >> 4) * 16);
                    ldsm_x4(bK[nt], kvbase + boff);
                }
                #pragma unroll
                for (int n8 = 0; n8 < 8; n8++) {
                    int nt = n8 >> 1;
                    int lo = n8 & 1;
                    mma_f16_2(sacc[n8], aQ, bK[nt][lo], bK[nt][lo+2]);
                }
            }

            // ---- mask + online softmax ----
            bool needCausal = (kt >= 2*qt);
            int rg0 = qt*128 + warp*16 + rloc;
            #pragma unroll
            for (int n8 = 0; n8 < 8; n8++) {
                int c0 = n8*8 + (lane & 3)*2;
                float mb0 = mkc[c0]   ? -1e30f : 0.f;
                float mb1 = mkc[c0+1] ? -1e30f : 0.f;
                sacc[n8][0] += mb0; sacc[n8][1] += mb1;
                sacc[n8][2] += mb0; sacc[n8][3] += mb1;
                if (needCausal) {
                    int cga = kt*64 + c0;
                    if (cga     > rg0)     sacc[n8][0] = -1e30f;
                    if (cga + 1 > rg0)     sacc[n8][1] = -1e30f;
                    if (cga     > rg0 + 8) sacc[n8][2] = -1e30f;
                    if (cga + 1 > rg0 + 8) sacc[n8][3] = -1e30f;
                }
            }
            float mx0 = m0, mx1 = m1;
            #pragma unroll
            for (int n8 = 0; n8 < 8; n8++) {
                mx0 = fmaxf(mx0, fmaxf(sacc[n8][0], sacc[n8][1]));
                mx1 = fmaxf(mx1, fmaxf(sacc[n8][2], sacc[n8][3]));
            }
            mx0 = fmaxf(mx0, __shfl_xor_sync(0xffffffff, mx0, 1));
            mx0 = fmaxf(mx0, __shfl_xor_sync(0xffffffff, mx0, 2));
            mx1 = fmaxf(mx1, __shfl_xor_sync(0xffffffff, mx1, 1));
            mx1 = fmaxf(mx1, __shfl_xor_sync(0xffffffff, mx1, 2));
            float ls0 = 0.f, ls1 = 0.f;
            #pragma unroll
            for (int n8 = 0; n8 < 8; n8++) {
                sacc[n8][0] = __expf(sacc[n8][0] - mx0);
                sacc[n8][1] = __expf(sacc[n8][1] - mx0);
                sacc[n8][2] = __expf(sacc[n8][2] - mx1);
                sacc[n8][3] = __expf(sacc[n8][3] - mx1);
                ls0 += sacc[n8][0] + sacc[n8][1];
                ls1 += sacc[n8][2] + sacc[n8][3];
            }
            ls0 += __shfl_xor_sync(0xffffffff, ls0, 1);
            ls0 += __shfl_xor_sync(0xffffffff, ls0, 2);
            ls1 += __shfl_xor_sync(0xffffffff, ls1, 1);
            ls1 += __shfl_xor_sync(0xffffffff, ls1, 2);
            float sc0 = __expf(m0 - mx0);
            float sc1 = __expf(m1 - mx1);
            m0 = mx0; m1 = mx1;
            l0 = l0 * sc0 + ls0;
            l1 = l1 * sc1 + ls1;

            // repack P into A-fragments
            uint32_t ph[8][2];
            #pragma unroll
            for (int n8 = 0; n8 < 8; n8++) {
                __half2 t;
                t.x = __float2half(sacc[n8][0]);
                t.y = __float2half(sacc[n8][1]);
                ph[n8][0] = *(uint32_t*)&t;
                t.x = __float2half(sacc[n8][2]);
                t.y = __float2half(sacc[n8][3]);
                ph[n8][1] = *(uint32_t*)&t;
            }

            // rescale O
            #pragma unroll
            for (int n8 = 0; n8 < 16; n8++) {
                o[n8][0] *= sc0; o[n8][1] *= sc0;
                o[n8][2] *= sc1; o[n8][3] *= sc1;
            }

            // ---- O += P @ V ----
            #pragma unroll
            for (int ks = 0; ks < 4; ks++) {
                uint32_t aP[4] = {ph[2*ks][0], ph[2*ks][1], ph[2*ks+1][0], ph[2*ks+1][1]};
                uint32_t vV[8][4];
                #pragma unroll
                for (int nt = 0; nt < 8; nt++) {
                    uint32_t voff = (uint32_t)(ks*16 + (lane & 15)) * AT_STRIDE
                                  + (uint32_t)(nt*16)*2 + ((lane >> 4) * 16);
                    ldsm_x4t(vV[nt], kvbase + 17408 + voff);
                }
                #pragma unroll
                for (int n8 = 0; n8 < 16; n8++) {
                    int nt = n8 >> 1, hf = (n8 & 1) * 2;
                    mma_f16(o[n8], aP, &vV[nt][hf]);
                }
            }
        }
    }

    // ---- epilogue: O /= l, write fp16 ----
    {
        float inv0 = 1.f / l0;
        float inv1 = 1.f / l1;
        #pragma unroll
        for (int half = 0; half < 2; half++) {
            int rg = qt*128 + warp*16 + rloc + half*8;
            float inv = half ? inv1 : inv0;
            size_t rowoff = (size_t)(b*SEQ + rg) * DM + (size_t)h * HD;
            #pragma unroll
            for (int n8 = 0; n8 < 16; n8++) {
                int c = n8*8 + (lane & 3)*2;
                __half2 pp;
                pp.x = __float2half(o[n8][half*2+0] * inv);
                pp.y = __float2half(o[n8][half*2+1] * inv);
                *(__half2*)&Oh[rowoff + c] = pp;
            }
        }
    }
}

// ---------------------------------------------------------------------------
// kernel_launch
// ---------------------------------------------------------------------------
extern "C" void kernel_launch(void* const* d_in, const int* in_sizes, int n_in,
                              void* d_out, int out_size)
{
    const float* hidden = (const float*)d_in[0];
    const int*   amask  = (const int*)  d_in[1];
    const int*   posids = (const int*)  d_in[2];
    const float* wqkv   = (const float*)d_in[3];
    const float* w_out  = (const float*)d_in[4];
    const float* n1w    = (const float*)d_in[5];
    const float* n2w    = (const float*)d_in[6];
    const float* rsin   = (const float*)d_in[7];
    const float* rcos   = (const float*)d_in[8];
    float* out = (float*)d_out;

    __half *p_xn, *p_at, *p_wq, *p_wo, *p_q, *p_k, *p_v;
    cudaGetSymbolAddress((void**)&p_xn,  g_xn);
    cudaGetSymbolAddress((void**)&p_at,  g_at);
    cudaGetSymbolAddress((void**)&p_wq,  g_wq);
    cudaGetSymbolAddress((void**)&p_wo,  g_wo);
    cudaGetSymbolAddress((void**)&p_q,   g_q);
    cudaGetSymbolAddress((void**)&p_k,   g_k);
    cudaGetSymbolAddress((void**)&p_v,   g_v);

    cudaFuncSetAttribute(hgemm_qkv_kernel,
                         cudaFuncAttributeMaxDynamicSharedMemorySize, HG_SMEM);
    cudaFuncSetAttribute(hgemm_resid_kernel,
                         cudaFuncAttributeMaxDynamicSharedMemorySize, HG_SMEM);
    cudaFuncSetAttribute(attn_fa2_kernel,
                         cudaFuncAttributeMaxDynamicSharedMemorySize, ATT_SMEM);

    // 1. pre-norm -> fp16
    rmsnorm_h_kernel<<<BS, 256>>>(hidden, n1w, p_xn);

    // weight conversions (fp16)
    cvt_h_kernel<<<(DM*QKV_N/4 + 255)/256, 256>>>(wqkv, p_wq, DM*QKV_N/4);
    cvt_h_kernel<<<(DM*DM/4 + 255)/256, 256>>>(w_out, p_wo, DM*DM/4);

    // 2. QKV projection + clip + RoPE (fused, fp16)
    {
        dim3 grid(QKV_N/128, BS/128);
        hgemm_qkv_kernel<<<grid, 256, HG_SMEM>>>(p_xn, p_wq,
                                                 posids, rsin, rcos,
                                                 p_q, p_k, p_v);
    }

    // 3. flash attention (FA2, fp16)
    {
        dim3 grid(SEQ/128, NH, BATCH);
        attn_fa2_kernel<<<grid, 256, ATT_SMEM>>>(p_q, p_k, p_v, amask, p_at);
    }

    // 4. out-proj + residual add (fp16)
    {
        dim3 grid(DM/128, BS/128);
        hgemm_resid_kernel<<<grid, 256, HG_SMEM>>>(p_at, p_wo,
                                                   hidden, out, BS, DM, DM);
    }

    // 5. post-norm
    rmsnorm_kernel<<<BS, 256>>>(out, n2w, out + (size_t)BS * DM);
}